// round 3
// baseline (speedup 1.0000x reference)
#include <cuda_runtime.h>
#include <math.h>

// ---------------- problem constants ----------------
#define S_   2048
#define D_   1024
#define H_   16
#define HD_  64
#define TE_  16
#define TOPK 2
#define ED_  512
#define DS_  2048
#define T_   2048
#define NSLOT (T_*TOPK)
#define EPS_ 1e-5f

// ---------------- scratch (device bss, no allocation) ----------------
__device__ float d_xn[(size_t)T_*D_];          // rmsnorm(x, attn_norm)
__device__ float d_qkv[(size_t)T_*3*D_];       // qkv (rope applied in-place)
__device__ float d_ao[(size_t)T_*D_];          // attention output
__device__ float d_xffn_in[(size_t)T_*D_];     // o-proj + residual
__device__ float d_xffn[(size_t)T_*D_];        // rmsnorm(ffn input)
__device__ float d_scores[NSLOT];
__device__ int   d_counts[TE_];
__device__ int   d_list[TE_*NSLOT];
__device__ float d_g[(size_t)NSLOT*ED_];       // swiglu intermediates per slot
__device__ float d_ys[(size_t)NSLOT*D_];       // per-slot expert outputs
__device__ float d_y[(size_t)T_*D_];           // combined routed output
__device__ float d_up[(size_t)T_*2*DS_];       // shared expert up-proj
__device__ float d_gs[(size_t)T_*DS_];         // shared swiglu
__device__ float d_ysh[(size_t)T_*D_];         // shared expert down-proj

// ---------------- reduction helpers ----------------
__device__ __forceinline__ float block_reduce_sum(float v, float* sh) {
    __syncthreads();
    int lane = threadIdx.x & 31, wid = threadIdx.x >> 5;
#pragma unroll
    for (int o = 16; o; o >>= 1) v += __shfl_xor_sync(0xffffffffu, v, o);
    if (lane == 0) sh[wid] = v;
    __syncthreads();
    int nw = blockDim.x >> 5;
    v = (threadIdx.x < nw) ? sh[threadIdx.x] : 0.f;
    if (wid == 0) {
#pragma unroll
        for (int o = 16; o; o >>= 1) v += __shfl_xor_sync(0xffffffffu, v, o);
        if (lane == 0) sh[0] = v;
    }
    __syncthreads();
    return sh[0];
}

__device__ __forceinline__ float block_reduce_max(float v, float* sh) {
    __syncthreads();
    int lane = threadIdx.x & 31, wid = threadIdx.x >> 5;
#pragma unroll
    for (int o = 16; o; o >>= 1) v = fmaxf(v, __shfl_xor_sync(0xffffffffu, v, o));
    if (lane == 0) sh[wid] = v;
    __syncthreads();
    int nw = blockDim.x >> 5;
    v = (threadIdx.x < nw) ? sh[threadIdx.x] : -1e30f;
    if (wid == 0) {
#pragma unroll
        for (int o = 16; o; o >>= 1) v = fmaxf(v, __shfl_xor_sync(0xffffffffu, v, o));
        if (lane == 0) sh[0] = v;
    }
    __syncthreads();
    return sh[0];
}

// ---------------- rmsnorm ----------------
__global__ void rmsnorm_kernel(const float* __restrict__ x, const float* __restrict__ w,
                               float* __restrict__ out) {
    int row = blockIdx.x;
    const float* xr = x + (size_t)row * D_;
    float ss = 0.f;
    for (int i = threadIdx.x; i < D_; i += blockDim.x) { float v = xr[i]; ss += v * v; }
    __shared__ float sh[32];
    float tot = block_reduce_sum(ss, sh);
    float rinv = rsqrtf(tot / (float)D_ + EPS_);
    float* o = out + (size_t)row * D_;
    for (int i = threadIdx.x; i < D_; i += blockDim.x) o[i] = xr[i] * rinv * w[i];
}

// ---------------- SGEMM: C[M,N] = A[M,K] @ B[N,K]^T (+ optional residual) ----------------
template<int WITH_RES>
__global__ void sgemm_abt(const float* __restrict__ A, const float* __restrict__ Bm,
                          float* __restrict__ C, int M, int N, int Kd,
                          const float* __restrict__ Res) {
    __shared__ float As[16][64];
    __shared__ float Bs[16][64];
    int tid = threadIdx.x;
    int tx = tid & 15, ty = tid >> 4;
    int row0 = blockIdx.y * 64, col0 = blockIdx.x * 64;
    int lm = tid >> 2, lk = (tid & 3) << 2;
    float acc[4][4] = {};
    for (int k0 = 0; k0 < Kd; k0 += 16) {
        float4 a = *(const float4*)(A + (size_t)(row0 + lm) * Kd + k0 + lk);
        float4 b = *(const float4*)(Bm + (size_t)(col0 + lm) * Kd + k0 + lk);
        As[lk + 0][lm] = a.x; As[lk + 1][lm] = a.y; As[lk + 2][lm] = a.z; As[lk + 3][lm] = a.w;
        Bs[lk + 0][lm] = b.x; Bs[lk + 1][lm] = b.y; Bs[lk + 2][lm] = b.z; Bs[lk + 3][lm] = b.w;
        __syncthreads();
#pragma unroll
        for (int k = 0; k < 16; k++) {
            float4 av = ((const float4*)&As[k][0])[ty];
            float4 bv = ((const float4*)&Bs[k][0])[tx];
            float aa[4] = {av.x, av.y, av.z, av.w};
            float bb[4] = {bv.x, bv.y, bv.z, bv.w};
#pragma unroll
            for (int i = 0; i < 4; i++)
#pragma unroll
                for (int j = 0; j < 4; j++) acc[i][j] += aa[i] * bb[j];
        }
        __syncthreads();
    }
#pragma unroll
    for (int i = 0; i < 4; i++) {
        int r = row0 + ty * 4 + i;
#pragma unroll
        for (int j = 0; j < 4; j++) {
            int c = col0 + tx * 4 + j;
            float v = acc[i][j];
            if (WITH_RES) v += Res[(size_t)r * N + c];
            C[(size_t)r * N + c] = v;
        }
    }
}

// ---------------- RoPE (in place on q,k parts of qkv) ----------------
__global__ void rope_kernel(float* __restrict__ qkv) {
    int s = blockIdx.x, h = blockIdx.y, i = threadIdx.x;  // i in [0,32)
    float inv = powf(10000.0f, -(float)i / 32.0f);
    float fr = (float)s * inv;
    float c = cosf(fr), sn = sinf(fr);
    float* q = qkv + (size_t)s * 3 * D_ + h * HD_;
    float* k = q + D_;
    float q1 = q[i], q2 = q[i + 32];
    q[i] = q1 * c + q2 * sn;  q[i + 32] = -q1 * sn + q2 * c;
    float k1 = k[i], k2 = k[i + 32];
    k[i] = k1 * c + k2 * sn;  k[i + 32] = -k1 * sn + k2 * c;
}

// ---------------- attention: one block per (q, head), causal two-pass softmax ----------------
__global__ void attn_kernel(const float* __restrict__ qkv, float* __restrict__ o) {
    int qpos = blockIdx.x, h = blockIdx.y;
    int tid = threadIdx.x;  // 128 threads
    __shared__ float sp[S_];
    __shared__ float qv[HD_];
    __shared__ float red[32];
    __shared__ float oacc[2][HD_];
    const float* qrow = qkv + (size_t)qpos * 3 * D_ + h * HD_;
    if (tid < HD_) qv[tid] = qrow[tid];
    __syncthreads();
    int len = qpos + 1;
    float lmax = -1e30f;
    for (int k = tid; k < len; k += 128) {
        const float* krow = qkv + (size_t)k * 3 * D_ + D_ + h * HD_;
        float s = 0.f;
#pragma unroll
        for (int d = 0; d < HD_; d++) s += qv[d] * krow[d];
        s *= 0.125f;
        sp[k] = s;
        lmax = fmaxf(lmax, s);
    }
    float m = block_reduce_max(lmax, red);
    float lsum = 0.f;
    for (int k = tid; k < len; k += 128) {
        float e = expf(sp[k] - m);
        sp[k] = e;
        lsum += e;
    }
    float tot = block_reduce_sum(lsum, red);
    float inv = 1.0f / tot;
    int d = tid & 63, half = tid >> 6;
    int mid = (len + 1) >> 1;
    int ks = half ? mid : 0, ke = half ? len : mid;
    float acc = 0.f;
    const float* vbase = qkv + 2 * D_ + h * HD_ + d;
    for (int k = ks; k < ke; k++) acc += sp[k] * vbase[(size_t)k * 3 * D_];
    oacc[half][d] = acc;
    __syncthreads();
    if (tid < HD_)
        o[(size_t)qpos * D_ + h * HD_ + tid] = (oacc[0][tid] + oacc[1][tid]) * inv;
}

// ---------------- router ----------------
__global__ void router_kernel(const float* __restrict__ xffn, const float* __restrict__ keys,
                              const int* __restrict__ idx, const float* __restrict__ vals,
                              const float* __restrict__ bias) {
    int t = blockIdx.x, lane = threadIdx.x;  // 32 threads
    int e0 = idx[t * 2], e1 = idx[t * 2 + 1];
    const float* xr = xffn + (size_t)t * D_;
    float s0 = 0.f, s1 = 0.f;
    for (int d = lane; d < D_; d += 32) {
        float x = xr[d];
        s0 += x * keys[d * TE_ + e0];
        s1 += x * keys[d * TE_ + e1];
    }
#pragma unroll
    for (int o = 16; o; o >>= 1) {
        s0 += __shfl_xor_sync(0xffffffffu, s0, o);
        s1 += __shfl_xor_sync(0xffffffffu, s1, o);
    }
    if (lane == 0) {
        float v0 = vals[t * 2] + s0 + bias[e0];
        float v1 = vals[t * 2 + 1] + s1 + bias[e1];
        float mm = fmaxf(v0, v1);
        float a = expf(v0 - mm), b = expf(v1 - mm);
        float inv = 1.0f / (a + b);
        d_scores[t * 2] = a * inv;
        d_scores[t * 2 + 1] = b * inv;
    }
}

// ---------------- expert routing lists ----------------
__global__ void zero_counts_kernel() {
    if (threadIdx.x < TE_) d_counts[threadIdx.x] = 0;
}
__global__ void scatter_kernel(const int* __restrict__ idx) {
    int slot = blockIdx.x * blockDim.x + threadIdx.x;
    if (slot < NSLOT) {
        int e = idx[slot];
        int p = atomicAdd(&d_counts[e], 1);
        d_list[e * NSLOT + p] = slot;
    }
}

// ---------------- expert GEMM1: H1,H2 = Xg @ W1/W2[e]  ([D,ED] row-major), fused SwiGLU ----------------
__global__ void expert_gemm1(const float* __restrict__ xffn, const float* __restrict__ experts) {
    int e = blockIdx.z;
    int cnt = d_counts[e];
    int mt = blockIdx.y;
    if (mt * 64 >= cnt) return;
    __shared__ float As[16][64];
    __shared__ float B1s[16][64];
    __shared__ float B2s[16][64];
    __shared__ int slots[64];
    __shared__ int toks[64];
    int tid = threadIdx.x;
    if (tid < 64) {
        int r = mt * 64 + tid;
        int sl = (r < cnt) ? d_list[e * NSLOT + r] : -1;
        slots[tid] = sl;
        toks[tid] = (sl >= 0) ? sl / TOPK : 0;
    }
    __syncthreads();
    const float* W1 = experts + ((size_t)(0 * TE_ + e)) * D_ * ED_;
    const float* W2 = experts + ((size_t)(1 * TE_ + e)) * D_ * ED_;
    int tx = tid & 15, ty = tid >> 4;
    int lm = tid >> 2, lk = (tid & 3) << 2;      // A gather loader
    int bn4 = (tid & 15) << 2, bk = tid >> 4;    // B loader (row = k, contiguous n)
    int col0 = blockIdx.x * 64;
    float acc1[4][4] = {}, acc2[4][4] = {};
    for (int k0 = 0; k0 < D_; k0 += 16) {
        bool valid = slots[lm] >= 0;
        float4 a = *(const float4*)(xffn + (size_t)toks[lm] * D_ + k0 + lk);
        As[lk + 0][lm] = valid ? a.x : 0.f;
        As[lk + 1][lm] = valid ? a.y : 0.f;
        As[lk + 2][lm] = valid ? a.z : 0.f;
        As[lk + 3][lm] = valid ? a.w : 0.f;
        float4 b1 = *(const float4*)(W1 + (size_t)(k0 + bk) * ED_ + col0 + bn4);
        float4 b2 = *(const float4*)(W2 + (size_t)(k0 + bk) * ED_ + col0 + bn4);
        B1s[bk][bn4 + 0] = b1.x; B1s[bk][bn4 + 1] = b1.y; B1s[bk][bn4 + 2] = b1.z; B1s[bk][bn4 + 3] = b1.w;
        B2s[bk][bn4 + 0] = b2.x; B2s[bk][bn4 + 1] = b2.y; B2s[bk][bn4 + 2] = b2.z; B2s[bk][bn4 + 3] = b2.w;
        __syncthreads();
#pragma unroll
        for (int k = 0; k < 16; k++) {
            float4 av = ((const float4*)&As[k][0])[ty];
            float4 b1v = ((const float4*)&B1s[k][0])[tx];
            float4 b2v = ((const float4*)&B2s[k][0])[tx];
            float aa[4] = {av.x, av.y, av.z, av.w};
            float p[4] = {b1v.x, b1v.y, b1v.z, b1v.w};
            float q[4] = {b2v.x, b2v.y, b2v.z, b2v.w};
#pragma unroll
            for (int i = 0; i < 4; i++)
#pragma unroll
                for (int j = 0; j < 4; j++) {
                    acc1[i][j] += aa[i] * p[j];
                    acc2[i][j] += aa[i] * q[j];
                }
        }
        __syncthreads();
    }
#pragma unroll
    for (int i = 0; i < 4; i++) {
        int sl = slots[ty * 4 + i];
        if (sl < 0) continue;
#pragma unroll
        for (int j = 0; j < 4; j++) {
            float h1 = acc1[i][j], h2 = acc2[i][j];
            float g = (h1 / (1.f + expf(-h1))) * h2;
            d_g[(size_t)sl * ED_ + col0 + tx * 4 + j] = g;
        }
    }
}

// ---------------- expert GEMM2: Ys = G @ W3[e]^T  (W3 [D,ED] row-major) ----------------
__global__ void expert_gemm2(const float* __restrict__ experts) {
    int e = blockIdx.z;
    int cnt = d_counts[e];
    int mt = blockIdx.y;
    if (mt * 64 >= cnt) return;
    __shared__ float As[16][64];
    __shared__ float Bs[16][64];
    __shared__ int slots[64];
    int tid = threadIdx.x;
    if (tid < 64) {
        int r = mt * 64 + tid;
        slots[tid] = (r < cnt) ? d_list[e * NSLOT + r] : -1;
    }
    __syncthreads();
    const float* W3 = experts + ((size_t)(2 * TE_ + e)) * D_ * ED_;
    int tx = tid & 15, ty = tid >> 4;
    int lm = tid >> 2, lk = (tid & 3) << 2;
    int col0 = blockIdx.x * 64;
    float acc[4][4] = {};
    for (int k0 = 0; k0 < ED_; k0 += 16) {
        int sl = slots[lm];
        bool valid = sl >= 0;
        float4 a = *(const float4*)(d_g + (size_t)(valid ? sl : 0) * ED_ + k0 + lk);
        As[lk + 0][lm] = valid ? a.x : 0.f;
        As[lk + 1][lm] = valid ? a.y : 0.f;
        As[lk + 2][lm] = valid ? a.z : 0.f;
        As[lk + 3][lm] = valid ? a.w : 0.f;
        float4 b = *(const float4*)(W3 + (size_t)(col0 + lm) * ED_ + k0 + lk);
        Bs[lk + 0][lm] = b.x; Bs[lk + 1][lm] = b.y; Bs[lk + 2][lm] = b.z; Bs[lk + 3][lm] = b.w;
        __syncthreads();
#pragma unroll
        for (int k = 0; k < 16; k++) {
            float4 av = ((const float4*)&As[k][0])[ty];
            float4 bv = ((const float4*)&Bs[k][0])[tx];
            float aa[4] = {av.x, av.y, av.z, av.w};
            float bb[4] = {bv.x, bv.y, bv.z, bv.w};
#pragma unroll
            for (int i = 0; i < 4; i++)
#pragma unroll
                for (int j = 0; j < 4; j++) acc[i][j] += aa[i] * bb[j];
        }
        __syncthreads();
    }
#pragma unroll
    for (int i = 0; i < 4; i++) {
        int sl = slots[ty * 4 + i];
        if (sl < 0) continue;
#pragma unroll
        for (int j = 0; j < 4; j++)
            d_ys[(size_t)sl * D_ + col0 + tx * 4 + j] = acc[i][j];
    }
}

// ---------------- combine routed outputs (scores + output_coeff) ----------------
__global__ void combine_kernel(const float* __restrict__ coeff) {
    int t = blockIdx.x, tid = threadIdx.x;
    float s0 = d_scores[t * 2], s1 = d_scores[t * 2 + 1];
    const float* y0 = d_ys + (size_t)(t * 2) * D_;
    const float* y1 = d_ys + (size_t)(t * 2 + 1) * D_;
    float* yo = d_y + (size_t)t * D_;
    for (int dd = tid; dd < D_; dd += 256)
        yo[dd] = (s0 * y0[dd] + s1 * y1[dd]) * coeff[dd];
}

// ---------------- shared expert swiglu ----------------
__global__ void swiglu_shared_kernel() {
    size_t i = (size_t)blockIdx.x * blockDim.x + threadIdx.x;
    if (i < (size_t)T_ * DS_) {
        size_t t = i / DS_, hh = i % DS_;
        float a = d_up[t * 2 * DS_ + hh];
        float b = d_up[t * 2 * DS_ + DS_ + hh];
        d_gs[i] = (a / (1.f + expf(-a))) * b;
    }
}

// ---------------- final: rmsnorm(shared) + add everything ----------------
__global__ void final_kernel(const float* __restrict__ sharedw, float* __restrict__ out) {
    int t = blockIdx.x;
    const float* ysh = d_ysh + (size_t)t * D_;
    float ss = 0.f;
    for (int i = threadIdx.x; i < D_; i += blockDim.x) { float v = ysh[i]; ss += v * v; }
    __shared__ float sh[32];
    float tot = block_reduce_sum(ss, sh);
    float rinv = rsqrtf(tot / (float)D_ + EPS_);
    const float* yr = d_y + (size_t)t * D_;
    const float* xr = d_xffn_in + (size_t)t * D_;
    float* o = out + (size_t)t * D_;
    for (int i = threadIdx.x; i < D_; i += blockDim.x)
        o[i] = yr[i] + ysh[i] * rinv * sharedw[i] + xr[i];
}

// ---------------- host launch ----------------
static float* symf(const void* sym) { void* p = nullptr; cudaGetSymbolAddress(&p, sym); return (float*)p; }

extern "C" void kernel_launch(void* const* d_in, const int* in_sizes, int n_in,
                              void* d_out, int out_size) {
    const float* x_input      = (const float*)d_in[0];
    const int*   indices      = (const int*)  d_in[1];
    const float* values       = (const float*)d_in[2];
    const float* attn_w       = (const float*)d_in[3];
    const float* attn_o_w     = (const float*)d_in[4];
    const float* attn_norm_w  = (const float*)d_in[5];
    const float* ffn_norm_w   = (const float*)d_in[6];
    const float* ffn_experts  = (const float*)d_in[7];
    const float* main_keys    = (const float*)d_in[8];
    const float* main_bias    = (const float*)d_in[9];
    const float* output_coeff = (const float*)d_in[10];
    const float* ffn_up_w     = (const float*)d_in[11];
    const float* ffn_down_w   = (const float*)d_in[12];
    const float* shared_norm_w= (const float*)d_in[13];
    float* out = (float*)d_out;

    float* p_xn      = symf(d_xn);
    float* p_qkv     = symf(d_qkv);
    float* p_ao      = symf(d_ao);
    float* p_xffn_in = symf(d_xffn_in);
    float* p_xffn    = symf(d_xffn);
    float* p_up      = symf(d_up);
    float* p_gs      = symf(d_gs);
    float* p_ysh     = symf(d_ysh);

    // attention block
    rmsnorm_kernel<<<T_, 256>>>(x_input, attn_norm_w, p_xn);
    sgemm_abt<0><<<dim3(3 * D_ / 64, T_ / 64), 256>>>(p_xn, attn_w, p_qkv, T_, 3 * D_, D_, nullptr);
    rope_kernel<<<dim3(S_, H_), 32>>>(p_qkv);
    attn_kernel<<<dim3(S_, H_), 128>>>(p_qkv, p_ao);
    sgemm_abt<1><<<dim3(D_ / 64, T_ / 64), 256>>>(p_ao, attn_o_w, p_xffn_in, T_, D_, D_, x_input);

    // ffn norm + router
    rmsnorm_kernel<<<T_, 256>>>(p_xffn_in, ffn_norm_w, p_xffn);
    router_kernel<<<T_, 32>>>(p_xffn, main_keys, indices, values, main_bias);
    zero_counts_kernel<<<1, 32>>>();
    scatter_kernel<<<(NSLOT + 255) / 256, 256>>>(indices);

    // routed experts (grouped, gathered)
    expert_gemm1<<<dim3(ED_ / 64, NSLOT / 64, TE_), 256>>>(p_xffn, ffn_experts);
    expert_gemm2<<<dim3(D_ / 64, NSLOT / 64, TE_), 256>>>(ffn_experts);
    combine_kernel<<<T_, 256>>>(output_coeff);

    // shared expert
    sgemm_abt<0><<<dim3(2 * DS_ / 64, T_ / 64), 256>>>(p_xffn, ffn_up_w, p_up, T_, 2 * DS_, D_, nullptr);
    swiglu_shared_kernel<<<((size_t)T_ * DS_ + 255) / 256, 256>>>();
    sgemm_abt<0><<<dim3(D_ / 64, T_ / 64), 256>>>(p_gs, ffn_down_w, p_ysh, T_, D_, DS_, nullptr);

    // final combine
    final_kernel<<<T_, 256>>>(shared_norm_w, out);
}

// round 5
// speedup vs baseline: 7.0218x; 7.0218x over previous
#include <cuda_runtime.h>
#include <cuda_bf16.h>
#include <math.h>
#include <stdint.h>

// ---------------- problem constants ----------------
#define S_   2048
#define D_   1024
#define H_   16
#define HD_  64
#define TE_  16
#define TOPK 2
#define ED_  512
#define DS_  2048
#define T_   2048
#define NSLOT (T_*TOPK)
#define EPS_ 1e-5f

// ---------------- scratch (device bss, no allocation) ----------------
__device__ __align__(256) __nv_bfloat16 d_xn_h[(size_t)T_*D_],     d_xn_l[(size_t)T_*D_];
__device__ __align__(256) __nv_bfloat16 d_aw_h[(size_t)3*D_*D_],   d_aw_l[(size_t)3*D_*D_];
__device__ __align__(256) __nv_bfloat16 d_ow_h[(size_t)D_*D_],     d_ow_l[(size_t)D_*D_];
__device__ __align__(256) __nv_bfloat16 d_ao_h[(size_t)T_*D_],     d_ao_l[(size_t)T_*D_];
__device__ __align__(256) __nv_bfloat16 d_xffn_h[(size_t)T_*D_],   d_xffn_l[(size_t)T_*D_];
__device__ __align__(256) __nv_bfloat16 d_upw_h[(size_t)2*DS_*D_], d_upw_l[(size_t)2*DS_*D_];
__device__ __align__(256) __nv_bfloat16 d_dnw_h[(size_t)D_*DS_],   d_dnw_l[(size_t)D_*DS_];
__device__ __align__(256) __nv_bfloat16 d_w12t_h[(size_t)TE_*2*ED_*D_], d_w12t_l[(size_t)TE_*2*ED_*D_];
__device__ __align__(256) __nv_bfloat16 d_w3_h[(size_t)TE_*D_*ED_],     d_w3_l[(size_t)TE_*D_*ED_];
__device__ __align__(256) __nv_bfloat16 d_g_h[(size_t)NSLOT*ED_],  d_g_l[(size_t)NSLOT*ED_];
__device__ __align__(256) __nv_bfloat16 d_gs_h[(size_t)T_*DS_],    d_gs_l[(size_t)T_*DS_];
__device__ __align__(256) float d_qkv[(size_t)T_*3*D_];
__device__ __align__(256) float d_xffn_in[(size_t)T_*D_];
__device__ __align__(256) float d_xffn[(size_t)T_*D_];
__device__ __align__(256) float d_h12[(size_t)NSLOT*2*ED_];
__device__ __align__(256) float d_ys[(size_t)NSLOT*D_];
__device__ __align__(256) float d_y[(size_t)T_*D_];
__device__ __align__(256) float d_up[(size_t)T_*2*DS_];
__device__ __align__(256) float d_ysh[(size_t)T_*D_];
__device__ float d_scores[NSLOT];
__device__ int   d_counts[TE_];
__device__ int   d_list[TE_*NSLOT];

// ---------------- helpers ----------------
__device__ __forceinline__ void f2hilo(float x, __nv_bfloat16* h, __nv_bfloat16* l) {
    __nv_bfloat16 hh = __float2bfloat16(x);
    *h = hh;
    *l = __float2bfloat16(x - __bfloat162float(hh));
}
__device__ __forceinline__ float block_reduce_sum(float v, float* sh) {
    __syncthreads();
    int lane = threadIdx.x & 31, wid = threadIdx.x >> 5;
#pragma unroll
    for (int o = 16; o; o >>= 1) v += __shfl_xor_sync(0xffffffffu, v, o);
    if (lane == 0) sh[wid] = v;
    __syncthreads();
    int nw = blockDim.x >> 5;
    v = (threadIdx.x < nw) ? sh[threadIdx.x] : 0.f;
    if (wid == 0) {
#pragma unroll
        for (int o = 16; o; o >>= 1) v += __shfl_xor_sync(0xffffffffu, v, o);
        if (lane == 0) sh[0] = v;
    }
    __syncthreads();
    return sh[0];
}
__device__ __forceinline__ void mma16816(float* d, const uint32_t* a, const uint32_t* b) {
    asm volatile(
        "mma.sync.aligned.m16n8k16.row.col.f32.bf16.bf16.f32 "
        "{%0,%1,%2,%3}, {%4,%5,%6,%7}, {%8,%9}, {%0,%1,%2,%3};"
        : "+f"(d[0]), "+f"(d[1]), "+f"(d[2]), "+f"(d[3])
        : "r"(a[0]), "r"(a[1]), "r"(a[2]), "r"(a[3]), "r"(b[0]), "r"(b[1]));
}

// ---------------- conversion kernels ----------------
__global__ void conv_hilo_kernel(const float* __restrict__ src, __nv_bfloat16* __restrict__ hi,
                                 __nv_bfloat16* __restrict__ lo, size_t n) {
    for (size_t i = (size_t)blockIdx.x * blockDim.x + threadIdx.x; i < n;
         i += (size_t)gridDim.x * blockDim.x)
        f2hilo(src[i], hi + i, lo + i);
}

// experts W1/W2 [m][e][k=D][n=ED] -> w12t [e][n'(=m*512+n)][k] hi/lo
__global__ void transpose_w12_kernel(const float* __restrict__ experts) {
    __shared__ float tile[32][33];
    int e = blockIdx.z;
    int n0 = blockIdx.x * 32, k0 = blockIdx.y * 32;
    for (int yy = threadIdx.y; yy < 32; yy += 8) {
        int k = k0 + yy;
        int ng = n0 + threadIdx.x;
        int m = ng >> 9, c = ng & 511;
        tile[yy][threadIdx.x] = experts[((size_t)(m * TE_ + e) * D_ + k) * ED_ + c];
    }
    __syncthreads();
    for (int yy = threadIdx.y; yy < 32; yy += 8) {
        int ng = n0 + yy;
        int k = k0 + threadIdx.x;
        size_t o = ((size_t)e << 20) + (size_t)ng * 1024 + k;
        f2hilo(tile[threadIdx.x][yy], d_w12t_h + o, d_w12t_l + o);
    }
}

// ---------------- rmsnorm (fp32 optional + hi/lo) ----------------
__global__ void rmsnorm_kernel(const float* __restrict__ x, const float* __restrict__ w,
                               float* __restrict__ outf, __nv_bfloat16* __restrict__ oh,
                               __nv_bfloat16* __restrict__ ol) {
    int row = blockIdx.x;
    const float* xr = x + (size_t)row * D_;
    float ss = 0.f;
    for (int i = threadIdx.x; i < D_; i += blockDim.x) { float v = xr[i]; ss += v * v; }
    __shared__ float sh[32];
    float tot = block_reduce_sum(ss, sh);
    float rinv = rsqrtf(tot / (float)D_ + EPS_);
    for (int i = threadIdx.x; i < D_; i += blockDim.x) {
        float v = xr[i] * rinv * w[i];
        size_t o = (size_t)row * D_ + i;
        if (outf) outf[o] = v;
        f2hilo(v, oh + o, ol + o);
    }
}

// ---------------- warp-MMA split-bf16 GEMM: C[M,N] = A @ B^T ----------------
// CTA tile 128x128, BK=32, 8 warps (2x4), warp tile 64x32, double-buffered smem.
#define SD    40                   /* smem row stride in bf16 (conflict-free) */
#define STG_E (4*128*SD)           /* bf16 elems per stage (Ah,Al,Bh,Bl) */
#define GEMM_SMEM (2*STG_E*2)      /* bytes */

template<int GATHER, int RES>
__global__ void __launch_bounds__(256, 1) gemm_mma(
    const __nv_bfloat16* __restrict__ Ah, const __nv_bfloat16* __restrict__ Al,
    const __nv_bfloat16* __restrict__ Bh, const __nv_bfloat16* __restrict__ Bl,
    float* __restrict__ C, const float* __restrict__ Res,
    int N, int K, long long bstride)
{
    __shared__ int s_row[128];
    __shared__ int s_out[128];
    int tid = threadIdx.x, wid = tid >> 5, lid = tid & 31;
    if (GATHER) {
        int e = blockIdx.z, cnt = d_counts[e];
        if ((int)blockIdx.y * 128 >= cnt) return;
        if (tid < 128) {
            int r = blockIdx.y * 128 + tid;
            int sl = (r < cnt) ? d_list[e * NSLOT + r] : -1;
            s_out[tid] = sl;
            s_row[tid] = (sl < 0) ? -1 : (GATHER == 1 ? (sl >> 1) : sl);
        }
        Bh += (size_t)blockIdx.z * bstride;
        Bl += (size_t)blockIdx.z * bstride;
    } else if (tid < 128) {
        int r = blockIdx.y * 128 + tid;
        s_row[tid] = r; s_out[tid] = r;
    }
    extern __shared__ __nv_bfloat16 sm[];
    int n0 = blockIdx.x * 128;
    int NC = K >> 5;
    __syncthreads();

    uint4 pf[8];
    auto load_regs = [&](int c) {
        int kc = c << 5;
#pragma unroll
        for (int j = 0; j < 2; j++) {
            int idx = tid + (j << 8);
            int row = idx >> 2, q = idx & 3;
            int ar = s_row[row];
            if (ar >= 0) {
                pf[j*4+0] = *((const uint4*)(Ah + (size_t)ar * K + kc) + q);
                pf[j*4+1] = *((const uint4*)(Al + (size_t)ar * K + kc) + q);
            } else {
                pf[j*4+0] = make_uint4(0u,0u,0u,0u);
                pf[j*4+1] = make_uint4(0u,0u,0u,0u);
            }
            pf[j*4+2] = *((const uint4*)(Bh + (size_t)(n0 + row) * K + kc) + q);
            pf[j*4+3] = *((const uint4*)(Bl + (size_t)(n0 + row) * K + kc) + q);
        }
    };
    auto store_regs = [&](int buf) {
        __nv_bfloat16* st = sm + buf * STG_E;
#pragma unroll
        for (int j = 0; j < 2; j++) {
            int idx = tid + (j << 8);
            int row = idx >> 2, q = idx & 3;
            int o = row * SD + q * 8;
            *(uint4*)(st + o)            = pf[j*4+0];
            *(uint4*)(st + 128*SD + o)   = pf[j*4+1];
            *(uint4*)(st + 2*128*SD + o) = pf[j*4+2];
            *(uint4*)(st + 3*128*SD + o) = pf[j*4+3];
        }
    };

    int wm = wid & 1, wn = wid >> 1;
    int r = lid >> 2, c2 = (lid & 3) << 1;
    float acc[4][4][4] = {};

    load_regs(0);
    store_regs(0);
    __syncthreads();
    for (int c = 0; c < NC; c++) {
        int buf = c & 1;
        if (c + 1 < NC) load_regs(c + 1);
        const __nv_bfloat16* Ahs = sm + buf * STG_E;
        const __nv_bfloat16* Als = Ahs + 128*SD;
        const __nv_bfloat16* Bhs = Ahs + 2*128*SD;
        const __nv_bfloat16* Bls = Ahs + 3*128*SD;
#pragma unroll
        for (int ks = 0; ks < 2; ks++) {
            int ko = ks << 4;
            uint32_t ah[4][4], al[4][4];
#pragma unroll
            for (int mt = 0; mt < 4; mt++) {
                int r0 = wm * 64 + mt * 16 + r;
                ah[mt][0] = *(const uint32_t*)(Ahs + r0 * SD + ko + c2);
                ah[mt][1] = *(const uint32_t*)(Ahs + (r0 + 8) * SD + ko + c2);
                ah[mt][2] = *(const uint32_t*)(Ahs + r0 * SD + ko + c2 + 8);
                ah[mt][3] = *(const uint32_t*)(Ahs + (r0 + 8) * SD + ko + c2 + 8);
                al[mt][0] = *(const uint32_t*)(Als + r0 * SD + ko + c2);
                al[mt][1] = *(const uint32_t*)(Als + (r0 + 8) * SD + ko + c2);
                al[mt][2] = *(const uint32_t*)(Als + r0 * SD + ko + c2 + 8);
                al[mt][3] = *(const uint32_t*)(Als + (r0 + 8) * SD + ko + c2 + 8);
            }
#pragma unroll
            for (int nt = 0; nt < 4; nt++) {
                int nr = wn * 32 + nt * 8 + r;
                uint32_t bh[2], bl[2];
                bh[0] = *(const uint32_t*)(Bhs + nr * SD + ko + c2);
                bh[1] = *(const uint32_t*)(Bhs + nr * SD + ko + c2 + 8);
                bl[0] = *(const uint32_t*)(Bls + nr * SD + ko + c2);
                bl[1] = *(const uint32_t*)(Bls + nr * SD + ko + c2 + 8);
#pragma unroll
                for (int mt = 0; mt < 4; mt++) {
                    mma16816(acc[mt][nt], ah[mt], bh);
                    mma16816(acc[mt][nt], al[mt], bh);
                    mma16816(acc[mt][nt], ah[mt], bl);
                }
            }
        }
        if (c + 1 < NC) {
            store_regs((c + 1) & 1);
            __syncthreads();
        }
    }

    // epilogue
#pragma unroll
    for (int mt = 0; mt < 4; mt++) {
        int rloc0 = wm * 64 + mt * 16 + r;
#pragma unroll
        for (int half = 0; half < 2; half++) {
            int rloc = rloc0 + half * 8;
            int outr = s_out[rloc];
            if (GATHER && outr < 0) continue;
            float* crow = C + (size_t)outr * N + n0;
#pragma unroll
            for (int nt = 0; nt < 4; nt++) {
                int col = wn * 32 + nt * 8 + c2;
                float v0 = acc[mt][nt][half * 2 + 0];
                float v1 = acc[mt][nt][half * 2 + 1];
                if (RES) {
                    const float* rrow = Res + (size_t)outr * N + n0;
                    v0 += rrow[col]; v1 += rrow[col + 1];
                }
                crow[col] = v0; crow[col + 1] = v1;
            }
        }
    }
}

// ---------------- RoPE (in place on q,k parts of qkv) ----------------
__global__ void rope_kernel(float* __restrict__ qkv) {
    int s = blockIdx.x, h = blockIdx.y, i = threadIdx.x;  // i in [0,32)
    float inv = powf(10000.0f, -(float)i / 32.0f);
    float fr = (float)s * inv;
    float c = cosf(fr), sn = sinf(fr);
    float* q = qkv + (size_t)s * 3 * D_ + h * HD_;
    float* k = q + D_;
    float q1 = q[i], q2 = q[i + 32];
    q[i] = q1 * c + q2 * sn;  q[i + 32] = -q1 * sn + q2 * c;
    float k1 = k[i], k2 = k[i + 32];
    k[i] = k1 * c + k2 * sn;  k[i + 32] = -k1 * sn + k2 * c;
}

// ---------------- flash attention: 64 q-tile x head, online softmax ----------------
#define AT_SMEM (4*64*68*4 + 2*64*4)
__global__ void flash_attn_kernel(const float* __restrict__ qkv) {
    extern __shared__ float fsm[];
    float* Qs = fsm;              // [d][q] stride 68
    float* Ks = Qs + 64 * 68;     // [d][k]
    float* Vs = Ks + 64 * 68;     // [k][d]
    float* Ps = Vs + 64 * 68;     // [k][q]
    float* ml = Ps + 64 * 68;     // m[64], l[64]
    int qt = blockIdx.x, h = blockIdx.y;
    int tid = threadIdx.x;
    int tx = tid & 15, ty = tid >> 4;
    int q0 = qt * 64;
#pragma unroll
    for (int i = 0; i < 4; i++) {
        int idx = tid + i * 256;
        int r = idx >> 4, c4 = (idx & 15) * 4;
        float4 v = *(const float4*)(qkv + (size_t)(q0 + r) * 3 * D_ + h * HD_ + c4);
        Qs[(c4 + 0) * 68 + r] = v.x; Qs[(c4 + 1) * 68 + r] = v.y;
        Qs[(c4 + 2) * 68 + r] = v.z; Qs[(c4 + 3) * 68 + r] = v.w;
    }
    if (tid < 64) { ml[tid] = -1e30f; ml[64 + tid] = 0.f; }
    float o[4][4] = {};
    for (int kt = 0; kt <= qt; kt++) {
        __syncthreads();
#pragma unroll
        for (int i = 0; i < 4; i++) {
            int idx = tid + i * 256;
            int r = idx >> 4, c4 = (idx & 15) * 4;
            const float* src = qkv + (size_t)(kt * 64 + r) * 3 * D_ + h * HD_;
            float4 kv = *(const float4*)(src + D_ + c4);
            Ks[(c4 + 0) * 68 + r] = kv.x; Ks[(c4 + 1) * 68 + r] = kv.y;
            Ks[(c4 + 2) * 68 + r] = kv.z; Ks[(c4 + 3) * 68 + r] = kv.w;
            *(float4*)&Vs[r * 68 + c4] = *(const float4*)(src + 2 * D_ + c4);
        }
        __syncthreads();
        float acc[4][4] = {};
#pragma unroll 4
        for (int d = 0; d < 64; d++) {
            float4 av = *(const float4*)&Qs[d * 68 + ty * 4];
            float4 bv = *(const float4*)&Ks[d * 68 + tx * 4];
            float aa[4] = {av.x, av.y, av.z, av.w};
            float bb[4] = {bv.x, bv.y, bv.z, bv.w};
#pragma unroll
            for (int i = 0; i < 4; i++)
#pragma unroll
                for (int j = 0; j < 4; j++) acc[i][j] += aa[i] * bb[j];
        }
        bool diag = (kt == qt);
#pragma unroll
        for (int i = 0; i < 4; i++)
#pragma unroll
            for (int j = 0; j < 4; j++) {
                float s = acc[i][j] * 0.125f;
                if (diag && (tx * 4 + j) > (ty * 4 + i)) s = -1e30f;
                acc[i][j] = s;
            }
        float fac[4], p[4][4];
        float nm[4], rs[4];
#pragma unroll
        for (int i = 0; i < 4; i++) {
            float mx = fmaxf(fmaxf(acc[i][0], acc[i][1]), fmaxf(acc[i][2], acc[i][3]));
#pragma unroll
            for (int off = 8; off; off >>= 1) mx = fmaxf(mx, __shfl_xor_sync(0xffffffffu, mx, off, 16));
            float mo = ml[ty * 4 + i];
            float newm = fmaxf(mo, mx);
            float sum = 0.f;
#pragma unroll
            for (int j = 0; j < 4; j++) { float e = __expf(acc[i][j] - newm); p[i][j] = e; sum += e; }
#pragma unroll
            for (int off = 8; off; off >>= 1) sum += __shfl_xor_sync(0xffffffffu, sum, off, 16);
            fac[i] = __expf(mo - newm);
            nm[i] = newm; rs[i] = sum;
        }
        __syncwarp();
        if (tx == 0) {
#pragma unroll
            for (int i = 0; i < 4; i++) {
                int rr = ty * 4 + i;
                ml[rr] = nm[i];
                ml[64 + rr] = ml[64 + rr] * fac[i] + rs[i];
            }
        }
#pragma unroll
        for (int i = 0; i < 4; i++)
#pragma unroll
            for (int j = 0; j < 4; j++) {
                o[i][j] *= fac[i];
                Ps[(tx * 4 + j) * 68 + ty * 4 + i] = p[i][j];
            }
        __syncthreads();
#pragma unroll 4
        for (int k = 0; k < 64; k++) {
            float4 av = *(const float4*)&Ps[k * 68 + ty * 4];
            float4 bv = *(const float4*)&Vs[k * 68 + tx * 4];
            float aa[4] = {av.x, av.y, av.z, av.w};
            float bb[4] = {bv.x, bv.y, bv.z, bv.w};
#pragma unroll
            for (int i = 0; i < 4; i++)
#pragma unroll
                for (int j = 0; j < 4; j++) o[i][j] += aa[i] * bb[j];
        }
    }
    __syncthreads();
#pragma unroll
    for (int i = 0; i < 4; i++) {
        float linv = 1.0f / ml[64 + ty * 4 + i];
        size_t row = (size_t)(q0 + ty * 4 + i) * D_ + h * HD_ + tx * 4;
#pragma unroll
        for (int j = 0; j < 4; j++)
            f2hilo(o[i][j] * linv, d_ao_h + row + j, d_ao_l + row + j);
    }
}

// ---------------- router ----------------
__global__ void router_kernel(const float* __restrict__ xffn, const float* __restrict__ keys,
                              const int* __restrict__ idx, const float* __restrict__ vals,
                              const float* __restrict__ bias) {
    int t = blockIdx.x, lane = threadIdx.x;
    int e0 = idx[t * 2], e1 = idx[t * 2 + 1];
    const float* xr = xffn + (size_t)t * D_;
    float s0 = 0.f, s1 = 0.f;
    for (int d = lane; d < D_; d += 32) {
        float x = xr[d];
        s0 += x * keys[d * TE_ + e0];
        s1 += x * keys[d * TE_ + e1];
    }
#pragma unroll
    for (int o = 16; o; o >>= 1) {
        s0 += __shfl_xor_sync(0xffffffffu, s0, o);
        s1 += __shfl_xor_sync(0xffffffffu, s1, o);
    }
    if (lane == 0) {
        float v0 = vals[t * 2] + s0 + bias[e0];
        float v1 = vals[t * 2 + 1] + s1 + bias[e1];
        float mm = fmaxf(v0, v1);
        float a = expf(v0 - mm), b = expf(v1 - mm);
        float inv = 1.0f / (a + b);
        d_scores[t * 2] = a * inv;
        d_scores[t * 2 + 1] = b * inv;
    }
}

__global__ void zero_counts_kernel() {
    if (threadIdx.x < TE_) d_counts[threadIdx.x] = 0;
}
__global__ void scatter_kernel(const int* __restrict__ idx) {
    int slot = blockIdx.x * blockDim.x + threadIdx.x;
    if (slot < NSLOT) {
        int e = idx[slot];
        int p = atomicAdd(&d_counts[e], 1);
        d_list[e * NSLOT + p] = slot;
    }
}

// ---------------- swiglu (experts): h12 -> g hi/lo ----------------
__global__ void swiglu_expert_kernel() {
    int i = blockIdx.x * 256 + threadIdx.x;
    if (i < NSLOT * ED_) {
        int sl = i >> 9, j = i & 511;
        float a = d_h12[(size_t)sl * 1024 + j];
        float b = d_h12[(size_t)sl * 1024 + 512 + j];
        float g = (a / (1.f + __expf(-a))) * b;
        f2hilo(g, d_g_h + (size_t)sl * ED_ + j, d_g_l + (size_t)sl * ED_ + j);
    }
}

// ---------------- shared swiglu: up -> gs hi/lo ----------------
__global__ void swiglu_shared_kernel() {
    size_t i = (size_t)blockIdx.x * 256 + threadIdx.x;
    if (i < (size_t)T_ * DS_) {
        size_t t = i / DS_, j = i % DS_;
        float a = d_up[t * 2 * DS_ + j];
        float b = d_up[t * 2 * DS_ + DS_ + j];
        float g = (a / (1.f + __expf(-a))) * b;
        f2hilo(g, d_gs_h + i, d_gs_l + i);
    }
}

// ---------------- combine routed outputs ----------------
__global__ void combine_kernel(const float* __restrict__ coeff) {
    int t = blockIdx.x, tid = threadIdx.x;
    float s0 = d_scores[t * 2], s1 = d_scores[t * 2 + 1];
    const float* y0 = d_ys + (size_t)(t * 2) * D_;
    const float* y1 = d_ys + (size_t)(t * 2 + 1) * D_;
    float* yo = d_y + (size_t)t * D_;
    for (int dd = tid; dd < D_; dd += 256)
        yo[dd] = (s0 * y0[dd] + s1 * y1[dd]) * coeff[dd];
}

// ---------------- final combine ----------------
__global__ void final_kernel(const float* __restrict__ sharedw, float* __restrict__ out) {
    int t = blockIdx.x;
    const float* ysh = d_ysh + (size_t)t * D_;
    float ss = 0.f;
    for (int i = threadIdx.x; i < D_; i += blockDim.x) { float v = ysh[i]; ss += v * v; }
    __shared__ float sh[32];
    float tot = block_reduce_sum(ss, sh);
    float rinv = rsqrtf(tot / (float)D_ + EPS_);
    const float* yr = d_y + (size_t)t * D_;
    const float* xr = d_xffn_in + (size_t)t * D_;
    float* o = out + (size_t)t * D_;
    for (int i = threadIdx.x; i < D_; i += blockDim.x)
        o[i] = yr[i] + ysh[i] * rinv * sharedw[i] + xr[i];
}

// ---------------- host launch ----------------
static void* sym(const void* s) { void* p = nullptr; cudaGetSymbolAddress(&p, s); return p; }

extern "C" void kernel_launch(void* const* d_in, const int* in_sizes, int n_in,
                              void* d_out, int out_size) {
    const float* x_input      = (const float*)d_in[0];
    const int*   indices      = (const int*)  d_in[1];
    const float* values       = (const float*)d_in[2];
    const float* attn_w       = (const float*)d_in[3];
    const float* attn_o_w     = (const float*)d_in[4];
    const float* attn_norm_w  = (const float*)d_in[5];
    const float* ffn_norm_w   = (const float*)d_in[6];
    const float* ffn_experts  = (const float*)d_in[7];
    const float* main_keys    = (const float*)d_in[8];
    const float* main_bias    = (const float*)d_in[9];
    const float* output_coeff = (const float*)d_in[10];
    const float* ffn_up_w     = (const float*)d_in[11];
    const float* ffn_down_w   = (const float*)d_in[12];
    const float* shared_norm_w= (const float*)d_in[13];
    float* out = (float*)d_out;

    cudaFuncSetAttribute((const void*)gemm_mma<0,0>, cudaFuncAttributeMaxDynamicSharedMemorySize, GEMM_SMEM);
    cudaFuncSetAttribute((const void*)gemm_mma<0,1>, cudaFuncAttributeMaxDynamicSharedMemorySize, GEMM_SMEM);
    cudaFuncSetAttribute((const void*)gemm_mma<1,0>, cudaFuncAttributeMaxDynamicSharedMemorySize, GEMM_SMEM);
    cudaFuncSetAttribute((const void*)gemm_mma<2,0>, cudaFuncAttributeMaxDynamicSharedMemorySize, GEMM_SMEM);
    cudaFuncSetAttribute((const void*)flash_attn_kernel, cudaFuncAttributeMaxDynamicSharedMemorySize, AT_SMEM);

    __nv_bfloat16 *p_xn_h=(__nv_bfloat16*)sym(d_xn_h), *p_xn_l=(__nv_bfloat16*)sym(d_xn_l);
    __nv_bfloat16 *p_aw_h=(__nv_bfloat16*)sym(d_aw_h), *p_aw_l=(__nv_bfloat16*)sym(d_aw_l);
    __nv_bfloat16 *p_ow_h=(__nv_bfloat16*)sym(d_ow_h), *p_ow_l=(__nv_bfloat16*)sym(d_ow_l);
    __nv_bfloat16 *p_ao_h=(__nv_bfloat16*)sym(d_ao_h), *p_ao_l=(__nv_bfloat16*)sym(d_ao_l);
    __nv_bfloat16 *p_xf_h=(__nv_bfloat16*)sym(d_xffn_h), *p_xf_l=(__nv_bfloat16*)sym(d_xffn_l);
    __nv_bfloat16 *p_uw_h=(__nv_bfloat16*)sym(d_upw_h), *p_uw_l=(__nv_bfloat16*)sym(d_upw_l);
    __nv_bfloat16 *p_dw_h=(__nv_bfloat16*)sym(d_dnw_h), *p_dw_l=(__nv_bfloat16*)sym(d_dnw_l);
    __nv_bfloat16 *p_w12_h=(__nv_bfloat16*)sym(d_w12t_h), *p_w12_l=(__nv_bfloat16*)sym(d_w12t_l);
    __nv_bfloat16 *p_w3_h=(__nv_bfloat16*)sym(d_w3_h), *p_w3_l=(__nv_bfloat16*)sym(d_w3_l);
    __nv_bfloat16 *p_g_h=(__nv_bfloat16*)sym(d_g_h), *p_g_l=(__nv_bfloat16*)sym(d_g_l);
    __nv_bfloat16 *p_gs_h=(__nv_bfloat16*)sym(d_gs_h), *p_gs_l=(__nv_bfloat16*)sym(d_gs_l);
    float *p_qkv=(float*)sym(d_qkv), *p_xffn_in=(float*)sym(d_xffn_in), *p_xffn=(float*)sym(d_xffn);
    float *p_h12=(float*)sym(d_h12), *p_ys=(float*)sym(d_ys), *p_up=(float*)sym(d_up);
    float *p_ysh=(float*)sym(d_ysh);

    // per-launch weight conversions (deterministic, stateless)
    conv_hilo_kernel<<<512, 256>>>(attn_w, p_aw_h, p_aw_l, (size_t)3 * D_ * D_);
    conv_hilo_kernel<<<512, 256>>>(attn_o_w, p_ow_h, p_ow_l, (size_t)D_ * D_);
    conv_hilo_kernel<<<512, 256>>>(ffn_up_w, p_uw_h, p_uw_l, (size_t)2 * DS_ * D_);
    conv_hilo_kernel<<<512, 256>>>(ffn_down_w, p_dw_h, p_dw_l, (size_t)D_ * DS_);
    conv_hilo_kernel<<<512, 256>>>(ffn_experts + (size_t)2 * TE_ * D_ * ED_, p_w3_h, p_w3_l,
                                   (size_t)TE_ * D_ * ED_);
    transpose_w12_kernel<<<dim3(32, 32, 16), dim3(32, 8)>>>(ffn_experts);

    // attention block
    rmsnorm_kernel<<<T_, 256>>>(x_input, attn_norm_w, nullptr, p_xn_h, p_xn_l);
    gemm_mma<0,0><<<dim3(24, 16), 256, GEMM_SMEM>>>(p_xn_h, p_xn_l, p_aw_h, p_aw_l,
                                                    p_qkv, nullptr, 3 * D_, D_, 0);
    rope_kernel<<<dim3(S_, H_), 32>>>(p_qkv);
    flash_attn_kernel<<<dim3(S_ / 64, H_), 256, AT_SMEM>>>(p_qkv);
    gemm_mma<0,1><<<dim3(8, 16), 256, GEMM_SMEM>>>(p_ao_h, p_ao_l, p_ow_h, p_ow_l,
                                                   p_xffn_in, x_input, D_, D_, 0);

    // ffn norm + router
    rmsnorm_kernel<<<T_, 256>>>(p_xffn_in, ffn_norm_w, p_xffn, p_xf_h, p_xf_l);
    router_kernel<<<T_, 32>>>(p_xffn, main_keys, indices, values, main_bias);
    zero_counts_kernel<<<1, 32>>>();
    scatter_kernel<<<(NSLOT + 255) / 256, 256>>>(indices);

    // routed experts
    gemm_mma<1,0><<<dim3(8, NSLOT / 128, TE_), 256, GEMM_SMEM>>>(
        p_xf_h, p_xf_l, p_w12_h, p_w12_l, p_h12, nullptr, 1024, 1024, (long long)1024 * 1024);
    swiglu_expert_kernel<<<(NSLOT * ED_ + 255) / 256, 256>>>();
    gemm_mma<2,0><<<dim3(8, NSLOT / 128, TE_), 256, GEMM_SMEM>>>(
        p_g_h, p_g_l, p_w3_h, p_w3_l, p_ys, nullptr, 1024, 512, (long long)D_ * ED_);
    combine_kernel<<<T_, 256>>>(output_coeff);

    // shared expert
    gemm_mma<0,0><<<dim3(32, 16), 256, GEMM_SMEM>>>(p_xf_h, p_xf_l, p_uw_h, p_uw_l,
                                                    p_up, nullptr, 2 * DS_, D_, 0);
    swiglu_shared_kernel<<<((size_t)T_ * DS_ + 255) / 256, 256>>>();
    gemm_mma<0,0><<<dim3(8, 16), 256, GEMM_SMEM>>>(p_gs_h, p_gs_l, p_dw_h, p_dw_l,
                                                   p_ysh, nullptr, D_, DS_, 0);

    // final combine
    final_kernel<<<T_, 256>>>(shared_norm_w, out);
}

// round 6
// speedup vs baseline: 7.9029x; 1.1255x over previous
#include <cuda_runtime.h>
#include <cuda_bf16.h>
#include <math.h>
#include <stdint.h>

// ---------------- problem constants ----------------
#define S_   2048
#define D_   1024
#define H_   16
#define HD_  64
#define TE_  16
#define TOPK 2
#define ED_  512
#define DS_  2048
#define T_   2048
#define NSLOT (T_*TOPK)
#define EPS_ 1e-5f

// ---------------- scratch (device bss, no allocation) ----------------
__device__ __align__(256) __nv_bfloat16 d_xn_h[(size_t)T_*D_],     d_xn_l[(size_t)T_*D_];
__device__ __align__(256) __nv_bfloat16 d_aw_h[(size_t)3*D_*D_],   d_aw_l[(size_t)3*D_*D_];
__device__ __align__(256) __nv_bfloat16 d_ow_h[(size_t)D_*D_],     d_ow_l[(size_t)D_*D_];
__device__ __align__(256) __nv_bfloat16 d_ao_h[(size_t)T_*D_],     d_ao_l[(size_t)T_*D_];
__device__ __align__(256) __nv_bfloat16 d_xffn_h[(size_t)T_*D_],   d_xffn_l[(size_t)T_*D_];
__device__ __align__(256) __nv_bfloat16 d_upw_h[(size_t)2*DS_*D_], d_upw_l[(size_t)2*DS_*D_];
__device__ __align__(256) __nv_bfloat16 d_dnw_h[(size_t)D_*DS_],   d_dnw_l[(size_t)D_*DS_];
__device__ __align__(256) __nv_bfloat16 d_w12t_h[(size_t)TE_*2*ED_*D_], d_w12t_l[(size_t)TE_*2*ED_*D_];
__device__ __align__(256) __nv_bfloat16 d_w3_h[(size_t)TE_*D_*ED_],     d_w3_l[(size_t)TE_*D_*ED_];
__device__ __align__(256) __nv_bfloat16 d_g_h[(size_t)NSLOT*ED_],  d_g_l[(size_t)NSLOT*ED_];
__device__ __align__(256) __nv_bfloat16 d_gs_h[(size_t)T_*DS_],    d_gs_l[(size_t)T_*DS_];
__device__ __align__(256) float d_qkv[(size_t)T_*3*D_];
__device__ __align__(256) float d_xffn_in[(size_t)T_*D_];
__device__ __align__(256) float d_xffn[(size_t)T_*D_];
__device__ __align__(256) float d_h12[(size_t)NSLOT*2*ED_];
__device__ __align__(256) float d_ys[(size_t)NSLOT*D_];
__device__ __align__(256) float d_y[(size_t)T_*D_];
__device__ __align__(256) float d_up[(size_t)T_*2*DS_];
__device__ __align__(256) float d_ysh[(size_t)T_*D_];
__device__ float d_scores[NSLOT];
__device__ int   d_counts[TE_];
__device__ int   d_list[TE_*NSLOT];

// ---------------- helpers ----------------
__device__ __forceinline__ void f2hilo(float x, __nv_bfloat16* h, __nv_bfloat16* l) {
    __nv_bfloat16 hh = __float2bfloat16(x);
    *h = hh;
    *l = __float2bfloat16(x - __bfloat162float(hh));
}
__device__ __forceinline__ uint32_t bpack(__nv_bfloat16 a, __nv_bfloat16 b) {
    uint16_t ua = *(uint16_t*)&a, ub = *(uint16_t*)&b;
    return ((uint32_t)ub << 16) | ua;
}
__device__ __forceinline__ float block_reduce_sum(float v, float* sh) {
    __syncthreads();
    int lane = threadIdx.x & 31, wid = threadIdx.x >> 5;
#pragma unroll
    for (int o = 16; o; o >>= 1) v += __shfl_xor_sync(0xffffffffu, v, o);
    if (lane == 0) sh[wid] = v;
    __syncthreads();
    int nw = blockDim.x >> 5;
    v = (threadIdx.x < nw) ? sh[threadIdx.x] : 0.f;
    if (wid == 0) {
#pragma unroll
        for (int o = 16; o; o >>= 1) v += __shfl_xor_sync(0xffffffffu, v, o);
        if (lane == 0) sh[0] = v;
    }
    __syncthreads();
    return sh[0];
}
__device__ __forceinline__ void mma16816(float* d, const uint32_t* a, const uint32_t* b) {
    asm volatile(
        "mma.sync.aligned.m16n8k16.row.col.f32.bf16.bf16.f32 "
        "{%0,%1,%2,%3}, {%4,%5,%6,%7}, {%8,%9}, {%0,%1,%2,%3};"
        : "+f"(d[0]), "+f"(d[1]), "+f"(d[2]), "+f"(d[3])
        : "r"(a[0]), "r"(a[1]), "r"(a[2]), "r"(a[3]), "r"(b[0]), "r"(b[1]));
}
__device__ __forceinline__ void ldsm_x4(uint32_t* r, uint32_t addr) {
    asm volatile("ldmatrix.sync.aligned.m8n8.x4.shared.b16 {%0,%1,%2,%3}, [%4];"
        : "=r"(r[0]), "=r"(r[1]), "=r"(r[2]), "=r"(r[3]) : "r"(addr));
}

// ---------------- conversion kernels (vectorized) ----------------
__global__ void conv_hilo_kernel(const float4* __restrict__ src, uint2* __restrict__ hi,
                                 uint2* __restrict__ lo, size_t n4) {
    for (size_t i = (size_t)blockIdx.x * blockDim.x + threadIdx.x; i < n4;
         i += (size_t)gridDim.x * blockDim.x) {
        float4 v = src[i];
        __nv_bfloat16 h0, l0, h1, l1, h2, l2, h3, l3;
        f2hilo(v.x, &h0, &l0); f2hilo(v.y, &h1, &l1);
        f2hilo(v.z, &h2, &l2); f2hilo(v.w, &h3, &l3);
        uint2 ho, lw;
        ho.x = bpack(h0, h1); ho.y = bpack(h2, h3);
        lw.x = bpack(l0, l1); lw.y = bpack(l2, l3);
        hi[i] = ho; lo[i] = lw;
    }
}

// experts W1/W2 [m][e][k=D][n=ED] -> w12t [e][n'(=m*512+n)][k] hi/lo (packed stores)
__global__ void transpose_w12_kernel(const float* __restrict__ experts) {
    __shared__ float tile[64][33];
    int e = blockIdx.z;
    int n0 = blockIdx.x * 32, k0 = blockIdx.y * 64;
    int m = n0 >> 9, c0 = n0 & 511;
    for (int kk = threadIdx.y; kk < 64; kk += 8)
        tile[kk][threadIdx.x] =
            experts[((size_t)(m * TE_ + e) * D_ + k0 + kk) * ED_ + c0 + threadIdx.x];
    __syncthreads();
    for (int ny = threadIdx.y; ny < 32; ny += 8) {
        float va = tile[threadIdx.x * 2][ny];
        float vb = tile[threadIdx.x * 2 + 1][ny];
        __nv_bfloat16 ha, la, hb, lb;
        f2hilo(va, &ha, &la); f2hilo(vb, &hb, &lb);
        size_t o = ((size_t)e << 20) + (size_t)(n0 + ny) * 1024 + k0 + threadIdx.x * 2;
        *(uint32_t*)(d_w12t_h + o) = bpack(ha, hb);
        *(uint32_t*)(d_w12t_l + o) = bpack(la, lb);
    }
}

// ---------------- rmsnorm (fp32 optional + hi/lo) ----------------
__global__ void rmsnorm_kernel(const float* __restrict__ x, const float* __restrict__ w,
                               float* __restrict__ outf, __nv_bfloat16* __restrict__ oh,
                               __nv_bfloat16* __restrict__ ol) {
    int row = blockIdx.x;
    const float* xr = x + (size_t)row * D_;
    float ss = 0.f;
    for (int i = threadIdx.x; i < D_; i += blockDim.x) { float v = xr[i]; ss += v * v; }
    __shared__ float sh[32];
    float tot = block_reduce_sum(ss, sh);
    float rinv = rsqrtf(tot / (float)D_ + EPS_);
    for (int i = threadIdx.x; i < D_; i += blockDim.x) {
        float v = xr[i] * rinv * w[i];
        size_t o = (size_t)row * D_ + i;
        if (outf) outf[o] = v;
        f2hilo(v, oh + o, ol + o);
    }
}

// ---------------- warp-MMA split-bf16 GEMM: C[M,N] = A @ B^T ----------------
// CTA tile 128x128, BK=32, 8 warps (2x4), warp tile 64x32, double-buffered smem,
// ldmatrix fragment loads.
#define SD    40                   /* smem row stride in bf16 (conflict-free) */
#define STG_E (4*128*SD)           /* bf16 elems per stage (Ah,Al,Bh,Bl) */
#define GEMM_SMEM (2*STG_E*2)      /* bytes */

template<int GATHER, int RES>
__global__ void __launch_bounds__(256, 1) gemm_mma(
    const __nv_bfloat16* __restrict__ Ah, const __nv_bfloat16* __restrict__ Al,
    const __nv_bfloat16* __restrict__ Bh, const __nv_bfloat16* __restrict__ Bl,
    float* __restrict__ C, const float* __restrict__ Res,
    int N, int K, long long bstride)
{
    __shared__ int s_row[128];
    __shared__ int s_out[128];
    int tid = threadIdx.x, wid = tid >> 5, lid = tid & 31;
    if (GATHER) {
        int e = blockIdx.z, cnt = d_counts[e];
        if ((int)blockIdx.y * 128 >= cnt) return;
        if (tid < 128) {
            int r = blockIdx.y * 128 + tid;
            int sl = (r < cnt) ? d_list[e * NSLOT + r] : -1;
            s_out[tid] = sl;
            s_row[tid] = (sl < 0) ? -1 : (GATHER == 1 ? (sl >> 1) : sl);
        }
        Bh += (size_t)blockIdx.z * bstride;
        Bl += (size_t)blockIdx.z * bstride;
    } else if (tid < 128) {
        int r = blockIdx.y * 128 + tid;
        s_row[tid] = r; s_out[tid] = r;
    }
    extern __shared__ __nv_bfloat16 sm[];
    uint32_t smb = (uint32_t)__cvta_generic_to_shared(sm);
    int n0 = blockIdx.x * 128;
    int NC = K >> 5;
    __syncthreads();

    uint4 pf[8];
    auto load_regs = [&](int c) {
        int kc = c << 5;
#pragma unroll
        for (int j = 0; j < 2; j++) {
            int idx = tid + (j << 8);
            int row = idx >> 2, q = idx & 3;
            int ar = s_row[row];
            if (ar >= 0) {
                pf[j*4+0] = *((const uint4*)(Ah + (size_t)ar * K + kc) + q);
                pf[j*4+1] = *((const uint4*)(Al + (size_t)ar * K + kc) + q);
            } else {
                pf[j*4+0] = make_uint4(0u,0u,0u,0u);
                pf[j*4+1] = make_uint4(0u,0u,0u,0u);
            }
            pf[j*4+2] = *((const uint4*)(Bh + (size_t)(n0 + row) * K + kc) + q);
            pf[j*4+3] = *((const uint4*)(Bl + (size_t)(n0 + row) * K + kc) + q);
        }
    };
    auto store_regs = [&](int buf) {
        __nv_bfloat16* st = sm + buf * STG_E;
#pragma unroll
        for (int j = 0; j < 2; j++) {
            int idx = tid + (j << 8);
            int row = idx >> 2, q = idx & 3;
            int o = row * SD + q * 8;
            *(uint4*)(st + o)            = pf[j*4+0];
            *(uint4*)(st + 128*SD + o)   = pf[j*4+1];
            *(uint4*)(st + 2*128*SD + o) = pf[j*4+2];
            *(uint4*)(st + 3*128*SD + o) = pf[j*4+3];
        }
    };

    int wm = wid & 1, wn = wid >> 1;
    int r = lid >> 2, c2 = (lid & 3) << 1;
    // ldmatrix per-lane byte offsets
    uint32_t a_lane = (uint32_t)(((lid & 15) * SD + ((lid >> 4) << 3)) << 1);
    uint32_t b_lane = (uint32_t)((((((lid >> 4) << 3) + (lid & 7)) * SD) + (((lid >> 3) & 1) << 3)) << 1);
    float acc[4][4][4] = {};

    load_regs(0);
    store_regs(0);
    __syncthreads();
    for (int c = 0; c < NC; c++) {
        int buf = c & 1;
        if (c + 1 < NC) load_regs(c + 1);
        uint32_t base = smb + (uint32_t)(buf * STG_E * 2);
#pragma unroll
        for (int ks = 0; ks < 2; ks++) {
            uint32_t kb = (uint32_t)(ks << 5);   // ko*2 bytes (ko = 16*ks)
            uint32_t ah[4][4], al[4][4];
#pragma unroll
            for (int mt = 0; mt < 4; mt++) {
                uint32_t ab = base + (uint32_t)(((wm * 64 + mt * 16) * SD) << 1) + kb + a_lane;
                ldsm_x4(ah[mt], ab);
                ldsm_x4(al[mt], ab + (uint32_t)((128 * SD) << 1));
            }
            uint32_t bh[4][2], bl[4][2];
#pragma unroll
            for (int p = 0; p < 2; p++) {
                uint32_t bb = base + (uint32_t)((2 * 128 * SD) << 1)
                            + (uint32_t)(((wn * 32 + p * 16) * SD) << 1) + kb + b_lane;
                uint32_t t[4];
                ldsm_x4(t, bb);
                bh[2*p][0] = t[0]; bh[2*p][1] = t[1];
                bh[2*p+1][0] = t[2]; bh[2*p+1][1] = t[3];
                ldsm_x4(t, bb + (uint32_t)((128 * SD) << 1));
                bl[2*p][0] = t[0]; bl[2*p][1] = t[1];
                bl[2*p+1][0] = t[2]; bl[2*p+1][1] = t[3];
            }
#pragma unroll
            for (int nt = 0; nt < 4; nt++)
#pragma unroll
                for (int mt = 0; mt < 4; mt++) {
                    mma16816(acc[mt][nt], ah[mt], bh[nt]);
                    mma16816(acc[mt][nt], al[mt], bh[nt]);
                    mma16816(acc[mt][nt], ah[mt], bl[nt]);
                }
        }
        if (c + 1 < NC) {
            store_regs((c + 1) & 1);
            __syncthreads();
        }
    }

    // epilogue (float2 stores)
#pragma unroll
    for (int mt = 0; mt < 4; mt++) {
        int rloc0 = wm * 64 + mt * 16 + r;
#pragma unroll
        for (int half = 0; half < 2; half++) {
            int rloc = rloc0 + half * 8;
            int outr = s_out[rloc];
            if (GATHER && outr < 0) continue;
            float* crow = C + (size_t)outr * N + n0;
#pragma unroll
            for (int nt = 0; nt < 4; nt++) {
                int col = wn * 32 + nt * 8 + c2;
                float v0 = acc[mt][nt][half * 2 + 0];
                float v1 = acc[mt][nt][half * 2 + 1];
                if (RES) {
                    const float* rrow = Res + (size_t)outr * N + n0;
                    v0 += rrow[col]; v1 += rrow[col + 1];
                }
                float2 fv = make_float2(v0, v1);
                *(float2*)(crow + col) = fv;
            }
        }
    }
}

// ---------------- RoPE (in place on q,k parts of qkv) ----------------
__global__ void rope_kernel(float* __restrict__ qkv) {
    int s = blockIdx.x, h = blockIdx.y, i = threadIdx.x;  // i in [0,32)
    float inv = powf(10000.0f, -(float)i / 32.0f);
    float fr = (float)s * inv;
    float c = cosf(fr), sn = sinf(fr);
    float* q = qkv + (size_t)s * 3 * D_ + h * HD_;
    float* k = q + D_;
    float q1 = q[i], q2 = q[i + 32];
    q[i] = q1 * c + q2 * sn;  q[i + 32] = -q1 * sn + q2 * c;
    float k1 = k[i], k2 = k[i + 32];
    k[i] = k1 * c + k2 * sn;  k[i + 32] = -k1 * sn + k2 * c;
}

// ---------------- flash attention: 64 q-tile x head, online softmax ----------------
#define AT_SMEM (4*64*68*4 + 2*64*4)
__global__ void flash_attn_kernel(const float* __restrict__ qkv) {
    extern __shared__ float fsm[];
    float* Qs = fsm;              // [d][q] stride 68
    float* Ks = Qs + 64 * 68;     // [d][k]
    float* Vs = Ks + 64 * 68;     // [k][d]
    float* Ps = Vs + 64 * 68;     // [k][q]
    float* ml = Ps + 64 * 68;     // m[64], l[64]
    int qt = blockIdx.x, h = blockIdx.y;
    int tid = threadIdx.x;
    int tx = tid & 15, ty = tid >> 4;
    int q0 = qt * 64;
#pragma unroll
    for (int i = 0; i < 4; i++) {
        int idx = tid + i * 256;
        int r = idx >> 4, c4 = (idx & 15) * 4;
        float4 v = *(const float4*)(qkv + (size_t)(q0 + r) * 3 * D_ + h * HD_ + c4);
        Qs[(c4 + 0) * 68 + r] = v.x; Qs[(c4 + 1) * 68 + r] = v.y;
        Qs[(c4 + 2) * 68 + r] = v.z; Qs[(c4 + 3) * 68 + r] = v.w;
    }
    if (tid < 64) { ml[tid] = -1e30f; ml[64 + tid] = 0.f; }
    float o[4][4] = {};
    for (int kt = 0; kt <= qt; kt++) {
        __syncthreads();
#pragma unroll
        for (int i = 0; i < 4; i++) {
            int idx = tid + i * 256;
            int r = idx >> 4, c4 = (idx & 15) * 4;
            const float* src = qkv + (size_t)(kt * 64 + r) * 3 * D_ + h * HD_;
            float4 kv = *(const float4*)(src + D_ + c4);
            Ks[(c4 + 0) * 68 + r] = kv.x; Ks[(c4 + 1) * 68 + r] = kv.y;
            Ks[(c4 + 2) * 68 + r] = kv.z; Ks[(c4 + 3) * 68 + r] = kv.w;
            *(float4*)&Vs[r * 68 + c4] = *(const float4*)(src + 2 * D_ + c4);
        }
        __syncthreads();
        float acc[4][4] = {};
#pragma unroll 4
        for (int d = 0; d < 64; d++) {
            float4 av = *(const float4*)&Qs[d * 68 + ty * 4];
            float4 bv = *(const float4*)&Ks[d * 68 + tx * 4];
            float aa[4] = {av.x, av.y, av.z, av.w};
            float bb[4] = {bv.x, bv.y, bv.z, bv.w};
#pragma unroll
            for (int i = 0; i < 4; i++)
#pragma unroll
                for (int j = 0; j < 4; j++) acc[i][j] += aa[i] * bb[j];
        }
        bool diag = (kt == qt);
#pragma unroll
        for (int i = 0; i < 4; i++)
#pragma unroll
            for (int j = 0; j < 4; j++) {
                float s = acc[i][j] * 0.125f;
                if (diag && (tx * 4 + j) > (ty * 4 + i)) s = -1e30f;
                acc[i][j] = s;
            }
        float fac[4], p[4][4];
        float nm[4], rs[4];
#pragma unroll
        for (int i = 0; i < 4; i++) {
            float mx = fmaxf(fmaxf(acc[i][0], acc[i][1]), fmaxf(acc[i][2], acc[i][3]));
#pragma unroll
            for (int off = 8; off; off >>= 1) mx = fmaxf(mx, __shfl_xor_sync(0xffffffffu, mx, off, 16));
            float mo = ml[ty * 4 + i];
            float newm = fmaxf(mo, mx);
            float sum = 0.f;
#pragma unroll
            for (int j = 0; j < 4; j++) { float e = __expf(acc[i][j] - newm); p[i][j] = e; sum += e; }
#pragma unroll
            for (int off = 8; off; off >>= 1) sum += __shfl_xor_sync(0xffffffffu, sum, off, 16);
            fac[i] = __expf(mo - newm);
            nm[i] = newm; rs[i] = sum;
        }
        __syncwarp();
        if (tx == 0) {
#pragma unroll
            for (int i = 0; i < 4; i++) {
                int rr = ty * 4 + i;
                ml[rr] = nm[i];
                ml[64 + rr] = ml[64 + rr] * fac[i] + rs[i];
            }
        }
#pragma unroll
        for (int i = 0; i < 4; i++)
#pragma unroll
            for (int j = 0; j < 4; j++) {
                o[i][j] *= fac[i];
                Ps[(tx * 4 + j) * 68 + ty * 4 + i] = p[i][j];
            }
        __syncthreads();
#pragma unroll 4
        for (int k = 0; k < 64; k++) {
            float4 av = *(const float4*)&Ps[k * 68 + ty * 4];
            float4 bv = *(const float4*)&Vs[k * 68 + tx * 4];
            float aa[4] = {av.x, av.y, av.z, av.w};
            float bb[4] = {bv.x, bv.y, bv.z, bv.w};
#pragma unroll
            for (int i = 0; i < 4; i++)
#pragma unroll
                for (int j = 0; j < 4; j++) o[i][j] += aa[i] * bb[j];
        }
    }
    __syncthreads();
#pragma unroll
    for (int i = 0; i < 4; i++) {
        float linv = 1.0f / ml[64 + ty * 4 + i];
        size_t row = (size_t)(q0 + ty * 4 + i) * D_ + h * HD_ + tx * 4;
#pragma unroll
        for (int j = 0; j < 4; j++)
            f2hilo(o[i][j] * linv, d_ao_h + row + j, d_ao_l + row + j);
    }
}

// ---------------- router ----------------
__global__ void router_kernel(const float* __restrict__ xffn, const float* __restrict__ keys,
                              const int* __restrict__ idx, const float* __restrict__ vals,
                              const float* __restrict__ bias) {
    int t = blockIdx.x, lane = threadIdx.x;
    int e0 = idx[t * 2], e1 = idx[t * 2 + 1];
    const float* xr = xffn + (size_t)t * D_;
    float s0 = 0.f, s1 = 0.f;
    for (int d = lane; d < D_; d += 32) {
        float x = xr[d];
        s0 += x * keys[d * TE_ + e0];
        s1 += x * keys[d * TE_ + e1];
    }
#pragma unroll
    for (int o = 16; o; o >>= 1) {
        s0 += __shfl_xor_sync(0xffffffffu, s0, o);
        s1 += __shfl_xor_sync(0xffffffffu, s1, o);
    }
    if (lane == 0) {
        float v0 = vals[t * 2] + s0 + bias[e0];
        float v1 = vals[t * 2 + 1] + s1 + bias[e1];
        float mm = fmaxf(v0, v1);
        float a = expf(v0 - mm), b = expf(v1 - mm);
        float inv = 1.0f / (a + b);
        d_scores[t * 2] = a * inv;
        d_scores[t * 2 + 1] = b * inv;
    }
}

__global__ void zero_counts_kernel() {
    if (threadIdx.x < TE_) d_counts[threadIdx.x] = 0;
}
__global__ void scatter_kernel(const int* __restrict__ idx) {
    int slot = blockIdx.x * blockDim.x + threadIdx.x;
    if (slot < NSLOT) {
        int e = idx[slot];
        int p = atomicAdd(&d_counts[e], 1);
        d_list[e * NSLOT + p] = slot;
    }
}

// ---------------- swiglu (experts): h12 -> g hi/lo ----------------
__global__ void swiglu_expert_kernel() {
    int i = blockIdx.x * 256 + threadIdx.x;
    if (i < NSLOT * ED_) {
        int sl = i >> 9, j = i & 511;
        float a = d_h12[(size_t)sl * 1024 + j];
        float b = d_h12[(size_t)sl * 1024 + 512 + j];
        float g = (a / (1.f + __expf(-a))) * b;
        f2hilo(g, d_g_h + (size_t)sl * ED_ + j, d_g_l + (size_t)sl * ED_ + j);
    }
}

// ---------------- shared swiglu: up -> gs hi/lo ----------------
__global__ void swiglu_shared_kernel() {
    size_t i = (size_t)blockIdx.x * 256 + threadIdx.x;
    if (i < (size_t)T_ * DS_) {
        size_t t = i / DS_, j = i % DS_;
        float a = d_up[t * 2 * DS_ + j];
        float b = d_up[t * 2 * DS_ + DS_ + j];
        float g = (a / (1.f + __expf(-a))) * b;
        f2hilo(g, d_gs_h + i, d_gs_l + i);
    }
}

// ---------------- combine routed outputs ----------------
__global__ void combine_kernel(const float* __restrict__ coeff) {
    int t = blockIdx.x, tid = threadIdx.x;
    float s0 = d_scores[t * 2], s1 = d_scores[t * 2 + 1];
    const float* y0 = d_ys + (size_t)(t * 2) * D_;
    const float* y1 = d_ys + (size_t)(t * 2 + 1) * D_;
    float* yo = d_y + (size_t)t * D_;
    for (int dd = tid; dd < D_; dd += 256)
        yo[dd] = (s0 * y0[dd] + s1 * y1[dd]) * coeff[dd];
}

// ---------------- final combine ----------------
__global__ void final_kernel(const float* __restrict__ sharedw, float* __restrict__ out) {
    int t = blockIdx.x;
    const float* ysh = d_ysh + (size_t)t * D_;
    float ss = 0.f;
    for (int i = threadIdx.x; i < D_; i += blockDim.x) { float v = ysh[i]; ss += v * v; }
    __shared__ float sh[32];
    float tot = block_reduce_sum(ss, sh);
    float rinv = rsqrtf(tot / (float)D_ + EPS_);
    const float* yr = d_y + (size_t)t * D_;
    const float* xr = d_xffn_in + (size_t)t * D_;
    float* o = out + (size_t)t * D_;
    for (int i = threadIdx.x; i < D_; i += blockDim.x)
        o[i] = yr[i] + ysh[i] * rinv * sharedw[i] + xr[i];
}

// ---------------- host launch ----------------
static void* sym(const void* s) { void* p = nullptr; cudaGetSymbolAddress(&p, s); return p; }

extern "C" void kernel_launch(void* const* d_in, const int* in_sizes, int n_in,
                              void* d_out, int out_size) {
    const float* x_input      = (const float*)d_in[0];
    const int*   indices      = (const int*)  d_in[1];
    const float* values       = (const float*)d_in[2];
    const float* attn_w       = (const float*)d_in[3];
    const float* attn_o_w     = (const float*)d_in[4];
    const float* attn_norm_w  = (const float*)d_in[5];
    const float* ffn_norm_w   = (const float*)d_in[6];
    const float* ffn_experts  = (const float*)d_in[7];
    const float* main_keys    = (const float*)d_in[8];
    const float* main_bias    = (const float*)d_in[9];
    const float* output_coeff = (const float*)d_in[10];
    const float* ffn_up_w     = (const float*)d_in[11];
    const float* ffn_down_w   = (const float*)d_in[12];
    const float* shared_norm_w= (const float*)d_in[13];
    float* out = (float*)d_out;

    cudaFuncSetAttribute((const void*)gemm_mma<0,0>, cudaFuncAttributeMaxDynamicSharedMemorySize, GEMM_SMEM);
    cudaFuncSetAttribute((const void*)gemm_mma<0,1>, cudaFuncAttributeMaxDynamicSharedMemorySize, GEMM_SMEM);
    cudaFuncSetAttribute((const void*)gemm_mma<1,0>, cudaFuncAttributeMaxDynamicSharedMemorySize, GEMM_SMEM);
    cudaFuncSetAttribute((const void*)gemm_mma<2,0>, cudaFuncAttributeMaxDynamicSharedMemorySize, GEMM_SMEM);
    cudaFuncSetAttribute((const void*)flash_attn_kernel, cudaFuncAttributeMaxDynamicSharedMemorySize, AT_SMEM);

    __nv_bfloat16 *p_xn_h=(__nv_bfloat16*)sym(d_xn_h), *p_xn_l=(__nv_bfloat16*)sym(d_xn_l);
    __nv_bfloat16 *p_aw_h=(__nv_bfloat16*)sym(d_aw_h), *p_aw_l=(__nv_bfloat16*)sym(d_aw_l);
    __nv_bfloat16 *p_ow_h=(__nv_bfloat16*)sym(d_ow_h), *p_ow_l=(__nv_bfloat16*)sym(d_ow_l);
    __nv_bfloat16 *p_ao_h=(__nv_bfloat16*)sym(d_ao_h), *p_ao_l=(__nv_bfloat16*)sym(d_ao_l);
    __nv_bfloat16 *p_xf_h=(__nv_bfloat16*)sym(d_xffn_h), *p_xf_l=(__nv_bfloat16*)sym(d_xffn_l);
    __nv_bfloat16 *p_uw_h=(__nv_bfloat16*)sym(d_upw_h), *p_uw_l=(__nv_bfloat16*)sym(d_upw_l);
    __nv_bfloat16 *p_dw_h=(__nv_bfloat16*)sym(d_dnw_h), *p_dw_l=(__nv_bfloat16*)sym(d_dnw_l);
    __nv_bfloat16 *p_w12_h=(__nv_bfloat16*)sym(d_w12t_h), *p_w12_l=(__nv_bfloat16*)sym(d_w12t_l);
    __nv_bfloat16 *p_w3_h=(__nv_bfloat16*)sym(d_w3_h), *p_w3_l=(__nv_bfloat16*)sym(d_w3_l);
    __nv_bfloat16 *p_g_h=(__nv_bfloat16*)sym(d_g_h), *p_g_l=(__nv_bfloat16*)sym(d_g_l);
    __nv_bfloat16 *p_gs_h=(__nv_bfloat16*)sym(d_gs_h), *p_gs_l=(__nv_bfloat16*)sym(d_gs_l);
    float *p_qkv=(float*)sym(d_qkv), *p_xffn_in=(float*)sym(d_xffn_in), *p_xffn=(float*)sym(d_xffn);
    float *p_h12=(float*)sym(d_h12), *p_ys=(float*)sym(d_ys), *p_up=(float*)sym(d_up);
    float *p_ysh=(float*)sym(d_ysh);

    // per-launch weight conversions (vectorized)
    conv_hilo_kernel<<<2048, 256>>>((const float4*)attn_w, (uint2*)p_aw_h, (uint2*)p_aw_l,
                                    (size_t)3 * D_ * D_ / 4);
    conv_hilo_kernel<<<1024, 256>>>((const float4*)attn_o_w, (uint2*)p_ow_h, (uint2*)p_ow_l,
                                    (size_t)D_ * D_ / 4);
    conv_hilo_kernel<<<2048, 256>>>((const float4*)ffn_up_w, (uint2*)p_uw_h, (uint2*)p_uw_l,
                                    (size_t)2 * DS_ * D_ / 4);
    conv_hilo_kernel<<<2048, 256>>>((const float4*)ffn_down_w, (uint2*)p_dw_h, (uint2*)p_dw_l,
                                    (size_t)D_ * DS_ / 4);
    conv_hilo_kernel<<<4096, 256>>>((const float4*)(ffn_experts + (size_t)2 * TE_ * D_ * ED_),
                                    (uint2*)p_w3_h, (uint2*)p_w3_l, (size_t)TE_ * D_ * ED_ / 4);
    transpose_w12_kernel<<<dim3(32, 16, 16), dim3(32, 8)>>>(ffn_experts);

    // attention block
    rmsnorm_kernel<<<T_, 256>>>(x_input, attn_norm_w, nullptr, p_xn_h, p_xn_l);
    gemm_mma<0,0><<<dim3(24, 16), 256, GEMM_SMEM>>>(p_xn_h, p_xn_l, p_aw_h, p_aw_l,
                                                    p_qkv, nullptr, 3 * D_, D_, 0);
    rope_kernel<<<dim3(S_, H_), 32>>>(p_qkv);
    flash_attn_kernel<<<dim3(S_ / 64, H_), 256, AT_SMEM>>>(p_qkv);
    gemm_mma<0,1><<<dim3(8, 16), 256, GEMM_SMEM>>>(p_ao_h, p_ao_l, p_ow_h, p_ow_l,
                                                   p_xffn_in, x_input, D_, D_, 0);

    // ffn norm + router
    rmsnorm_kernel<<<T_, 256>>>(p_xffn_in, ffn_norm_w, p_xffn, p_xf_h, p_xf_l);
    router_kernel<<<T_, 32>>>(p_xffn, main_keys, indices, values, main_bias);
    zero_counts_kernel<<<1, 32>>>();
    scatter_kernel<<<(NSLOT + 255) / 256, 256>>>(indices);

    // routed experts
    gemm_mma<1,0><<<dim3(8, NSLOT / 128, TE_), 256, GEMM_SMEM>>>(
        p_xf_h, p_xf_l, p_w12_h, p_w12_l, p_h12, nullptr, 1024, 1024, (long long)1024 * 1024);
    swiglu_expert_kernel<<<(NSLOT * ED_ + 255) / 256, 256>>>();
    gemm_mma<2,0><<<dim3(8, NSLOT / 128, TE_), 256, GEMM_SMEM>>>(
        p_g_h, p_g_l, p_w3_h, p_w3_l, p_ys, nullptr, 1024, 512, (long long)D_ * ED_);
    combine_kernel<<<T_, 256>>>(output_coeff);

    // shared expert
    gemm_mma<0,0><<<dim3(32, 16), 256, GEMM_SMEM>>>(p_xf_h, p_xf_l, p_uw_h, p_uw_l,
                                                    p_up, nullptr, 2 * DS_, D_, 0);
    swiglu_shared_kernel<<<((size_t)T_ * DS_ + 255) / 256, 256>>>();
    gemm_mma<0,0><<<dim3(8, 16), 256, GEMM_SMEM>>>(p_gs_h, p_gs_l, p_dw_h, p_dw_l,
                                                   p_ysh, nullptr, D_, DS_, 0);

    // final combine
    final_kernel<<<T_, 256>>>(shared_norm_w, out);
}

// round 7
// speedup vs baseline: 9.5123x; 1.2036x over previous
#include <cuda_runtime.h>
#include <cuda_bf16.h>
#include <math.h>
#include <stdint.h>

// ---------------- problem constants ----------------
#define S_   2048
#define D_   1024
#define H_   16
#define HD_  64
#define TE_  16
#define TOPK 2
#define ED_  512
#define DS_  2048
#define T_   2048
#define NSLOT (T_*TOPK)
#define EPS_ 1e-5f

// ---------------- scratch (device bss, no allocation) ----------------
__device__ __align__(256) __nv_bfloat16 d_xn_h[(size_t)T_*D_],     d_xn_l[(size_t)T_*D_];
__device__ __align__(256) __nv_bfloat16 d_aw_h[(size_t)3*D_*D_],   d_aw_l[(size_t)3*D_*D_];
__device__ __align__(256) __nv_bfloat16 d_ow_h[(size_t)D_*D_],     d_ow_l[(size_t)D_*D_];
__device__ __align__(256) __nv_bfloat16 d_ao_h[(size_t)T_*D_],     d_ao_l[(size_t)T_*D_];
__device__ __align__(256) __nv_bfloat16 d_xffn_h[(size_t)T_*D_],   d_xffn_l[(size_t)T_*D_];
__device__ __align__(256) __nv_bfloat16 d_upw_h[(size_t)2*DS_*D_], d_upw_l[(size_t)2*DS_*D_];
__device__ __align__(256) __nv_bfloat16 d_dnw_h[(size_t)D_*DS_],   d_dnw_l[(size_t)D_*DS_];
__device__ __align__(256) __nv_bfloat16 d_w12t_h[(size_t)TE_*2*ED_*D_], d_w12t_l[(size_t)TE_*2*ED_*D_];
__device__ __align__(256) __nv_bfloat16 d_w3_h[(size_t)TE_*D_*ED_],     d_w3_l[(size_t)TE_*D_*ED_];
__device__ __align__(256) __nv_bfloat16 d_g_h[(size_t)NSLOT*ED_],  d_g_l[(size_t)NSLOT*ED_];
__device__ __align__(256) __nv_bfloat16 d_gs_h[(size_t)T_*DS_],    d_gs_l[(size_t)T_*DS_];
__device__ __align__(256) float d_qkv[(size_t)T_*3*D_];
__device__ __align__(256) float d_xffn_in[(size_t)T_*D_];
__device__ __align__(256) float d_xffn[(size_t)T_*D_];
__device__ __align__(256) float d_h12[(size_t)NSLOT*2*ED_];
__device__ __align__(256) float d_ys[(size_t)NSLOT*D_];
__device__ __align__(256) float d_y[(size_t)T_*D_];
__device__ __align__(256) float d_up[(size_t)T_*2*DS_];
__device__ __align__(256) float d_ysh[(size_t)T_*D_];
__device__ float d_scores[NSLOT];
__device__ int   d_counts[TE_];
__device__ int   d_list[TE_*NSLOT];

// ---------------- helpers ----------------
__device__ __forceinline__ void f2hilo(float x, __nv_bfloat16* h, __nv_bfloat16* l) {
    __nv_bfloat16 hh = __float2bfloat16(x);
    *h = hh;
    *l = __float2bfloat16(x - __bfloat162float(hh));
}
__device__ __forceinline__ uint32_t bpack(__nv_bfloat16 a, __nv_bfloat16 b) {
    uint16_t ua = *(uint16_t*)&a, ub = *(uint16_t*)&b;
    return ((uint32_t)ub << 16) | ua;
}
__device__ __forceinline__ uint32_t packh(float x, float y, uint32_t* lo) {
    __nv_bfloat16 hx = __float2bfloat16(x), hy = __float2bfloat16(y);
    __nv_bfloat16 lx = __float2bfloat16(x - __bfloat162float(hx));
    __nv_bfloat16 ly = __float2bfloat16(y - __bfloat162float(hy));
    *lo = bpack(lx, ly);
    return bpack(hx, hy);
}
__device__ __forceinline__ float block_reduce_sum(float v, float* sh) {
    __syncthreads();
    int lane = threadIdx.x & 31, wid = threadIdx.x >> 5;
#pragma unroll
    for (int o = 16; o; o >>= 1) v += __shfl_xor_sync(0xffffffffu, v, o);
    if (lane == 0) sh[wid] = v;
    __syncthreads();
    int nw = blockDim.x >> 5;
    v = (threadIdx.x < nw) ? sh[threadIdx.x] : 0.f;
    if (wid == 0) {
#pragma unroll
        for (int o = 16; o; o >>= 1) v += __shfl_xor_sync(0xffffffffu, v, o);
        if (lane == 0) sh[0] = v;
    }
    __syncthreads();
    return sh[0];
}
__device__ __forceinline__ void mma16816(float* d, const uint32_t* a, const uint32_t* b) {
    asm volatile(
        "mma.sync.aligned.m16n8k16.row.col.f32.bf16.bf16.f32 "
        "{%0,%1,%2,%3}, {%4,%5,%6,%7}, {%8,%9}, {%0,%1,%2,%3};"
        : "+f"(d[0]), "+f"(d[1]), "+f"(d[2]), "+f"(d[3])
        : "r"(a[0]), "r"(a[1]), "r"(a[2]), "r"(a[3]), "r"(b[0]), "r"(b[1]));
}
__device__ __forceinline__ void ldsm_x4(uint32_t* r, uint32_t addr) {
    asm volatile("ldmatrix.sync.aligned.m8n8.x4.shared.b16 {%0,%1,%2,%3}, [%4];"
        : "=r"(r[0]), "=r"(r[1]), "=r"(r[2]), "=r"(r[3]) : "r"(addr));
}
__device__ __forceinline__ void ldsm_x4t(uint32_t* r, uint32_t addr) {
    asm volatile("ldmatrix.sync.aligned.m8n8.x4.trans.shared.b16 {%0,%1,%2,%3}, [%4];"
        : "=r"(r[0]), "=r"(r[1]), "=r"(r[2]), "=r"(r[3]) : "r"(addr));
}
__device__ __forceinline__ void cpa16(uint32_t dst, const void* src, int sb) {
    asm volatile("cp.async.cg.shared.global [%0], [%1], 16, %2;"
                 :: "r"(dst), "l"(src), "r"(sb));
}
__device__ __forceinline__ void cpa_commit() { asm volatile("cp.async.commit_group;"); }
template<int N> __device__ __forceinline__ void cpa_wait() {
    asm volatile("cp.async.wait_group %0;" :: "n"(N));
}

// ---------------- conversion kernels (vectorized) ----------------
__global__ void conv_hilo_kernel(const float4* __restrict__ src, uint2* __restrict__ hi,
                                 uint2* __restrict__ lo, size_t n4) {
    for (size_t i = (size_t)blockIdx.x * blockDim.x + threadIdx.x; i < n4;
         i += (size_t)gridDim.x * blockDim.x) {
        float4 v = src[i];
        __nv_bfloat16 h0, l0, h1, l1, h2, l2, h3, l3;
        f2hilo(v.x, &h0, &l0); f2hilo(v.y, &h1, &l1);
        f2hilo(v.z, &h2, &l2); f2hilo(v.w, &h3, &l3);
        uint2 ho, lw;
        ho.x = bpack(h0, h1); ho.y = bpack(h2, h3);
        lw.x = bpack(l0, l1); lw.y = bpack(l2, l3);
        hi[i] = ho; lo[i] = lw;
    }
}

// experts W1/W2 [m][e][k=D][n=ED] -> w12t [e][n'(=m*512+n)][k] hi/lo (packed stores)
__global__ void transpose_w12_kernel(const float* __restrict__ experts) {
    __shared__ float tile[64][33];
    int e = blockIdx.z;
    int n0 = blockIdx.x * 32, k0 = blockIdx.y * 64;
    int m = n0 >> 9, c0 = n0 & 511;
    for (int kk = threadIdx.y; kk < 64; kk += 8)
        tile[kk][threadIdx.x] =
            experts[((size_t)(m * TE_ + e) * D_ + k0 + kk) * ED_ + c0 + threadIdx.x];
    __syncthreads();
    for (int ny = threadIdx.y; ny < 32; ny += 8) {
        float va = tile[threadIdx.x * 2][ny];
        float vb = tile[threadIdx.x * 2 + 1][ny];
        __nv_bfloat16 ha, la, hb, lb;
        f2hilo(va, &ha, &la); f2hilo(vb, &hb, &lb);
        size_t o = ((size_t)e << 20) + (size_t)(n0 + ny) * 1024 + k0 + threadIdx.x * 2;
        *(uint32_t*)(d_w12t_h + o) = bpack(ha, hb);
        *(uint32_t*)(d_w12t_l + o) = bpack(la, lb);
    }
}

// ---------------- rmsnorm (fp32 optional + hi/lo) ----------------
__global__ void rmsnorm_kernel(const float* __restrict__ x, const float* __restrict__ w,
                               float* __restrict__ outf, __nv_bfloat16* __restrict__ oh,
                               __nv_bfloat16* __restrict__ ol) {
    int row = blockIdx.x;
    const float* xr = x + (size_t)row * D_;
    float ss = 0.f;
    for (int i = threadIdx.x; i < D_; i += blockDim.x) { float v = xr[i]; ss += v * v; }
    __shared__ float sh[32];
    float tot = block_reduce_sum(ss, sh);
    float rinv = rsqrtf(tot / (float)D_ + EPS_);
    for (int i = threadIdx.x; i < D_; i += blockDim.x) {
        float v = xr[i] * rinv * w[i];
        size_t o = (size_t)row * D_ + i;
        if (outf) outf[o] = v;
        f2hilo(v, oh + o, ol + o);
    }
}

// ---------------- warp-MMA split-bf16 GEMM: C[M,N] = A @ B^T ----------------
// CTA tile 128x128, BK=32, 8 warps (2x4), warp tile 64x32, cp.async double-buffer,
// ldmatrix fragment loads.
#define SD    40                   /* smem row stride in bf16 (conflict-free) */
#define STG_E (4*128*SD)           /* bf16 elems per stage (Ah,Al,Bh,Bl) */
#define GEMM_SMEM (2*STG_E*2)      /* bytes */

template<int GATHER, int RES>
__global__ void __launch_bounds__(256, 1) gemm_mma(
    const __nv_bfloat16* __restrict__ Ah, const __nv_bfloat16* __restrict__ Al,
    const __nv_bfloat16* __restrict__ Bh, const __nv_bfloat16* __restrict__ Bl,
    float* __restrict__ C, const float* __restrict__ Res,
    int N, int K, long long bstride)
{
    __shared__ int s_row[128];
    __shared__ int s_out[128];
    int tid = threadIdx.x, wid = tid >> 5, lid = tid & 31;
    if (GATHER) {
        int e = blockIdx.z, cnt = d_counts[e];
        if ((int)blockIdx.y * 128 >= cnt) return;
        if (tid < 128) {
            int r = blockIdx.y * 128 + tid;
            int sl = (r < cnt) ? d_list[e * NSLOT + r] : -1;
            s_out[tid] = sl;
            s_row[tid] = (sl < 0) ? -1 : (GATHER == 1 ? (sl >> 1) : sl);
        }
        Bh += (size_t)blockIdx.z * bstride;
        Bl += (size_t)blockIdx.z * bstride;
    } else if (tid < 128) {
        int r = blockIdx.y * 128 + tid;
        s_row[tid] = r; s_out[tid] = r;
    }
    extern __shared__ __nv_bfloat16 sm[];
    uint32_t smb = (uint32_t)__cvta_generic_to_shared(sm);
    int n0 = blockIdx.x * 128;
    int NC = K >> 5;
    __syncthreads();

    int lrow = tid >> 2, lq = tid & 3;
    int arow0 = s_row[lrow];
    const __nv_bfloat16* asrc_h = Ah + (size_t)(arow0 < 0 ? 0 : arow0) * K + lq * 8;
    const __nv_bfloat16* asrc_l = Al + (size_t)(arow0 < 0 ? 0 : arow0) * K + lq * 8;
    const __nv_bfloat16* bsrc_h = Bh + (size_t)(n0 + lrow) * K + lq * 8;
    const __nv_bfloat16* bsrc_l = Bl + (size_t)(n0 + lrow) * K + lq * 8;
    int asb = (arow0 < 0) ? 0 : 16;
    int arow1 = s_row[lrow + 64];
    const __nv_bfloat16* asrc2_h = Ah + (size_t)(arow1 < 0 ? 0 : arow1) * K + lq * 8;
    const __nv_bfloat16* asrc2_l = Al + (size_t)(arow1 < 0 ? 0 : arow1) * K + lq * 8;
    const __nv_bfloat16* bsrc2_h = Bh + (size_t)(n0 + lrow + 64) * K + lq * 8;
    const __nv_bfloat16* bsrc2_l = Bl + (size_t)(n0 + lrow + 64) * K + lq * 8;
    int asb2 = (arow1 < 0) ? 0 : 16;
    uint32_t o1 = (uint32_t)((lrow * SD + lq * 8) << 1);
    uint32_t o2 = (uint32_t)(((lrow + 64) * SD + lq * 8) << 1);
    const uint32_t OFF_AL = (uint32_t)((128 * SD) << 1);
    const uint32_t OFF_BH = (uint32_t)((2 * 128 * SD) << 1);
    const uint32_t OFF_BL = (uint32_t)((3 * 128 * SD) << 1);

    auto issue = [&](int c, int buf) {
        uint32_t st = smb + (uint32_t)(buf * STG_E * 2);
        int kc = c << 5;
        cpa16(st + o1, asrc_h + kc, asb);
        cpa16(st + OFF_AL + o1, asrc_l + kc, asb);
        cpa16(st + OFF_BH + o1, bsrc_h + kc, 16);
        cpa16(st + OFF_BL + o1, bsrc_l + kc, 16);
        cpa16(st + o2, asrc2_h + kc, asb2);
        cpa16(st + OFF_AL + o2, asrc2_l + kc, asb2);
        cpa16(st + OFF_BH + o2, bsrc2_h + kc, 16);
        cpa16(st + OFF_BL + o2, bsrc2_l + kc, 16);
        cpa_commit();
    };

    int wm = wid & 1, wn = wid >> 1;
    int r = lid >> 2, c2 = (lid & 3) << 1;
    uint32_t a_lane = (uint32_t)(((lid & 15) * SD + ((lid >> 4) << 3)) << 1);
    uint32_t b_lane = (uint32_t)((((((lid >> 4) << 3) + (lid & 7)) * SD) + (((lid >> 3) & 1) << 3)) << 1);
    float acc[4][4][4] = {};

    issue(0, 0);
    if (NC > 1) issue(1, 1);
    for (int c = 0; c < NC; c++) {
        int buf = c & 1;
        if (c + 1 < NC) cpa_wait<1>(); else cpa_wait<0>();
        __syncthreads();
        uint32_t base = smb + (uint32_t)(buf * STG_E * 2);
#pragma unroll
        for (int ks = 0; ks < 2; ks++) {
            uint32_t kb = (uint32_t)(ks << 5);
            uint32_t ah[4][4], al[4][4];
#pragma unroll
            for (int mt = 0; mt < 4; mt++) {
                uint32_t ab = base + (uint32_t)(((wm * 64 + mt * 16) * SD) << 1) + kb + a_lane;
                ldsm_x4(ah[mt], ab);
                ldsm_x4(al[mt], ab + OFF_AL);
            }
            uint32_t bh[4][2], bl[4][2];
#pragma unroll
            for (int p = 0; p < 2; p++) {
                uint32_t bb = base + OFF_BH
                            + (uint32_t)(((wn * 32 + p * 16) * SD) << 1) + kb + b_lane;
                uint32_t t[4];
                ldsm_x4(t, bb);
                bh[2*p][0] = t[0]; bh[2*p][1] = t[1];
                bh[2*p+1][0] = t[2]; bh[2*p+1][1] = t[3];
                ldsm_x4(t, bb + OFF_AL);
                bl[2*p][0] = t[0]; bl[2*p][1] = t[1];
                bl[2*p+1][0] = t[2]; bl[2*p+1][1] = t[3];
            }
#pragma unroll
            for (int nt = 0; nt < 4; nt++)
#pragma unroll
                for (int mt = 0; mt < 4; mt++) {
                    mma16816(acc[mt][nt], ah[mt], bh[nt]);
                    mma16816(acc[mt][nt], al[mt], bh[nt]);
                    mma16816(acc[mt][nt], ah[mt], bl[nt]);
                }
        }
        __syncthreads();
        if (c + 2 < NC) issue(c + 2, buf);
    }

    // epilogue (float2 stores)
#pragma unroll
    for (int mt = 0; mt < 4; mt++) {
        int rloc0 = wm * 64 + mt * 16 + r;
#pragma unroll
        for (int half = 0; half < 2; half++) {
            int rloc = rloc0 + half * 8;
            int outr = s_out[rloc];
            if (GATHER && outr < 0) continue;
            float* crow = C + (size_t)outr * N + n0;
#pragma unroll
            for (int nt = 0; nt < 4; nt++) {
                int col = wn * 32 + nt * 8 + c2;
                float v0 = acc[mt][nt][half * 2 + 0];
                float v1 = acc[mt][nt][half * 2 + 1];
                if (RES) {
                    const float* rrow = Res + (size_t)outr * N + n0;
                    v0 += rrow[col]; v1 += rrow[col + 1];
                }
                float2 fv = make_float2(v0, v1);
                *(float2*)(crow + col) = fv;
            }
        }
    }
}

// ---------------- RoPE (in place on q,k parts of qkv) ----------------
__global__ void rope_kernel(float* __restrict__ qkv) {
    int s = blockIdx.x, h = blockIdx.y, i = threadIdx.x;  // i in [0,32)
    float inv = powf(10000.0f, -(float)i / 32.0f);
    float fr = (float)s * inv;
    float c = cosf(fr), sn = sinf(fr);
    float* q = qkv + (size_t)s * 3 * D_ + h * HD_;
    float* k = q + D_;
    float q1 = q[i], q2 = q[i + 32];
    q[i] = q1 * c + q2 * sn;  q[i + 32] = -q1 * sn + q2 * c;
    float k1 = k[i], k2 = k[i + 32];
    k[i] = k1 * c + k2 * sn;  k[i + 32] = -k1 * sn + k2 * c;
}

// ---------------- tensor-core flash attention ----------------
// 64 q-rows per CTA (4 warps x 16 rows), 64-key tiles, split-bf16 QK^T and PV.
#define ASD 72
#define AT2_SMEM (6*64*ASD*2)
__global__ void __launch_bounds__(128) flash_attn_tc(const float* __restrict__ qkv) {
    extern __shared__ __nv_bfloat16 asm_[];
    __nv_bfloat16* sQh = asm_;
    __nv_bfloat16* sQl = sQh + 64 * ASD;
    __nv_bfloat16* sKh = sQl + 64 * ASD;
    __nv_bfloat16* sKl = sKh + 64 * ASD;
    __nv_bfloat16* sVh = sKl + 64 * ASD;
    __nv_bfloat16* sVl = sVh + 64 * ASD;
    uint32_t bQh = (uint32_t)__cvta_generic_to_shared(sQh);
    uint32_t bQl = (uint32_t)__cvta_generic_to_shared(sQl);
    uint32_t bKh = (uint32_t)__cvta_generic_to_shared(sKh);
    uint32_t bKl = (uint32_t)__cvta_generic_to_shared(sKl);
    uint32_t bVh = (uint32_t)__cvta_generic_to_shared(sVh);
    uint32_t bVl = (uint32_t)__cvta_generic_to_shared(sVl);
    int qt = blockIdx.x, h = blockIdx.y;
    int tid = threadIdx.x, wid = tid >> 5, lid = tid & 31;
    int q0 = qt * 64;

    // load Q tile (rope already applied to qkv)
    for (int i = tid; i < 1024; i += 128) {
        int r = i >> 4, c4 = (i & 15) << 2;
        float4 v = *(const float4*)(qkv + (size_t)(q0 + r) * 3 * D_ + h * HD_ + c4);
        f2hilo(v.x, sQh + r * ASD + c4 + 0, sQl + r * ASD + c4 + 0);
        f2hilo(v.y, sQh + r * ASD + c4 + 1, sQl + r * ASD + c4 + 1);
        f2hilo(v.z, sQh + r * ASD + c4 + 2, sQl + r * ASD + c4 + 2);
        f2hilo(v.w, sQh + r * ASD + c4 + 3, sQl + r * ASD + c4 + 3);
    }

    uint32_t a_lane = (uint32_t)(((lid & 15) * ASD + ((lid >> 4) << 3)) << 1);
    uint32_t b_lane = (uint32_t)((((((lid >> 4) << 3) + (lid & 7)) * ASD) + (((lid >> 3) & 1) << 3)) << 1);
    uint32_t v_lane = (uint32_t)((((lid & 7) + (((lid >> 3) & 1) << 3)) * ASD + ((lid >> 4) << 3)) << 1);
    int ra = lid >> 2, c2 = (lid & 3) << 1;
    int rowa = wid * 16 + ra;           // local q row (also +8)
    int ga = q0 + rowa, gb = ga + 8;    // global q rows

    float m0 = -1e30f, m1 = -1e30f, l0 = 0.f, l1 = 0.f;
    float O[8][4] = {};

    for (int kt = 0; kt <= qt; kt++) {
        __syncthreads();
        for (int i = tid; i < 1024; i += 128) {
            int r = i >> 4, c4 = (i & 15) << 2;
            const float* src = qkv + (size_t)(kt * 64 + r) * 3 * D_ + h * HD_;
            float4 kv = *(const float4*)(src + D_ + c4);
            float4 vv = *(const float4*)(src + 2 * D_ + c4);
            f2hilo(kv.x, sKh + r * ASD + c4 + 0, sKl + r * ASD + c4 + 0);
            f2hilo(kv.y, sKh + r * ASD + c4 + 1, sKl + r * ASD + c4 + 1);
            f2hilo(kv.z, sKh + r * ASD + c4 + 2, sKl + r * ASD + c4 + 2);
            f2hilo(kv.w, sKh + r * ASD + c4 + 3, sKl + r * ASD + c4 + 3);
            f2hilo(vv.x, sVh + r * ASD + c4 + 0, sVl + r * ASD + c4 + 0);
            f2hilo(vv.y, sVh + r * ASD + c4 + 1, sVl + r * ASD + c4 + 1);
            f2hilo(vv.z, sVh + r * ASD + c4 + 2, sVl + r * ASD + c4 + 2);
            f2hilo(vv.w, sVh + r * ASD + c4 + 3, sVl + r * ASD + c4 + 3);
        }
        __syncthreads();

        // S = Q K^T (split-bf16, 3 MMAs)
        float S[8][4] = {};
#pragma unroll
        for (int ks = 0; ks < 4; ks++) {
            uint32_t kb = (uint32_t)(ks << 5);
            uint32_t ah[4], al[4];
            uint32_t ab = (uint32_t)(((wid * 16) * ASD) << 1) + kb + a_lane;
            ldsm_x4(ah, bQh + ab);
            ldsm_x4(al, bQl + ab);
#pragma unroll
            for (int p = 0; p < 4; p++) {
                uint32_t bb = (uint32_t)(((p * 16) * ASD) << 1) + kb + b_lane;
                uint32_t th[4], tl[4];
                ldsm_x4(th, bKh + bb);
                ldsm_x4(tl, bKl + bb);
                uint32_t bh0[2] = {th[0], th[1]}, bh1[2] = {th[2], th[3]};
                uint32_t bl0[2] = {tl[0], tl[1]}, bl1[2] = {tl[2], tl[3]};
                mma16816(S[2*p],   ah, bh0); mma16816(S[2*p],   al, bh0); mma16816(S[2*p],   ah, bl0);
                mma16816(S[2*p+1], ah, bh1); mma16816(S[2*p+1], al, bh1); mma16816(S[2*p+1], ah, bl1);
            }
        }
        // scale + causal mask
        bool diag = (kt == qt);
#pragma unroll
        for (int t = 0; t < 8; t++) {
            int col = kt * 64 + t * 8 + c2;
            S[t][0] *= 0.125f; S[t][1] *= 0.125f; S[t][2] *= 0.125f; S[t][3] *= 0.125f;
            if (diag) {
                if (col     > ga) S[t][0] = -1e30f;
                if (col + 1 > ga) S[t][1] = -1e30f;
                if (col     > gb) S[t][2] = -1e30f;
                if (col + 1 > gb) S[t][3] = -1e30f;
            }
        }
        // online softmax (rows ga, gb per thread; reduce over quad lanes)
        float mxa = -1e30f, mxb = -1e30f;
#pragma unroll
        for (int t = 0; t < 8; t++) {
            mxa = fmaxf(mxa, fmaxf(S[t][0], S[t][1]));
            mxb = fmaxf(mxb, fmaxf(S[t][2], S[t][3]));
        }
        mxa = fmaxf(mxa, __shfl_xor_sync(0xffffffffu, mxa, 1));
        mxa = fmaxf(mxa, __shfl_xor_sync(0xffffffffu, mxa, 2));
        mxb = fmaxf(mxb, __shfl_xor_sync(0xffffffffu, mxb, 1));
        mxb = fmaxf(mxb, __shfl_xor_sync(0xffffffffu, mxb, 2));
        float nma = fmaxf(m0, mxa), nmb = fmaxf(m1, mxb);
        float faca = __expf(m0 - nma), facb = __expf(m1 - nmb);
        m0 = nma; m1 = nmb;
        float suma = 0.f, sumb = 0.f;
#pragma unroll
        for (int t = 0; t < 8; t++) {
            S[t][0] = __expf(S[t][0] - nma); suma += S[t][0];
            S[t][1] = __expf(S[t][1] - nma); suma += S[t][1];
            S[t][2] = __expf(S[t][2] - nmb); sumb += S[t][2];
            S[t][3] = __expf(S[t][3] - nmb); sumb += S[t][3];
        }
        suma += __shfl_xor_sync(0xffffffffu, suma, 1);
        suma += __shfl_xor_sync(0xffffffffu, suma, 2);
        sumb += __shfl_xor_sync(0xffffffffu, sumb, 1);
        sumb += __shfl_xor_sync(0xffffffffu, sumb, 2);
        l0 = l0 * faca + suma; l1 = l1 * facb + sumb;
#pragma unroll
        for (int t = 0; t < 8; t++) {
            O[t][0] *= faca; O[t][1] *= faca; O[t][2] *= facb; O[t][3] *= facb;
        }
        // O += P V (P split hi/lo, V split hi/lo, 3 MMAs)
#pragma unroll
        for (int ks = 0; ks < 4; ks++) {
            uint32_t ph[4], pl[4];
            ph[0] = packh(S[2*ks][0],   S[2*ks][1],   &pl[0]);
            ph[1] = packh(S[2*ks][2],   S[2*ks][3],   &pl[1]);
            ph[2] = packh(S[2*ks+1][0], S[2*ks+1][1], &pl[2]);
            ph[3] = packh(S[2*ks+1][2], S[2*ks+1][3], &pl[3]);
#pragma unroll
            for (int p = 0; p < 4; p++) {
                uint32_t vb = (uint32_t)(((16 * ks) * ASD + 16 * p) << 1) + v_lane;
                uint32_t th[4], tl[4];
                ldsm_x4t(th, bVh + vb);
                ldsm_x4t(tl, bVl + vb);
                uint32_t bh0[2] = {th[0], th[1]}, bh1[2] = {th[2], th[3]};
                uint32_t bl0[2] = {tl[0], tl[1]}, bl1[2] = {tl[2], tl[3]};
                mma16816(O[2*p],   ph, bh0); mma16816(O[2*p],   pl, bh0); mma16816(O[2*p],   ph, bl0);
                mma16816(O[2*p+1], ph, bh1); mma16816(O[2*p+1], pl, bh1); mma16816(O[2*p+1], ph, bl1);
            }
        }
    }
    // epilogue: normalize + hi/lo store
    float il0 = 1.0f / l0, il1 = 1.0f / l1;
#pragma unroll
    for (int t = 0; t < 8; t++) {
        int col = h * HD_ + t * 8 + c2;
        size_t r0 = (size_t)ga * D_ + col;
        size_t r1 = (size_t)gb * D_ + col;
        f2hilo(O[t][0] * il0, d_ao_h + r0,     d_ao_l + r0);
        f2hilo(O[t][1] * il0, d_ao_h + r0 + 1, d_ao_l + r0 + 1);
        f2hilo(O[t][2] * il1, d_ao_h + r1,     d_ao_l + r1);
        f2hilo(O[t][3] * il1, d_ao_h + r1 + 1, d_ao_l + r1 + 1);
    }
}

// ---------------- router ----------------
__global__ void router_kernel(const float* __restrict__ xffn, const float* __restrict__ keys,
                              const int* __restrict__ idx, const float* __restrict__ vals,
                              const float* __restrict__ bias) {
    int t = blockIdx.x, lane = threadIdx.x;
    int e0 = idx[t * 2], e1 = idx[t * 2 + 1];
    const float* xr = xffn + (size_t)t * D_;
    float s0 = 0.f, s1 = 0.f;
    for (int d = lane; d < D_; d += 32) {
        float x = xr[d];
        s0 += x * keys[d * TE_ + e0];
        s1 += x * keys[d * TE_ + e1];
    }
#pragma unroll
    for (int o = 16; o; o >>= 1) {
        s0 += __shfl_xor_sync(0xffffffffu, s0, o);
        s1 += __shfl_xor_sync(0xffffffffu, s1, o);
    }
    if (lane == 0) {
        float v0 = vals[t * 2] + s0 + bias[e0];
        float v1 = vals[t * 2 + 1] + s1 + bias[e1];
        float mm = fmaxf(v0, v1);
        float a = expf(v0 - mm), b = expf(v1 - mm);
        float inv = 1.0f / (a + b);
        d_scores[t * 2] = a * inv;
        d_scores[t * 2 + 1] = b * inv;
    }
}

__global__ void zero_counts_kernel() {
    if (threadIdx.x < TE_) d_counts[threadIdx.x] = 0;
}
__global__ void scatter_kernel(const int* __restrict__ idx) {
    int slot = blockIdx.x * blockDim.x + threadIdx.x;
    if (slot < NSLOT) {
        int e = idx[slot];
        int p = atomicAdd(&d_counts[e], 1);
        d_list[e * NSLOT + p] = slot;
    }
}

// ---------------- swiglu (experts): h12 -> g hi/lo ----------------
__global__ void swiglu_expert_kernel() {
    int i = blockIdx.x * 256 + threadIdx.x;
    if (i < NSLOT * ED_) {
        int sl = i >> 9, j = i & 511;
        float a = d_h12[(size_t)sl * 1024 + j];
        float b = d_h12[(size_t)sl * 1024 + 512 + j];
        float g = (a / (1.f + __expf(-a))) * b;
        f2hilo(g, d_g_h + (size_t)sl * ED_ + j, d_g_l + (size_t)sl * ED_ + j);
    }
}

// ---------------- shared swiglu: up -> gs hi/lo ----------------
__global__ void swiglu_shared_kernel() {
    size_t i = (size_t)blockIdx.x * 256 + threadIdx.x;
    if (i < (size_t)T_ * DS_) {
        size_t t = i / DS_, j = i % DS_;
        float a = d_up[t * 2 * DS_ + j];
        float b = d_up[t * 2 * DS_ + DS_ + j];
        float g = (a / (1.f + __expf(-a))) * b;
        f2hilo(g, d_gs_h + i, d_gs_l + i);
    }
}

// ---------------- combine routed outputs ----------------
__global__ void combine_kernel(const float* __restrict__ coeff) {
    int t = blockIdx.x, tid = threadIdx.x;
    float s0 = d_scores[t * 2], s1 = d_scores[t * 2 + 1];
    const float* y0 = d_ys + (size_t)(t * 2) * D_;
    const float* y1 = d_ys + (size_t)(t * 2 + 1) * D_;
    float* yo = d_y + (size_t)t * D_;
    for (int dd = tid; dd < D_; dd += 256)
        yo[dd] = (s0 * y0[dd] + s1 * y1[dd]) * coeff[dd];
}

// ---------------- final combine ----------------
__global__ void final_kernel(const float* __restrict__ sharedw, float* __restrict__ out) {
    int t = blockIdx.x;
    const float* ysh = d_ysh + (size_t)t * D_;
    float ss = 0.f;
    for (int i = threadIdx.x; i < D_; i += blockDim.x) { float v = ysh[i]; ss += v * v; }
    __shared__ float sh[32];
    float tot = block_reduce_sum(ss, sh);
    float rinv = rsqrtf(tot / (float)D_ + EPS_);
    const float* yr = d_y + (size_t)t * D_;
    const float* xr = d_xffn_in + (size_t)t * D_;
    float* o = out + (size_t)t * D_;
    for (int i = threadIdx.x; i < D_; i += blockDim.x)
        o[i] = yr[i] + ysh[i] * rinv * sharedw[i] + xr[i];
}

// ---------------- host launch ----------------
static void* sym(const void* s) { void* p = nullptr; cudaGetSymbolAddress(&p, s); return p; }

extern "C" void kernel_launch(void* const* d_in, const int* in_sizes, int n_in,
                              void* d_out, int out_size) {
    const float* x_input      = (const float*)d_in[0];
    const int*   indices      = (const int*)  d_in[1];
    const float* values       = (const float*)d_in[2];
    const float* attn_w       = (const float*)d_in[3];
    const float* attn_o_w     = (const float*)d_in[4];
    const float* attn_norm_w  = (const float*)d_in[5];
    const float* ffn_norm_w   = (const float*)d_in[6];
    const float* ffn_experts  = (const float*)d_in[7];
    const float* main_keys    = (const float*)d_in[8];
    const float* main_bias    = (const float*)d_in[9];
    const float* output_coeff = (const float*)d_in[10];
    const float* ffn_up_w     = (const float*)d_in[11];
    const float* ffn_down_w   = (const float*)d_in[12];
    const float* shared_norm_w= (const float*)d_in[13];
    float* out = (float*)d_out;

    cudaFuncSetAttribute((const void*)gemm_mma<0,0>, cudaFuncAttributeMaxDynamicSharedMemorySize, GEMM_SMEM);
    cudaFuncSetAttribute((const void*)gemm_mma<0,1>, cudaFuncAttributeMaxDynamicSharedMemorySize, GEMM_SMEM);
    cudaFuncSetAttribute((const void*)gemm_mma<1,0>, cudaFuncAttributeMaxDynamicSharedMemorySize, GEMM_SMEM);
    cudaFuncSetAttribute((const void*)gemm_mma<2,0>, cudaFuncAttributeMaxDynamicSharedMemorySize, GEMM_SMEM);
    cudaFuncSetAttribute((const void*)flash_attn_tc, cudaFuncAttributeMaxDynamicSharedMemorySize, AT2_SMEM);

    __nv_bfloat16 *p_xn_h=(__nv_bfloat16*)sym(d_xn_h), *p_xn_l=(__nv_bfloat16*)sym(d_xn_l);
    __nv_bfloat16 *p_aw_h=(__nv_bfloat16*)sym(d_aw_h), *p_aw_l=(__nv_bfloat16*)sym(d_aw_l);
    __nv_bfloat16 *p_ow_h=(__nv_bfloat16*)sym(d_ow_h), *p_ow_l=(__nv_bfloat16*)sym(d_ow_l);
    __nv_bfloat16 *p_ao_h=(__nv_bfloat16*)sym(d_ao_h), *p_ao_l=(__nv_bfloat16*)sym(d_ao_l);
    __nv_bfloat16 *p_xf_h=(__nv_bfloat16*)sym(d_xffn_h), *p_xf_l=(__nv_bfloat16*)sym(d_xffn_l);
    __nv_bfloat16 *p_uw_h=(__nv_bfloat16*)sym(d_upw_h), *p_uw_l=(__nv_bfloat16*)sym(d_upw_l);
    __nv_bfloat16 *p_dw_h=(__nv_bfloat16*)sym(d_dnw_h), *p_dw_l=(__nv_bfloat16*)sym(d_dnw_l);
    __nv_bfloat16 *p_w12_h=(__nv_bfloat16*)sym(d_w12t_h), *p_w12_l=(__nv_bfloat16*)sym(d_w12t_l);
    __nv_bfloat16 *p_w3_h=(__nv_bfloat16*)sym(d_w3_h), *p_w3_l=(__nv_bfloat16*)sym(d_w3_l);
    __nv_bfloat16 *p_g_h=(__nv_bfloat16*)sym(d_g_h), *p_g_l=(__nv_bfloat16*)sym(d_g_l);
    __nv_bfloat16 *p_gs_h=(__nv_bfloat16*)sym(d_gs_h), *p_gs_l=(__nv_bfloat16*)sym(d_gs_l);
    float *p_qkv=(float*)sym(d_qkv), *p_xffn_in=(float*)sym(d_xffn_in), *p_xffn=(float*)sym(d_xffn);
    float *p_h12=(float*)sym(d_h12), *p_ys=(float*)sym(d_ys), *p_up=(float*)sym(d_up);
    float *p_ysh=(float*)sym(d_ysh);

    // per-launch weight conversions (vectorized)
    conv_hilo_kernel<<<2048, 256>>>((const float4*)attn_w, (uint2*)p_aw_h, (uint2*)p_aw_l,
                                    (size_t)3 * D_ * D_ / 4);
    conv_hilo_kernel<<<1024, 256>>>((const float4*)attn_o_w, (uint2*)p_ow_h, (uint2*)p_ow_l,
                                    (size_t)D_ * D_ / 4);
    conv_hilo_kernel<<<2048, 256>>>((const float4*)ffn_up_w, (uint2*)p_uw_h, (uint2*)p_uw_l,
                                    (size_t)2 * DS_ * D_ / 4);
    conv_hilo_kernel<<<2048, 256>>>((const float4*)ffn_down_w, (uint2*)p_dw_h, (uint2*)p_dw_l,
                                    (size_t)D_ * DS_ / 4);
    conv_hilo_kernel<<<4096, 256>>>((const float4*)(ffn_experts + (size_t)2 * TE_ * D_ * ED_),
                                    (uint2*)p_w3_h, (uint2*)p_w3_l, (size_t)TE_ * D_ * ED_ / 4);
    transpose_w12_kernel<<<dim3(32, 16, 16), dim3(32, 8)>>>(ffn_experts);

    // attention block
    rmsnorm_kernel<<<T_, 256>>>(x_input, attn_norm_w, nullptr, p_xn_h, p_xn_l);
    gemm_mma<0,0><<<dim3(24, 16), 256, GEMM_SMEM>>>(p_xn_h, p_xn_l, p_aw_h, p_aw_l,
                                                    p_qkv, nullptr, 3 * D_, D_, 0);
    rope_kernel<<<dim3(S_, H_), 32>>>(p_qkv);
    flash_attn_tc<<<dim3(S_ / 64, H_), 128, AT2_SMEM>>>(p_qkv);
    gemm_mma<0,1><<<dim3(8, 16), 256, GEMM_SMEM>>>(p_ao_h, p_ao_l, p_ow_h, p_ow_l,
                                                   p_xffn_in, x_input, D_, D_, 0);

    // ffn norm + router
    rmsnorm_kernel<<<T_, 256>>>(p_xffn_in, ffn_norm_w, p_xffn, p_xf_h, p_xf_l);
    router_kernel<<<T_, 32>>>(p_xffn, main_keys, indices, values, main_bias);
    zero_counts_kernel<<<1, 32>>>();
    scatter_kernel<<<(NSLOT + 255) / 256, 256>>>(indices);

    // routed experts
    gemm_mma<1,0><<<dim3(8, NSLOT / 128, TE_), 256, GEMM_SMEM>>>(
        p_xf_h, p_xf_l, p_w12_h, p_w12_l, p_h12, nullptr, 1024, 1024, (long long)1024 * 1024);
    swiglu_expert_kernel<<<(NSLOT * ED_ + 255) / 256, 256>>>();
    gemm_mma<2,0><<<dim3(8, NSLOT / 128, TE_), 256, GEMM_SMEM>>>(
        p_g_h, p_g_l, p_w3_h, p_w3_l, p_ys, nullptr, 1024, 512, (long long)D_ * ED_);
    combine_kernel<<<T_, 256>>>(output_coeff);

    // shared expert
    gemm_mma<0,0><<<dim3(32, 16), 256, GEMM_SMEM>>>(p_xf_h, p_xf_l, p_uw_h, p_uw_l,
                                                    p_up, nullptr, 2 * DS_, D_, 0);
    swiglu_shared_kernel<<<((size_t)T_ * DS_ + 255) / 256, 256>>>();
    gemm_mma<0,0><<<dim3(8, 16), 256, GEMM_SMEM>>>(p_gs_h, p_gs_l, p_dw_h, p_dw_l,
                                                   p_ysh, nullptr, D_, DS_, 0);

    // final combine
    final_kernel<<<T_, 256>>>(shared_norm_w, out);
}

// round 8
// speedup vs baseline: 9.9008x; 1.0408x over previous
#include <cuda_runtime.h>
#include <cuda_bf16.h>
#include <math.h>
#include <stdint.h>

// ---------------- problem constants ----------------
#define S_   2048
#define D_   1024
#define H_   16
#define HD_  64
#define TE_  16
#define TOPK 2
#define ED_  512
#define DS_  2048
#define T_   2048
#define NSLOT (T_*TOPK)
#define EPS_ 1e-5f

// ---------------- scratch (device bss, no allocation) ----------------
__device__ __align__(256) __nv_bfloat16 d_xn_h[(size_t)T_*D_],     d_xn_l[(size_t)T_*D_];
__device__ __align__(256) __nv_bfloat16 d_aw_h[(size_t)3*D_*D_],   d_aw_l[(size_t)3*D_*D_];
__device__ __align__(256) __nv_bfloat16 d_ow_h[(size_t)D_*D_],     d_ow_l[(size_t)D_*D_];
__device__ __align__(256) __nv_bfloat16 d_ao_h[(size_t)T_*D_],     d_ao_l[(size_t)T_*D_];
__device__ __align__(256) __nv_bfloat16 d_xffn_h[(size_t)T_*D_],   d_xffn_l[(size_t)T_*D_];
__device__ __align__(256) __nv_bfloat16 d_upw_h[(size_t)2*DS_*D_], d_upw_l[(size_t)2*DS_*D_];
__device__ __align__(256) __nv_bfloat16 d_dnw_h[(size_t)D_*DS_],   d_dnw_l[(size_t)D_*DS_];
__device__ __align__(256) __nv_bfloat16 d_w12t_h[(size_t)TE_*2*ED_*D_], d_w12t_l[(size_t)TE_*2*ED_*D_];
__device__ __align__(256) __nv_bfloat16 d_w3_h[(size_t)TE_*D_*ED_],     d_w3_l[(size_t)TE_*D_*ED_];
__device__ __align__(256) __nv_bfloat16 d_g_h[(size_t)NSLOT*ED_],  d_g_l[(size_t)NSLOT*ED_];
__device__ __align__(256) __nv_bfloat16 d_gs_h[(size_t)T_*DS_],    d_gs_l[(size_t)T_*DS_];
__device__ __align__(256) __nv_bfloat16 d_q_h[(size_t)T_*D_], d_q_l[(size_t)T_*D_];
__device__ __align__(256) __nv_bfloat16 d_k_h[(size_t)T_*D_], d_k_l[(size_t)T_*D_];
__device__ __align__(256) __nv_bfloat16 d_v_h[(size_t)T_*D_], d_v_l[(size_t)T_*D_];
__device__ __align__(256) float d_qkv[(size_t)T_*3*D_];
__device__ __align__(256) float d_xffn_in[(size_t)T_*D_];
__device__ __align__(256) float d_xffn[(size_t)T_*D_];
__device__ __align__(256) float d_h12[(size_t)NSLOT*2*ED_];
__device__ __align__(256) float d_ys[(size_t)NSLOT*D_];
__device__ __align__(256) float d_y[(size_t)T_*D_];
__device__ __align__(256) float d_up[(size_t)T_*2*DS_];
__device__ __align__(256) float d_ysh[(size_t)T_*D_];
__device__ float d_scores[NSLOT];
__device__ int   d_counts[TE_];
__device__ int   d_list[TE_*NSLOT];

// ---------------- helpers ----------------
__device__ __forceinline__ void f2hilo(float x, __nv_bfloat16* h, __nv_bfloat16* l) {
    __nv_bfloat16 hh = __float2bfloat16(x);
    *h = hh;
    *l = __float2bfloat16(x - __bfloat162float(hh));
}
__device__ __forceinline__ uint32_t bpack(__nv_bfloat16 a, __nv_bfloat16 b) {
    uint16_t ua = *(uint16_t*)&a, ub = *(uint16_t*)&b;
    return ((uint32_t)ub << 16) | ua;
}
__device__ __forceinline__ uint32_t packh(float x, float y, uint32_t* lo) {
    __nv_bfloat16 hx = __float2bfloat16(x), hy = __float2bfloat16(y);
    __nv_bfloat16 lx = __float2bfloat16(x - __bfloat162float(hx));
    __nv_bfloat16 ly = __float2bfloat16(y - __bfloat162float(hy));
    *lo = bpack(lx, ly);
    return bpack(hx, hy);
}
__device__ __forceinline__ float block_reduce_sum(float v, float* sh) {
    __syncthreads();
    int lane = threadIdx.x & 31, wid = threadIdx.x >> 5;
#pragma unroll
    for (int o = 16; o; o >>= 1) v += __shfl_xor_sync(0xffffffffu, v, o);
    if (lane == 0) sh[wid] = v;
    __syncthreads();
    int nw = blockDim.x >> 5;
    v = (threadIdx.x < nw) ? sh[threadIdx.x] : 0.f;
    if (wid == 0) {
#pragma unroll
        for (int o = 16; o; o >>= 1) v += __shfl_xor_sync(0xffffffffu, v, o);
        if (lane == 0) sh[0] = v;
    }
    __syncthreads();
    return sh[0];
}
__device__ __forceinline__ void mma16816(float* d, const uint32_t* a, const uint32_t* b) {
    asm volatile(
        "mma.sync.aligned.m16n8k16.row.col.f32.bf16.bf16.f32 "
        "{%0,%1,%2,%3}, {%4,%5,%6,%7}, {%8,%9}, {%0,%1,%2,%3};"
        : "+f"(d[0]), "+f"(d[1]), "+f"(d[2]), "+f"(d[3])
        : "r"(a[0]), "r"(a[1]), "r"(a[2]), "r"(a[3]), "r"(b[0]), "r"(b[1]));
}
__device__ __forceinline__ void ldsm_x4(uint32_t* r, uint32_t addr) {
    asm volatile("ldmatrix.sync.aligned.m8n8.x4.shared.b16 {%0,%1,%2,%3}, [%4];"
        : "=r"(r[0]), "=r"(r[1]), "=r"(r[2]), "=r"(r[3]) : "r"(addr));
}
__device__ __forceinline__ void ldsm_x4t(uint32_t* r, uint32_t addr) {
    asm volatile("ldmatrix.sync.aligned.m8n8.x4.trans.shared.b16 {%0,%1,%2,%3}, [%4];"
        : "=r"(r[0]), "=r"(r[1]), "=r"(r[2]), "=r"(r[3]) : "r"(addr));
}
__device__ __forceinline__ void cpa16(uint32_t dst, const void* src, int sb) {
    asm volatile("cp.async.cg.shared.global [%0], [%1], 16, %2;"
                 :: "r"(dst), "l"(src), "r"(sb));
}
__device__ __forceinline__ void cpa_commit() { asm volatile("cp.async.commit_group;"); }
template<int N> __device__ __forceinline__ void cpa_wait() {
    asm volatile("cp.async.wait_group %0;" :: "n"(N));
}

// ---------------- conversion kernels (vectorized) ----------------
__global__ void conv_hilo_kernel(const float4* __restrict__ src, uint2* __restrict__ hi,
                                 uint2* __restrict__ lo, size_t n4) {
    for (size_t i = (size_t)blockIdx.x * blockDim.x + threadIdx.x; i < n4;
         i += (size_t)gridDim.x * blockDim.x) {
        float4 v = src[i];
        __nv_bfloat16 h0, l0, h1, l1, h2, l2, h3, l3;
        f2hilo(v.x, &h0, &l0); f2hilo(v.y, &h1, &l1);
        f2hilo(v.z, &h2, &l2); f2hilo(v.w, &h3, &l3);
        uint2 ho, lw;
        ho.x = bpack(h0, h1); ho.y = bpack(h2, h3);
        lw.x = bpack(l0, l1); lw.y = bpack(l2, l3);
        hi[i] = ho; lo[i] = lw;
    }
}

// experts W1/W2 [m][e][k=D][n=ED] -> w12t [e][n'(=m*512+n)][k] hi/lo (packed stores)
__global__ void transpose_w12_kernel(const float* __restrict__ experts) {
    __shared__ float tile[64][33];
    int e = blockIdx.z;
    int n0 = blockIdx.x * 32, k0 = blockIdx.y * 64;
    int m = n0 >> 9, c0 = n0 & 511;
    for (int kk = threadIdx.y; kk < 64; kk += 8)
        tile[kk][threadIdx.x] =
            experts[((size_t)(m * TE_ + e) * D_ + k0 + kk) * ED_ + c0 + threadIdx.x];
    __syncthreads();
    for (int ny = threadIdx.y; ny < 32; ny += 8) {
        float va = tile[threadIdx.x * 2][ny];
        float vb = tile[threadIdx.x * 2 + 1][ny];
        __nv_bfloat16 ha, la, hb, lb;
        f2hilo(va, &ha, &la); f2hilo(vb, &hb, &lb);
        size_t o = ((size_t)e << 20) + (size_t)(n0 + ny) * 1024 + k0 + threadIdx.x * 2;
        *(uint32_t*)(d_w12t_h + o) = bpack(ha, hb);
        *(uint32_t*)(d_w12t_l + o) = bpack(la, lb);
    }
}

// ---------------- rmsnorm (fp32 optional + hi/lo) ----------------
__global__ void rmsnorm_kernel(const float* __restrict__ x, const float* __restrict__ w,
                               float* __restrict__ outf, __nv_bfloat16* __restrict__ oh,
                               __nv_bfloat16* __restrict__ ol) {
    int row = blockIdx.x;
    const float* xr = x + (size_t)row * D_;
    float ss = 0.f;
    for (int i = threadIdx.x; i < D_; i += blockDim.x) { float v = xr[i]; ss += v * v; }
    __shared__ float sh[32];
    float tot = block_reduce_sum(ss, sh);
    float rinv = rsqrtf(tot / (float)D_ + EPS_);
    for (int i = threadIdx.x; i < D_; i += blockDim.x) {
        float v = xr[i] * rinv * w[i];
        size_t o = (size_t)row * D_ + i;
        if (outf) outf[o] = v;
        f2hilo(v, oh + o, ol + o);
    }
}

// ---------------- warp-MMA split-bf16 GEMM: C[M,N] = A @ B^T ----------------
// CTA tile 128x128, BK=32, 8 warps (2x4), warp tile 64x32, 3-stage cp.async ring,
// ldmatrix fragment loads, one barrier per chunk.
#define SD    40                   /* smem row stride in bf16 (conflict-free) */
#define STG_E (4*128*SD)           /* bf16 elems per stage (Ah,Al,Bh,Bl) */
#define GEMM_SMEM (3*STG_E*2)      /* bytes */

template<int GATHER, int RES>
__global__ void __launch_bounds__(256, 1) gemm_mma(
    const __nv_bfloat16* __restrict__ Ah, const __nv_bfloat16* __restrict__ Al,
    const __nv_bfloat16* __restrict__ Bh, const __nv_bfloat16* __restrict__ Bl,
    float* __restrict__ C, const float* __restrict__ Res,
    int N, int K, long long bstride)
{
    __shared__ int s_row[128];
    __shared__ int s_out[128];
    int tid = threadIdx.x, wid = tid >> 5, lid = tid & 31;
    if (GATHER) {
        int e = blockIdx.z, cnt = d_counts[e];
        if ((int)blockIdx.y * 128 >= cnt) return;
        if (tid < 128) {
            int r = blockIdx.y * 128 + tid;
            int sl = (r < cnt) ? d_list[e * NSLOT + r] : -1;
            s_out[tid] = sl;
            s_row[tid] = (sl < 0) ? -1 : (GATHER == 1 ? (sl >> 1) : sl);
        }
        Bh += (size_t)blockIdx.z * bstride;
        Bl += (size_t)blockIdx.z * bstride;
    } else if (tid < 128) {
        int r = blockIdx.y * 128 + tid;
        s_row[tid] = r; s_out[tid] = r;
    }
    extern __shared__ __nv_bfloat16 sm[];
    uint32_t smb = (uint32_t)__cvta_generic_to_shared(sm);
    int n0 = blockIdx.x * 128;
    int NC = K >> 5;
    __syncthreads();

    int lrow = tid >> 2, lq = tid & 3;
    int arow0 = s_row[lrow];
    const __nv_bfloat16* asrc_h = Ah + (size_t)(arow0 < 0 ? 0 : arow0) * K + lq * 8;
    const __nv_bfloat16* asrc_l = Al + (size_t)(arow0 < 0 ? 0 : arow0) * K + lq * 8;
    const __nv_bfloat16* bsrc_h = Bh + (size_t)(n0 + lrow) * K + lq * 8;
    const __nv_bfloat16* bsrc_l = Bl + (size_t)(n0 + lrow) * K + lq * 8;
    int asb = (arow0 < 0) ? 0 : 16;
    int arow1 = s_row[lrow + 64];
    const __nv_bfloat16* asrc2_h = Ah + (size_t)(arow1 < 0 ? 0 : arow1) * K + lq * 8;
    const __nv_bfloat16* asrc2_l = Al + (size_t)(arow1 < 0 ? 0 : arow1) * K + lq * 8;
    const __nv_bfloat16* bsrc2_h = Bh + (size_t)(n0 + lrow + 64) * K + lq * 8;
    const __nv_bfloat16* bsrc2_l = Bl + (size_t)(n0 + lrow + 64) * K + lq * 8;
    int asb2 = (arow1 < 0) ? 0 : 16;
    uint32_t o1 = (uint32_t)((lrow * SD + lq * 8) << 1);
    uint32_t o2 = (uint32_t)(((lrow + 64) * SD + lq * 8) << 1);
    const uint32_t OFF_AL = (uint32_t)((128 * SD) << 1);
    const uint32_t OFF_BH = (uint32_t)((2 * 128 * SD) << 1);
    const uint32_t OFF_BL = (uint32_t)((3 * 128 * SD) << 1);

    auto issue = [&](int c, int buf) {
        uint32_t st = smb + (uint32_t)(buf * STG_E * 2);
        int kc = c << 5;
        cpa16(st + o1, asrc_h + kc, asb);
        cpa16(st + OFF_AL + o1, asrc_l + kc, asb);
        cpa16(st + OFF_BH + o1, bsrc_h + kc, 16);
        cpa16(st + OFF_BL + o1, bsrc_l + kc, 16);
        cpa16(st + o2, asrc2_h + kc, asb2);
        cpa16(st + OFF_AL + o2, asrc2_l + kc, asb2);
        cpa16(st + OFF_BH + o2, bsrc2_h + kc, 16);
        cpa16(st + OFF_BL + o2, bsrc2_l + kc, 16);
        cpa_commit();
    };

    int wm = wid & 1, wn = wid >> 1;
    int r = lid >> 2, c2 = (lid & 3) << 1;
    uint32_t a_lane = (uint32_t)(((lid & 15) * SD + ((lid >> 4) << 3)) << 1);
    uint32_t b_lane = (uint32_t)((((((lid >> 4) << 3) + (lid & 7)) * SD) + (((lid >> 3) & 1) << 3)) << 1);
    float acc[4][4][4] = {};

    issue(0, 0);
    if (NC > 1) issue(1, 1);
    for (int c = 0; c < NC; c++) {
        int buf = c % 3;
        if (c + 1 < NC) cpa_wait<1>(); else cpa_wait<0>();
        __syncthreads();
        uint32_t base = smb + (uint32_t)(buf * STG_E * 2);
#pragma unroll
        for (int ks = 0; ks < 2; ks++) {
            uint32_t kb = (uint32_t)(ks << 5);
            uint32_t ah[4][4], al[4][4];
#pragma unroll
            for (int mt = 0; mt < 4; mt++) {
                uint32_t ab = base + (uint32_t)(((wm * 64 + mt * 16) * SD) << 1) + kb + a_lane;
                ldsm_x4(ah[mt], ab);
                ldsm_x4(al[mt], ab + OFF_AL);
            }
            uint32_t bh[4][2], bl[4][2];
#pragma unroll
            for (int p = 0; p < 2; p++) {
                uint32_t bb = base + OFF_BH
                            + (uint32_t)(((wn * 32 + p * 16) * SD) << 1) + kb + b_lane;
                uint32_t t[4];
                ldsm_x4(t, bb);
                bh[2*p][0] = t[0]; bh[2*p][1] = t[1];
                bh[2*p+1][0] = t[2]; bh[2*p+1][1] = t[3];
                ldsm_x4(t, bb + OFF_AL);
                bl[2*p][0] = t[0]; bl[2*p][1] = t[1];
                bl[2*p+1][0] = t[2]; bl[2*p+1][1] = t[3];
            }
#pragma unroll
            for (int nt = 0; nt < 4; nt++)
#pragma unroll
                for (int mt = 0; mt < 4; mt++) {
                    mma16816(acc[mt][nt], ah[mt], bh[nt]);
                    mma16816(acc[mt][nt], al[mt], bh[nt]);
                    mma16816(acc[mt][nt], ah[mt], bl[nt]);
                }
        }
        if (c + 2 < NC) issue(c + 2, (c + 2) % 3);
    }

    // epilogue (float2 stores)
#pragma unroll
    for (int mt = 0; mt < 4; mt++) {
        int rloc0 = wm * 64 + mt * 16 + r;
#pragma unroll
        for (int half = 0; half < 2; half++) {
            int rloc = rloc0 + half * 8;
            int outr = s_out[rloc];
            if (GATHER && outr < 0) continue;
            float* crow = C + (size_t)outr * N + n0;
#pragma unroll
            for (int nt = 0; nt < 4; nt++) {
                int col = wn * 32 + nt * 8 + c2;
                float v0 = acc[mt][nt][half * 2 + 0];
                float v1 = acc[mt][nt][half * 2 + 1];
                if (RES) {
                    const float* rrow = Res + (size_t)outr * N + n0;
                    v0 += rrow[col]; v1 += rrow[col + 1];
                }
                float2 fv = make_float2(v0, v1);
                *(float2*)(crow + col) = fv;
            }
        }
    }
}

// ---------------- RoPE + convert: qkv fp32 -> q/k/v bf16 hi/lo ----------------
__global__ void rope_conv_kernel(const float* __restrict__ qkv) {
    int s = blockIdx.x, h = blockIdx.y, i = threadIdx.x;  // i in [0,32)
    float inv = powf(10000.0f, -(float)i / 32.0f);
    float fr = (float)s * inv;
    float c = cosf(fr), sn = sinf(fr);
    const float* q = qkv + (size_t)s * 3 * D_ + h * HD_;
    const float* k = q + D_;
    const float* v = q + 2 * D_;
    size_t o = (size_t)s * D_ + h * HD_ + i;
    float q1 = q[i], q2 = q[i + 32];
    f2hilo(q1 * c + q2 * sn,  d_q_h + o,      d_q_l + o);
    f2hilo(-q1 * sn + q2 * c, d_q_h + o + 32, d_q_l + o + 32);
    float k1 = k[i], k2 = k[i + 32];
    f2hilo(k1 * c + k2 * sn,  d_k_h + o,      d_k_l + o);
    f2hilo(-k1 * sn + k2 * c, d_k_h + o + 32, d_k_l + o + 32);
    f2hilo(v[i],      d_v_h + o,      d_v_l + o);
    f2hilo(v[i + 32], d_v_h + o + 32, d_v_l + o + 32);
}

// ---------------- tensor-core flash attention (bf16 inputs, cp.async ring) ----------------
// 64 q-rows per CTA (4 warps x 16 rows), 64-key tiles, 3-stage K/V ring, 1 barrier/tile.
#define ASD 72
#define AMAT (64*ASD)                 /* bf16 elems per matrix */
#define AT2_SMEM ((2 + 12)*AMAT*2)    /* Qh,Ql + 3 stages x (Kh,Kl,Vh,Vl) */
__global__ void __launch_bounds__(128) flash_attn_tc(int dummy) {
    extern __shared__ __nv_bfloat16 asm_[];
    uint32_t bQ = (uint32_t)__cvta_generic_to_shared(asm_);
    const uint32_t OFF1 = (uint32_t)(AMAT << 1);      // bytes per matrix
    int qt = blockIdx.x, h = blockIdx.y;
    int tid = threadIdx.x, wid = tid >> 5, lid = tid & 31;
    int q0 = qt * 64;
    int lrow = tid >> 1, lc0 = (tid & 1) * 32;

    // Q tile load (grouped with stage 0)
    {
        const __nv_bfloat16* qh = d_q_h + (size_t)(q0 + lrow) * D_ + h * HD_ + lc0;
        const __nv_bfloat16* ql = d_q_l + (size_t)(q0 + lrow) * D_ + h * HD_ + lc0;
#pragma unroll
        for (int j = 0; j < 4; j++) {
            uint32_t off = (uint32_t)((lrow * ASD + lc0 + j * 8) << 1);
            cpa16(bQ + off, qh + j * 8, 16);
            cpa16(bQ + OFF1 + off, ql + j * 8, 16);
        }
    }
    auto issueKV = [&](int kt, int s) {
        uint32_t st = bQ + (uint32_t)((2 + 4 * s) * AMAT * 2);
        size_t src = (size_t)(kt * 64 + lrow) * D_ + h * HD_ + lc0;
#pragma unroll
        for (int j = 0; j < 4; j++) {
            uint32_t off = (uint32_t)((lrow * ASD + lc0 + j * 8) << 1);
            cpa16(st + off,            d_k_h + src + j * 8, 16);
            cpa16(st + OFF1 + off,     d_k_l + src + j * 8, 16);
            cpa16(st + 2 * OFF1 + off, d_v_h + src + j * 8, 16);
            cpa16(st + 3 * OFF1 + off, d_v_l + src + j * 8, 16);
        }
        cpa_commit();
    };
    issueKV(0, 0);                    // group 0: Q + stage0
    if (qt >= 1) issueKV(1, 1);       // group 1

    uint32_t a_lane = (uint32_t)(((lid & 15) * ASD + ((lid >> 4) << 3)) << 1);
    uint32_t b_lane = (uint32_t)((((((lid >> 4) << 3) + (lid & 7)) * ASD) + (((lid >> 3) & 1) << 3)) << 1);
    uint32_t v_lane = (uint32_t)((((lid & 7) + (((lid >> 3) & 1) << 3)) * ASD + ((lid >> 4) << 3)) << 1);
    int ra = lid >> 2, c2 = (lid & 3) << 1;
    int rowa = wid * 16 + ra;
    int ga = q0 + rowa, gb = ga + 8;

    float m0 = -1e30f, m1 = -1e30f, l0 = 0.f, l1 = 0.f;
    float O[8][4] = {};

    for (int kt = 0; kt <= qt; kt++) {
        if (kt + 1 <= qt) cpa_wait<1>(); else cpa_wait<0>();
        __syncthreads();
        uint32_t bK = bQ + (uint32_t)((2 + 4 * (kt % 3)) * AMAT * 2);
        uint32_t bV = bK + 2 * OFF1;

        // S = Q K^T (split-bf16, 3 MMAs)
        float S[8][4] = {};
#pragma unroll
        for (int ks = 0; ks < 4; ks++) {
            uint32_t kb = (uint32_t)(ks << 5);
            uint32_t ah[4], al[4];
            uint32_t ab = (uint32_t)(((wid * 16) * ASD) << 1) + kb + a_lane;
            ldsm_x4(ah, bQ + ab);
            ldsm_x4(al, bQ + OFF1 + ab);
#pragma unroll
            for (int p = 0; p < 4; p++) {
                uint32_t bb = (uint32_t)(((p * 16) * ASD) << 1) + kb + b_lane;
                uint32_t th[4], tl[4];
                ldsm_x4(th, bK + bb);
                ldsm_x4(tl, bK + OFF1 + bb);
                uint32_t bh0[2] = {th[0], th[1]}, bh1[2] = {th[2], th[3]};
                uint32_t bl0[2] = {tl[0], tl[1]}, bl1[2] = {tl[2], tl[3]};
                mma16816(S[2*p],   ah, bh0); mma16816(S[2*p],   al, bh0); mma16816(S[2*p],   ah, bl0);
                mma16816(S[2*p+1], ah, bh1); mma16816(S[2*p+1], al, bh1); mma16816(S[2*p+1], ah, bl1);
            }
        }
        // scale + causal mask
        bool diag = (kt == qt);
#pragma unroll
        for (int t = 0; t < 8; t++) {
            int col = kt * 64 + t * 8 + c2;
            S[t][0] *= 0.125f; S[t][1] *= 0.125f; S[t][2] *= 0.125f; S[t][3] *= 0.125f;
            if (diag) {
                if (col     > ga) S[t][0] = -1e30f;
                if (col + 1 > ga) S[t][1] = -1e30f;
                if (col     > gb) S[t][2] = -1e30f;
                if (col + 1 > gb) S[t][3] = -1e30f;
            }
        }
        // online softmax
        float mxa = -1e30f, mxb = -1e30f;
#pragma unroll
        for (int t = 0; t < 8; t++) {
            mxa = fmaxf(mxa, fmaxf(S[t][0], S[t][1]));
            mxb = fmaxf(mxb, fmaxf(S[t][2], S[t][3]));
        }
        mxa = fmaxf(mxa, __shfl_xor_sync(0xffffffffu, mxa, 1));
        mxa = fmaxf(mxa, __shfl_xor_sync(0xffffffffu, mxa, 2));
        mxb = fmaxf(mxb, __shfl_xor_sync(0xffffffffu, mxb, 1));
        mxb = fmaxf(mxb, __shfl_xor_sync(0xffffffffu, mxb, 2));
        float nma = fmaxf(m0, mxa), nmb = fmaxf(m1, mxb);
        float faca = __expf(m0 - nma), facb = __expf(m1 - nmb);
        m0 = nma; m1 = nmb;
        float suma = 0.f, sumb = 0.f;
#pragma unroll
        for (int t = 0; t < 8; t++) {
            S[t][0] = __expf(S[t][0] - nma); suma += S[t][0];
            S[t][1] = __expf(S[t][1] - nma); suma += S[t][1];
            S[t][2] = __expf(S[t][2] - nmb); sumb += S[t][2];
            S[t][3] = __expf(S[t][3] - nmb); sumb += S[t][3];
        }
        suma += __shfl_xor_sync(0xffffffffu, suma, 1);
        suma += __shfl_xor_sync(0xffffffffu, suma, 2);
        sumb += __shfl_xor_sync(0xffffffffu, sumb, 1);
        sumb += __shfl_xor_sync(0xffffffffu, sumb, 2);
        l0 = l0 * faca + suma; l1 = l1 * facb + sumb;
#pragma unroll
        for (int t = 0; t < 8; t++) {
            O[t][0] *= faca; O[t][1] *= faca; O[t][2] *= facb; O[t][3] *= facb;
        }
        // O += P V
#pragma unroll
        for (int ks = 0; ks < 4; ks++) {
            uint32_t ph[4], pl[4];
            ph[0] = packh(S[2*ks][0],   S[2*ks][1],   &pl[0]);
            ph[1] = packh(S[2*ks][2],   S[2*ks][3],   &pl[1]);
            ph[2] = packh(S[2*ks+1][0], S[2*ks+1][1], &pl[2]);
            ph[3] = packh(S[2*ks+1][2], S[2*ks+1][3], &pl[3]);
#pragma unroll
            for (int p = 0; p < 4; p++) {
                uint32_t vb = (uint32_t)(((16 * ks) * ASD + 16 * p) << 1) + v_lane;
                uint32_t th[4], tl[4];
                ldsm_x4t(th, bV + vb);
                ldsm_x4t(tl, bV + OFF1 + vb);
                uint32_t bh0[2] = {th[0], th[1]}, bh1[2] = {th[2], th[3]};
                uint32_t bl0[2] = {tl[0], tl[1]}, bl1[2] = {tl[2], tl[3]};
                mma16816(O[2*p],   ph, bh0); mma16816(O[2*p],   pl, bh0); mma16816(O[2*p],   ph, bl0);
                mma16816(O[2*p+1], ph, bh1); mma16816(O[2*p+1], pl, bh1); mma16816(O[2*p+1], ph, bl1);
            }
        }
        if (kt + 2 <= qt) issueKV(kt + 2, (kt + 2) % 3);
    }
    // epilogue: normalize + hi/lo store
    float il0 = 1.0f / l0, il1 = 1.0f / l1;
#pragma unroll
    for (int t = 0; t < 8; t++) {
        int col = h * HD_ + t * 8 + c2;
        size_t r0 = (size_t)ga * D_ + col;
        size_t r1 = (size_t)gb * D_ + col;
        f2hilo(O[t][0] * il0, d_ao_h + r0,     d_ao_l + r0);
        f2hilo(O[t][1] * il0, d_ao_h + r0 + 1, d_ao_l + r0 + 1);
        f2hilo(O[t][2] * il1, d_ao_h + r1,     d_ao_l + r1);
        f2hilo(O[t][3] * il1, d_ao_h + r1 + 1, d_ao_l + r1 + 1);
    }
}

// ---------------- router ----------------
__global__ void router_kernel(const float* __restrict__ xffn, const float* __restrict__ keys,
                              const int* __restrict__ idx, const float* __restrict__ vals,
                              const float* __restrict__ bias) {
    int t = blockIdx.x, lane = threadIdx.x;
    int e0 = idx[t * 2], e1 = idx[t * 2 + 1];
    const float* xr = xffn + (size_t)t * D_;
    float s0 = 0.f, s1 = 0.f;
    for (int d = lane; d < D_; d += 32) {
        float x = xr[d];
        s0 += x * keys[d * TE_ + e0];
        s1 += x * keys[d * TE_ + e1];
    }
#pragma unroll
    for (int o = 16; o; o >>= 1) {
        s0 += __shfl_xor_sync(0xffffffffu, s0, o);
        s1 += __shfl_xor_sync(0xffffffffu, s1, o);
    }
    if (lane == 0) {
        float v0 = vals[t * 2] + s0 + bias[e0];
        float v1 = vals[t * 2 + 1] + s1 + bias[e1];
        float mm = fmaxf(v0, v1);
        float a = expf(v0 - mm), b = expf(v1 - mm);
        float inv = 1.0f / (a + b);
        d_scores[t * 2] = a * inv;
        d_scores[t * 2 + 1] = b * inv;
    }
}

__global__ void zero_counts_kernel() {
    if (threadIdx.x < TE_) d_counts[threadIdx.x] = 0;
}
__global__ void scatter_kernel(const int* __restrict__ idx) {
    int slot = blockIdx.x * blockDim.x + threadIdx.x;
    if (slot < NSLOT) {
        int e = idx[slot];
        int p = atomicAdd(&d_counts[e], 1);
        d_list[e * NSLOT + p] = slot;
    }
}

// ---------------- swiglu (experts): h12 -> g hi/lo ----------------
__global__ void swiglu_expert_kernel() {
    int i = blockIdx.x * 256 + threadIdx.x;
    if (i < NSLOT * ED_) {
        int sl = i >> 9, j = i & 511;
        float a = d_h12[(size_t)sl * 1024 + j];
        float b = d_h12[(size_t)sl * 1024 + 512 + j];
        float g = (a / (1.f + __expf(-a))) * b;
        f2hilo(g, d_g_h + (size_t)sl * ED_ + j, d_g_l + (size_t)sl * ED_ + j);
    }
}

// ---------------- shared swiglu: up -> gs hi/lo ----------------
__global__ void swiglu_shared_kernel() {
    size_t i = (size_t)blockIdx.x * 256 + threadIdx.x;
    if (i < (size_t)T_ * DS_) {
        size_t t = i / DS_, j = i % DS_;
        float a = d_up[t * 2 * DS_ + j];
        float b = d_up[t * 2 * DS_ + DS_ + j];
        float g = (a / (1.f + __expf(-a))) * b;
        f2hilo(g, d_gs_h + i, d_gs_l + i);
    }
}

// ---------------- combine routed outputs ----------------
__global__ void combine_kernel(const float* __restrict__ coeff) {
    int t = blockIdx.x, tid = threadIdx.x;
    float s0 = d_scores[t * 2], s1 = d_scores[t * 2 + 1];
    const float* y0 = d_ys + (size_t)(t * 2) * D_;
    const float* y1 = d_ys + (size_t)(t * 2 + 1) * D_;
    float* yo = d_y + (size_t)t * D_;
    for (int dd = tid; dd < D_; dd += 256)
        yo[dd] = (s0 * y0[dd] + s1 * y1[dd]) * coeff[dd];
}

// ---------------- final combine ----------------
__global__ void final_kernel(const float* __restrict__ sharedw, float* __restrict__ out) {
    int t = blockIdx.x;
    const float* ysh = d_ysh + (size_t)t * D_;
    float ss = 0.f;
    for (int i = threadIdx.x; i < D_; i += blockDim.x) { float v = ysh[i]; ss += v * v; }
    __shared__ float sh[32];
    float tot = block_reduce_sum(ss, sh);
    float rinv = rsqrtf(tot / (float)D_ + EPS_);
    const float* yr = d_y + (size_t)t * D_;
    const float* xr = d_xffn_in + (size_t)t * D_;
    float* o = out + (size_t)t * D_;
    for (int i = threadIdx.x; i < D_; i += blockDim.x)
        o[i] = yr[i] + ysh[i] * rinv * sharedw[i] + xr[i];
}

// ---------------- host launch ----------------
static void* sym(const void* s) { void* p = nullptr; cudaGetSymbolAddress(&p, s); return p; }

extern "C" void kernel_launch(void* const* d_in, const int* in_sizes, int n_in,
                              void* d_out, int out_size) {
    const float* x_input      = (const float*)d_in[0];
    const int*   indices      = (const int*)  d_in[1];
    const float* values       = (const float*)d_in[2];
    const float* attn_w       = (const float*)d_in[3];
    const float* attn_o_w     = (const float*)d_in[4];
    const float* attn_norm_w  = (const float*)d_in[5];
    const float* ffn_norm_w   = (const float*)d_in[6];
    const float* ffn_experts  = (const float*)d_in[7];
    const float* main_keys    = (const float*)d_in[8];
    const float* main_bias    = (const float*)d_in[9];
    const float* output_coeff = (const float*)d_in[10];
    const float* ffn_up_w     = (const float*)d_in[11];
    const float* ffn_down_w   = (const float*)d_in[12];
    const float* shared_norm_w= (const float*)d_in[13];
    float* out = (float*)d_out;

    cudaFuncSetAttribute((const void*)gemm_mma<0,0>, cudaFuncAttributeMaxDynamicSharedMemorySize, GEMM_SMEM);
    cudaFuncSetAttribute((const void*)gemm_mma<0,1>, cudaFuncAttributeMaxDynamicSharedMemorySize, GEMM_SMEM);
    cudaFuncSetAttribute((const void*)gemm_mma<1,0>, cudaFuncAttributeMaxDynamicSharedMemorySize, GEMM_SMEM);
    cudaFuncSetAttribute((const void*)gemm_mma<2,0>, cudaFuncAttributeMaxDynamicSharedMemorySize, GEMM_SMEM);
    cudaFuncSetAttribute((const void*)flash_attn_tc, cudaFuncAttributeMaxDynamicSharedMemorySize, AT2_SMEM);

    __nv_bfloat16 *p_xn_h=(__nv_bfloat16*)sym(d_xn_h), *p_xn_l=(__nv_bfloat16*)sym(d_xn_l);
    __nv_bfloat16 *p_aw_h=(__nv_bfloat16*)sym(d_aw_h), *p_aw_l=(__nv_bfloat16*)sym(d_aw_l);
    __nv_bfloat16 *p_ow_h=(__nv_bfloat16*)sym(d_ow_h), *p_ow_l=(__nv_bfloat16*)sym(d_ow_l);
    __nv_bfloat16 *p_ao_h=(__nv_bfloat16*)sym(d_ao_h), *p_ao_l=(__nv_bfloat16*)sym(d_ao_l);
    __nv_bfloat16 *p_xf_h=(__nv_bfloat16*)sym(d_xffn_h), *p_xf_l=(__nv_bfloat16*)sym(d_xffn_l);
    __nv_bfloat16 *p_uw_h=(__nv_bfloat16*)sym(d_upw_h), *p_uw_l=(__nv_bfloat16*)sym(d_upw_l);
    __nv_bfloat16 *p_dw_h=(__nv_bfloat16*)sym(d_dnw_h), *p_dw_l=(__nv_bfloat16*)sym(d_dnw_l);
    __nv_bfloat16 *p_w12_h=(__nv_bfloat16*)sym(d_w12t_h), *p_w12_l=(__nv_bfloat16*)sym(d_w12t_l);
    __nv_bfloat16 *p_w3_h=(__nv_bfloat16*)sym(d_w3_h), *p_w3_l=(__nv_bfloat16*)sym(d_w3_l);
    __nv_bfloat16 *p_g_h=(__nv_bfloat16*)sym(d_g_h), *p_g_l=(__nv_bfloat16*)sym(d_g_l);
    __nv_bfloat16 *p_gs_h=(__nv_bfloat16*)sym(d_gs_h), *p_gs_l=(__nv_bfloat16*)sym(d_gs_l);
    float *p_qkv=(float*)sym(d_qkv), *p_xffn_in=(float*)sym(d_xffn_in), *p_xffn=(float*)sym(d_xffn);
    float *p_h12=(float*)sym(d_h12), *p_ys=(float*)sym(d_ys), *p_up=(float*)sym(d_up);
    float *p_ysh=(float*)sym(d_ysh);

    // per-launch weight conversions (vectorized)
    conv_hilo_kernel<<<2048, 256>>>((const float4*)attn_w, (uint2*)p_aw_h, (uint2*)p_aw_l,
                                    (size_t)3 * D_ * D_ / 4);
    conv_hilo_kernel<<<1024, 256>>>((const float4*)attn_o_w, (uint2*)p_ow_h, (uint2*)p_ow_l,
                                    (size_t)D_ * D_ / 4);
    conv_hilo_kernel<<<2048, 256>>>((const float4*)ffn_up_w, (uint2*)p_uw_h, (uint2*)p_uw_l,
                                    (size_t)2 * DS_ * D_ / 4);
    conv_hilo_kernel<<<2048, 256>>>((const float4*)ffn_down_w, (uint2*)p_dw_h, (uint2*)p_dw_l,
                                    (size_t)D_ * DS_ / 4);
    conv_hilo_kernel<<<4096, 256>>>((const float4*)(ffn_experts + (size_t)2 * TE_ * D_ * ED_),
                                    (uint2*)p_w3_h, (uint2*)p_w3_l, (size_t)TE_ * D_ * ED_ / 4);
    transpose_w12_kernel<<<dim3(32, 16, 16), dim3(32, 8)>>>(ffn_experts);

    // attention block
    rmsnorm_kernel<<<T_, 256>>>(x_input, attn_norm_w, nullptr, p_xn_h, p_xn_l);
    gemm_mma<0,0><<<dim3(24, 16), 256, GEMM_SMEM>>>(p_xn_h, p_xn_l, p_aw_h, p_aw_l,
                                                    p_qkv, nullptr, 3 * D_, D_, 0);
    rope_conv_kernel<<<dim3(S_, H_), 32>>>(p_qkv);
    flash_attn_tc<<<dim3(S_ / 64, H_), 128, AT2_SMEM>>>(0);
    gemm_mma<0,1><<<dim3(8, 16), 256, GEMM_SMEM>>>(p_ao_h, p_ao_l, p_ow_h, p_ow_l,
                                                   p_xffn_in, x_input, D_, D_, 0);

    // ffn norm + router
    rmsnorm_kernel<<<T_, 256>>>(p_xffn_in, ffn_norm_w, p_xffn, p_xf_h, p_xf_l);
    router_kernel<<<T_, 32>>>(p_xffn, main_keys, indices, values, main_bias);
    zero_counts_kernel<<<1, 32>>>();
    scatter_kernel<<<(NSLOT + 255) / 256, 256>>>(indices);

    // routed experts
    gemm_mma<1,0><<<dim3(8, NSLOT / 128, TE_), 256, GEMM_SMEM>>>(
        p_xf_h, p_xf_l, p_w12_h, p_w12_l, p_h12, nullptr, 1024, 1024, (long long)1024 * 1024);
    swiglu_expert_kernel<<<(NSLOT * ED_ + 255) / 256, 256>>>();
    gemm_mma<2,0><<<dim3(8, NSLOT / 128, TE_), 256, GEMM_SMEM>>>(
        p_g_h, p_g_l, p_w3_h, p_w3_l, p_ys, nullptr, 1024, 512, (long long)D_ * ED_);
    combine_kernel<<<T_, 256>>>(output_coeff);

    // shared expert
    gemm_mma<0,0><<<dim3(32, 16), 256, GEMM_SMEM>>>(p_xf_h, p_xf_l, p_uw_h, p_uw_l,
                                                    p_up, nullptr, 2 * DS_, D_, 0);
    swiglu_shared_kernel<<<((size_t)T_ * DS_ + 255) / 256, 256>>>();
    gemm_mma<0,0><<<dim3(8, 16), 256, GEMM_SMEM>>>(p_gs_h, p_gs_l, p_dw_h, p_dw_l,
                                                   p_ysh, nullptr, D_, DS_, 0);

    // final combine
    final_kernel<<<T_, 256>>>(shared_norm_w, out);
}

// round 10
// speedup vs baseline: 11.1138x; 1.1225x over previous
#include <cuda_runtime.h>
#include <cuda_bf16.h>
#include <math.h>
#include <stdint.h>

// ---------------- problem constants ----------------
#define S_   2048
#define D_   1024
#define H_   16
#define HD_  64
#define TE_  16
#define TOPK 2
#define ED_  512
#define DS_  2048
#define T_   2048
#define NSLOT (T_*TOPK)
#define EPS_ 1e-5f

// ---------------- scratch (device bss, no allocation) ----------------
__device__ __align__(256) __nv_bfloat16 d_xn_h[(size_t)T_*D_],     d_xn_l[(size_t)T_*D_];
__device__ __align__(256) __nv_bfloat16 d_aw_h[(size_t)3*D_*D_],   d_aw_l[(size_t)3*D_*D_];
__device__ __align__(256) __nv_bfloat16 d_ow_h[(size_t)D_*D_],     d_ow_l[(size_t)D_*D_];
__device__ __align__(256) __nv_bfloat16 d_ao_h[(size_t)T_*D_],     d_ao_l[(size_t)T_*D_];
__device__ __align__(256) __nv_bfloat16 d_xffn_h[(size_t)T_*D_],   d_xffn_l[(size_t)T_*D_];
__device__ __align__(256) __nv_bfloat16 d_upw_h[(size_t)2*DS_*D_], d_upw_l[(size_t)2*DS_*D_];
__device__ __align__(256) __nv_bfloat16 d_dnw_h[(size_t)D_*DS_],   d_dnw_l[(size_t)D_*DS_];
__device__ __align__(256) __nv_bfloat16 d_w12t_h[(size_t)TE_*2*ED_*D_], d_w12t_l[(size_t)TE_*2*ED_*D_];
__device__ __align__(256) __nv_bfloat16 d_w3_h[(size_t)TE_*D_*ED_],     d_w3_l[(size_t)TE_*D_*ED_];
__device__ __align__(256) __nv_bfloat16 d_g_h[(size_t)NSLOT*ED_],  d_g_l[(size_t)NSLOT*ED_];
__device__ __align__(256) __nv_bfloat16 d_gs_h[(size_t)T_*DS_],    d_gs_l[(size_t)T_*DS_];
__device__ __align__(256) __nv_bfloat16 d_q_h[(size_t)T_*D_], d_q_l[(size_t)T_*D_];
__device__ __align__(256) __nv_bfloat16 d_k_h[(size_t)T_*D_], d_k_l[(size_t)T_*D_];
__device__ __align__(256) __nv_bfloat16 d_v_h[(size_t)T_*D_], d_v_l[(size_t)T_*D_];
__device__ __align__(256) float d_qkv[(size_t)T_*3*D_];
__device__ __align__(256) float d_xffn_in[(size_t)T_*D_];
__device__ __align__(256) float d_xffn[(size_t)T_*D_];
__device__ __align__(256) float d_h12[(size_t)NSLOT*2*ED_];
__device__ __align__(256) float d_ys[(size_t)NSLOT*D_];
__device__ __align__(256) float d_y[(size_t)T_*D_];
__device__ __align__(256) float d_up[(size_t)T_*2*DS_];
__device__ __align__(256) float d_ysh[(size_t)T_*D_];
__device__ float d_scores[NSLOT];
__device__ int   d_counts[TE_];
__device__ int   d_list[TE_*NSLOT];

// ---------------- helpers ----------------
__device__ __forceinline__ void f2hilo(float x, __nv_bfloat16* h, __nv_bfloat16* l) {
    __nv_bfloat16 hh = __float2bfloat16(x);
    *h = hh;
    *l = __float2bfloat16(x - __bfloat162float(hh));
}
__device__ __forceinline__ uint32_t bpack(__nv_bfloat16 a, __nv_bfloat16 b) {
    uint16_t ua = *(uint16_t*)&a, ub = *(uint16_t*)&b;
    return ((uint32_t)ub << 16) | ua;
}
__device__ __forceinline__ uint32_t packh(float x, float y, uint32_t* lo) {
    __nv_bfloat16 hx = __float2bfloat16(x), hy = __float2bfloat16(y);
    __nv_bfloat16 lx = __float2bfloat16(x - __bfloat162float(hx));
    __nv_bfloat16 ly = __float2bfloat16(y - __bfloat162float(hy));
    *lo = bpack(lx, ly);
    return bpack(hx, hy);
}
__device__ __forceinline__ float block_reduce_sum(float v, float* sh) {
    __syncthreads();
    int lane = threadIdx.x & 31, wid = threadIdx.x >> 5;
#pragma unroll
    for (int o = 16; o; o >>= 1) v += __shfl_xor_sync(0xffffffffu, v, o);
    if (lane == 0) sh[wid] = v;
    __syncthreads();
    int nw = blockDim.x >> 5;
    v = (threadIdx.x < nw) ? sh[threadIdx.x] : 0.f;
    if (wid == 0) {
#pragma unroll
        for (int o = 16; o; o >>= 1) v += __shfl_xor_sync(0xffffffffu, v, o);
        if (lane == 0) sh[0] = v;
    }
    __syncthreads();
    return sh[0];
}
__device__ __forceinline__ void mma16816(float* d, const uint32_t* a, const uint32_t* b) {
    asm volatile(
        "mma.sync.aligned.m16n8k16.row.col.f32.bf16.bf16.f32 "
        "{%0,%1,%2,%3}, {%4,%5,%6,%7}, {%8,%9}, {%0,%1,%2,%3};"
        : "+f"(d[0]), "+f"(d[1]), "+f"(d[2]), "+f"(d[3])
        : "r"(a[0]), "r"(a[1]), "r"(a[2]), "r"(a[3]), "r"(b[0]), "r"(b[1]));
}
__device__ __forceinline__ void ldsm_x4(uint32_t* r, uint32_t addr) {
    asm volatile("ldmatrix.sync.aligned.m8n8.x4.shared.b16 {%0,%1,%2,%3}, [%4];"
        : "=r"(r[0]), "=r"(r[1]), "=r"(r[2]), "=r"(r[3]) : "r"(addr));
}
__device__ __forceinline__ void ldsm_x4t(uint32_t* r, uint32_t addr) {
    asm volatile("ldmatrix.sync.aligned.m8n8.x4.trans.shared.b16 {%0,%1,%2,%3}, [%4];"
        : "=r"(r[0]), "=r"(r[1]), "=r"(r[2]), "=r"(r[3]) : "r"(addr));
}
__device__ __forceinline__ void cpa16(uint32_t dst, const void* src, int sb) {
    asm volatile("cp.async.cg.shared.global [%0], [%1], 16, %2;"
                 :: "r"(dst), "l"(src), "r"(sb));
}
__device__ __forceinline__ void cpa_commit() { asm volatile("cp.async.commit_group;"); }
template<int N> __device__ __forceinline__ void cpa_wait() {
    asm volatile("cp.async.wait_group %0;" :: "n"(N));
}

// ---------------- conversion kernels (vectorized) ----------------
__global__ void conv_hilo_kernel(const float4* __restrict__ src, uint2* __restrict__ hi,
                                 uint2* __restrict__ lo, size_t n4) {
    for (size_t i = (size_t)blockIdx.x * blockDim.x + threadIdx.x; i < n4;
         i += (size_t)gridDim.x * blockDim.x) {
        float4 v = src[i];
        __nv_bfloat16 h0, l0, h1, l1, h2, l2, h3, l3;
        f2hilo(v.x, &h0, &l0); f2hilo(v.y, &h1, &l1);
        f2hilo(v.z, &h2, &l2); f2hilo(v.w, &h3, &l3);
        uint2 ho, lw;
        ho.x = bpack(h0, h1); ho.y = bpack(h2, h3);
        lw.x = bpack(l0, l1); lw.y = bpack(l2, l3);
        hi[i] = ho; lo[i] = lw;
    }
}

// experts W1/W2 [m][e][k=D][n=ED] -> w12t [e][n'(=m*512+n)][k] hi/lo (packed stores)
__global__ void transpose_w12_kernel(const float* __restrict__ experts) {
    __shared__ float tile[64][33];
    int e = blockIdx.z;
    int n0 = blockIdx.x * 32, k0 = blockIdx.y * 64;
    int m = n0 >> 9, c0 = n0 & 511;
    for (int kk = threadIdx.y; kk < 64; kk += 8)
        tile[kk][threadIdx.x] =
            experts[((size_t)(m * TE_ + e) * D_ + k0 + kk) * ED_ + c0 + threadIdx.x];
    __syncthreads();
    for (int ny = threadIdx.y; ny < 32; ny += 8) {
        float va = tile[threadIdx.x * 2][ny];
        float vb = tile[threadIdx.x * 2 + 1][ny];
        __nv_bfloat16 ha, la, hb, lb;
        f2hilo(va, &ha, &la); f2hilo(vb, &hb, &lb);
        size_t o = ((size_t)e << 20) + (size_t)(n0 + ny) * 1024 + k0 + threadIdx.x * 2;
        *(uint32_t*)(d_w12t_h + o) = bpack(ha, hb);
        *(uint32_t*)(d_w12t_l + o) = bpack(la, lb);
    }
}

// ---------------- rmsnorm (fp32 optional + hi/lo) ----------------
__global__ void rmsnorm_kernel(const float* __restrict__ x, const float* __restrict__ w,
                               float* __restrict__ outf, __nv_bfloat16* __restrict__ oh,
                               __nv_bfloat16* __restrict__ ol) {
    int row = blockIdx.x;
    const float* xr = x + (size_t)row * D_;
    float ss = 0.f;
    for (int i = threadIdx.x; i < D_; i += blockDim.x) { float v = xr[i]; ss += v * v; }
    __shared__ float sh[32];
    float tot = block_reduce_sum(ss, sh);
    float rinv = rsqrtf(tot / (float)D_ + EPS_);
    for (int i = threadIdx.x; i < D_; i += blockDim.x) {
        float v = xr[i] * rinv * w[i];
        size_t o = (size_t)row * D_ + i;
        if (outf) outf[o] = v;
        f2hilo(v, oh + o, ol + o);
    }
}

// ---------------- warp-MMA split-bf16 GEMM: C[M,N] = A @ B^T ----------------
// CTA tile 128x128, BK=32, 8 warps (2x4), warp tile 64x32, 4-stage cp.async ring,
// ldmatrix fragment loads, one barrier per chunk, depth-2 prefetch.
#define SD    40                   /* smem row stride in bf16 (conflict-free) */
#define STG_E (4*128*SD)           /* bf16 elems per stage (Ah,Al,Bh,Bl) */
#define GEMM_SMEM (4*STG_E*2)      /* bytes */

template<int GATHER, int RES>
__global__ void __launch_bounds__(256, 1) gemm_mma(
    const __nv_bfloat16* __restrict__ Ah, const __nv_bfloat16* __restrict__ Al,
    const __nv_bfloat16* __restrict__ Bh, const __nv_bfloat16* __restrict__ Bl,
    float* __restrict__ C, const float* __restrict__ Res,
    int N, int K, long long bstride)
{
    __shared__ int s_row[128];
    __shared__ int s_out[128];
    int tid = threadIdx.x, wid = tid >> 5, lid = tid & 31;
    if (GATHER) {
        int e = blockIdx.z, cnt = d_counts[e];
        if ((int)blockIdx.y * 128 >= cnt) return;
        if (tid < 128) {
            int r = blockIdx.y * 128 + tid;
            int sl = (r < cnt) ? d_list[e * NSLOT + r] : -1;
            s_out[tid] = sl;
            s_row[tid] = (sl < 0) ? -1 : (GATHER == 1 ? (sl >> 1) : sl);
        }
        Bh += (size_t)blockIdx.z * bstride;
        Bl += (size_t)blockIdx.z * bstride;
    } else if (tid < 128) {
        int r = blockIdx.y * 128 + tid;
        s_row[tid] = r; s_out[tid] = r;
    }
    extern __shared__ __nv_bfloat16 sm[];
    uint32_t smb = (uint32_t)__cvta_generic_to_shared(sm);
    int n0 = blockIdx.x * 128;
    int NC = K >> 5;
    __syncthreads();

    int lrow = tid >> 2, lq = tid & 3;
    int arow0 = s_row[lrow];
    const __nv_bfloat16* asrc_h = Ah + (size_t)(arow0 < 0 ? 0 : arow0) * K + lq * 8;
    const __nv_bfloat16* asrc_l = Al + (size_t)(arow0 < 0 ? 0 : arow0) * K + lq * 8;
    const __nv_bfloat16* bsrc_h = Bh + (size_t)(n0 + lrow) * K + lq * 8;
    const __nv_bfloat16* bsrc_l = Bl + (size_t)(n0 + lrow) * K + lq * 8;
    int asb = (arow0 < 0) ? 0 : 16;
    int arow1 = s_row[lrow + 64];
    const __nv_bfloat16* asrc2_h = Ah + (size_t)(arow1 < 0 ? 0 : arow1) * K + lq * 8;
    const __nv_bfloat16* asrc2_l = Al + (size_t)(arow1 < 0 ? 0 : arow1) * K + lq * 8;
    const __nv_bfloat16* bsrc2_h = Bh + (size_t)(n0 + lrow + 64) * K + lq * 8;
    const __nv_bfloat16* bsrc2_l = Bl + (size_t)(n0 + lrow + 64) * K + lq * 8;
    int asb2 = (arow1 < 0) ? 0 : 16;
    uint32_t o1 = (uint32_t)((lrow * SD + lq * 8) << 1);
    uint32_t o2 = (uint32_t)(((lrow + 64) * SD + lq * 8) << 1);
    const uint32_t OFF_AL = (uint32_t)((128 * SD) << 1);
    const uint32_t OFF_BH = (uint32_t)((2 * 128 * SD) << 1);
    const uint32_t OFF_BL = (uint32_t)((3 * 128 * SD) << 1);

    auto issue = [&](int c, int buf) {
        uint32_t st = smb + (uint32_t)(buf * STG_E * 2);
        int kc = c << 5;
        cpa16(st + o1, asrc_h + kc, asb);
        cpa16(st + OFF_AL + o1, asrc_l + kc, asb);
        cpa16(st + OFF_BH + o1, bsrc_h + kc, 16);
        cpa16(st + OFF_BL + o1, bsrc_l + kc, 16);
        cpa16(st + o2, asrc2_h + kc, asb2);
        cpa16(st + OFF_AL + o2, asrc2_l + kc, asb2);
        cpa16(st + OFF_BH + o2, bsrc2_h + kc, 16);
        cpa16(st + OFF_BL + o2, bsrc2_l + kc, 16);
        cpa_commit();
    };

    int wm = wid & 1, wn = wid >> 1;
    int r = lid >> 2, c2 = (lid & 3) << 1;
    uint32_t a_lane = (uint32_t)(((lid & 15) * SD + ((lid >> 4) << 3)) << 1);
    uint32_t b_lane = (uint32_t)((((((lid >> 4) << 3) + (lid & 7)) * SD) + (((lid >> 3) & 1) << 3)) << 1);
    float acc[4][4][4] = {};

    issue(0, 0);
    if (NC > 1) issue(1, 1);
    if (NC > 2) issue(2, 2);
    for (int c = 0; c < NC; c++) {
        int buf = c & 3;
        if (c + 2 < NC) cpa_wait<2>();
        else if (c + 1 < NC) cpa_wait<1>();
        else cpa_wait<0>();
        __syncthreads();
        uint32_t base = smb + (uint32_t)(buf * STG_E * 2);
#pragma unroll
        for (int ks = 0; ks < 2; ks++) {
            uint32_t kb = (uint32_t)(ks << 5);
            uint32_t ah[4][4], al[4][4];
#pragma unroll
            for (int mt = 0; mt < 4; mt++) {
                uint32_t ab = base + (uint32_t)(((wm * 64 + mt * 16) * SD) << 1) + kb + a_lane;
                ldsm_x4(ah[mt], ab);
                ldsm_x4(al[mt], ab + OFF_AL);
            }
            uint32_t bh[4][2], bl[4][2];
#pragma unroll
            for (int p = 0; p < 2; p++) {
                uint32_t bb = base + OFF_BH
                            + (uint32_t)(((wn * 32 + p * 16) * SD) << 1) + kb + b_lane;
                uint32_t t[4];
                ldsm_x4(t, bb);
                bh[2*p][0] = t[0]; bh[2*p][1] = t[1];
                bh[2*p+1][0] = t[2]; bh[2*p+1][1] = t[3];
                ldsm_x4(t, bb + OFF_AL);
                bl[2*p][0] = t[0]; bl[2*p][1] = t[1];
                bl[2*p+1][0] = t[2]; bl[2*p+1][1] = t[3];
            }
#pragma unroll
            for (int nt = 0; nt < 4; nt++)
#pragma unroll
                for (int mt = 0; mt < 4; mt++) {
                    mma16816(acc[mt][nt], ah[mt], bh[nt]);
                    mma16816(acc[mt][nt], al[mt], bh[nt]);
                    mma16816(acc[mt][nt], ah[mt], bl[nt]);
                }
        }
        if (c + 3 < NC) issue(c + 3, (c + 3) & 3);
    }

    // epilogue (float2 stores)
#pragma unroll
    for (int mt = 0; mt < 4; mt++) {
        int rloc0 = wm * 64 + mt * 16 + r;
#pragma unroll
        for (int half = 0; half < 2; half++) {
            int rloc = rloc0 + half * 8;
            int outr = s_out[rloc];
            if (GATHER && outr < 0) continue;
            float* crow = C + (size_t)outr * N + n0;
#pragma unroll
            for (int nt = 0; nt < 4; nt++) {
                int col = wn * 32 + nt * 8 + c2;
                float v0 = acc[mt][nt][half * 2 + 0];
                float v1 = acc[mt][nt][half * 2 + 1];
                if (RES) {
                    const float* rrow = Res + (size_t)outr * N + n0;
                    v0 += rrow[col]; v1 += rrow[col + 1];
                }
                float2 fv = make_float2(v0, v1);
                *(float2*)(crow + col) = fv;
            }
        }
    }
}

// ---------------- RoPE + convert: qkv fp32 -> q/k/v bf16 hi/lo ----------------
__global__ void rope_conv_kernel(const float* __restrict__ qkv) {
    int s = blockIdx.x, h = blockIdx.y, i = threadIdx.x;  // i in [0,32)
    float inv = powf(10000.0f, -(float)i / 32.0f);
    float fr = (float)s * inv;
    float c = cosf(fr), sn = sinf(fr);
    const float* q = qkv + (size_t)s * 3 * D_ + h * HD_;
    const float* k = q + D_;
    const float* v = q + 2 * D_;
    size_t o = (size_t)s * D_ + h * HD_ + i;
    float q1 = q[i], q2 = q[i + 32];
    f2hilo(q1 * c + q2 * sn,  d_q_h + o,      d_q_l + o);
    f2hilo(-q1 * sn + q2 * c, d_q_h + o + 32, d_q_l + o + 32);
    float k1 = k[i], k2 = k[i + 32];
    f2hilo(k1 * c + k2 * sn,  d_k_h + o,      d_k_l + o);
    f2hilo(-k1 * sn + k2 * c, d_k_h + o + 32, d_k_l + o + 32);
    f2hilo(v[i],      d_v_h + o,      d_v_l + o);
    f2hilo(v[i + 32], d_v_h + o + 32, d_v_l + o + 32);
}

// ---------------- tensor-core flash attention (bf16 inputs, cp.async ring) ----------------
#define ASD 72
#define AMAT (64*ASD)                 /* bf16 elems per matrix */
#define AT2_SMEM ((2 + 12)*AMAT*2)    /* Qh,Ql + 3 stages x (Kh,Kl,Vh,Vl) */
__global__ void __launch_bounds__(128) flash_attn_tc(int dummy) {
    extern __shared__ __nv_bfloat16 asm_[];
    uint32_t bQ = (uint32_t)__cvta_generic_to_shared(asm_);
    const uint32_t OFF1 = (uint32_t)(AMAT << 1);      // bytes per matrix
    int qt = blockIdx.x, h = blockIdx.y;
    int tid = threadIdx.x, wid = tid >> 5, lid = tid & 31;
    int q0 = qt * 64;
    int lrow = tid >> 1, lc0 = (tid & 1) * 32;

    // Q tile load (grouped with stage 0)
    {
        const __nv_bfloat16* qh = d_q_h + (size_t)(q0 + lrow) * D_ + h * HD_ + lc0;
        const __nv_bfloat16* ql = d_q_l + (size_t)(q0 + lrow) * D_ + h * HD_ + lc0;
#pragma unroll
        for (int j = 0; j < 4; j++) {
            uint32_t off = (uint32_t)((lrow * ASD + lc0 + j * 8) << 1);
            cpa16(bQ + off, qh + j * 8, 16);
            cpa16(bQ + OFF1 + off, ql + j * 8, 16);
        }
    }
    auto issueKV = [&](int kt, int s) {
        uint32_t st = bQ + (uint32_t)((2 + 4 * s) * AMAT * 2);
        size_t src = (size_t)(kt * 64 + lrow) * D_ + h * HD_ + lc0;
#pragma unroll
        for (int j = 0; j < 4; j++) {
            uint32_t off = (uint32_t)((lrow * ASD + lc0 + j * 8) << 1);
            cpa16(st + off,            d_k_h + src + j * 8, 16);
            cpa16(st + OFF1 + off,     d_k_l + src + j * 8, 16);
            cpa16(st + 2 * OFF1 + off, d_v_h + src + j * 8, 16);
            cpa16(st + 3 * OFF1 + off, d_v_l + src + j * 8, 16);
        }
        cpa_commit();
    };
    issueKV(0, 0);                    // group 0: Q + stage0
    if (qt >= 1) issueKV(1, 1);       // group 1

    uint32_t a_lane = (uint32_t)(((lid & 15) * ASD + ((lid >> 4) << 3)) << 1);
    uint32_t b_lane = (uint32_t)((((((lid >> 4) << 3) + (lid & 7)) * ASD) + (((lid >> 3) & 1) << 3)) << 1);
    uint32_t v_lane = (uint32_t)((((lid & 7) + (((lid >> 3) & 1) << 3)) * ASD + ((lid >> 4) << 3)) << 1);
    int ra = lid >> 2, c2 = (lid & 3) << 1;
    int rowa = wid * 16 + ra;
    int ga = q0 + rowa, gb = ga + 8;

    float m0 = -1e30f, m1 = -1e30f, l0 = 0.f, l1 = 0.f;
    float O[8][4] = {};

    for (int kt = 0; kt <= qt; kt++) {
        if (kt + 1 <= qt) cpa_wait<1>(); else cpa_wait<0>();
        __syncthreads();
        uint32_t bK = bQ + (uint32_t)((2 + 4 * (kt % 3)) * AMAT * 2);
        uint32_t bV = bK + 2 * OFF1;

        // S = Q K^T (split-bf16, 3 MMAs)
        float S[8][4] = {};
#pragma unroll
        for (int ks = 0; ks < 4; ks++) {
            uint32_t kb = (uint32_t)(ks << 5);
            uint32_t ah[4], al[4];
            uint32_t ab = (uint32_t)(((wid * 16) * ASD) << 1) + kb + a_lane;
            ldsm_x4(ah, bQ + ab);
            ldsm_x4(al, bQ + OFF1 + ab);
#pragma unroll
            for (int p = 0; p < 4; p++) {
                uint32_t bb = (uint32_t)(((p * 16) * ASD) << 1) + kb + b_lane;
                uint32_t th[4], tl[4];
                ldsm_x4(th, bK + bb);
                ldsm_x4(tl, bK + OFF1 + bb);
                uint32_t bh0[2] = {th[0], th[1]}, bh1[2] = {th[2], th[3]};
                uint32_t bl0[2] = {tl[0], tl[1]}, bl1[2] = {tl[2], tl[3]};
                mma16816(S[2*p],   ah, bh0); mma16816(S[2*p],   al, bh0); mma16816(S[2*p],   ah, bl0);
                mma16816(S[2*p+1], ah, bh1); mma16816(S[2*p+1], al, bh1); mma16816(S[2*p+1], ah, bl1);
            }
        }
        // scale + causal mask
        bool diag = (kt == qt);
#pragma unroll
        for (int t = 0; t < 8; t++) {
            int col = kt * 64 + t * 8 + c2;
            S[t][0] *= 0.125f; S[t][1] *= 0.125f; S[t][2] *= 0.125f; S[t][3] *= 0.125f;
            if (diag) {
                if (col     > ga) S[t][0] = -1e30f;
                if (col + 1 > ga) S[t][1] = -1e30f;
                if (col     > gb) S[t][2] = -1e30f;
                if (col + 1 > gb) S[t][3] = -1e30f;
            }
        }
        // online softmax
        float mxa = -1e30f, mxb = -1e30f;
#pragma unroll
        for (int t = 0; t < 8; t++) {
            mxa = fmaxf(mxa, fmaxf(S[t][0], S[t][1]));
            mxb = fmaxf(mxb, fmaxf(S[t][2], S[t][3]));
        }
        mxa = fmaxf(mxa, __shfl_xor_sync(0xffffffffu, mxa, 1));
        mxa = fmaxf(mxa, __shfl_xor_sync(0xffffffffu, mxa, 2));
        mxb = fmaxf(mxb, __shfl_xor_sync(0xffffffffu, mxb, 1));
        mxb = fmaxf(mxb, __shfl_xor_sync(0xffffffffu, mxb, 2));
        float nma = fmaxf(m0, mxa), nmb = fmaxf(m1, mxb);
        float faca = __expf(m0 - nma), facb = __expf(m1 - nmb);
        m0 = nma; m1 = nmb;
        float suma = 0.f, sumb = 0.f;
#pragma unroll
        for (int t = 0; t < 8; t++) {
            S[t][0] = __expf(S[t][0] - nma); suma += S[t][0];
            S[t][1] = __expf(S[t][1] - nma); suma += S[t][1];
            S[t][2] = __expf(S[t][2] - nmb); sumb += S[t][2];
            S[t][3] = __expf(S[t][3] - nmb); sumb += S[t][3];
        }
        suma += __shfl_xor_sync(0xffffffffu, suma, 1);
        suma += __shfl_xor_sync(0xffffffffu, suma, 2);
        sumb += __shfl_xor_sync(0xffffffffu, sumb, 1);
        sumb += __shfl_xor_sync(0xffffffffu, sumb, 2);
        l0 = l0 * faca + suma; l1 = l1 * facb + sumb;
#pragma unroll
        for (int t = 0; t < 8; t++) {
            O[t][0] *= faca; O[t][1] *= faca; O[t][2] *= facb; O[t][3] *= facb;
        }
        // O += P V
#pragma unroll
        for (int ks = 0; ks < 4; ks++) {
            uint32_t ph[4], pl[4];
            ph[0] = packh(S[2*ks][0],   S[2*ks][1],   &pl[0]);
            ph[1] = packh(S[2*ks][2],   S[2*ks][3],   &pl[1]);
            ph[2] = packh(S[2*ks+1][0], S[2*ks+1][1], &pl[2]);
            ph[3] = packh(S[2*ks+1][2], S[2*ks+1][3], &pl[3]);
#pragma unroll
            for (int p = 0; p < 4; p++) {
                uint32_t vb = (uint32_t)(((16 * ks) * ASD + 16 * p) << 1) + v_lane;
                uint32_t th[4], tl[4];
                ldsm_x4t(th, bV + vb);
                ldsm_x4t(tl, bV + OFF1 + vb);
                uint32_t bh0[2] = {th[0], th[1]}, bh1[2] = {th[2], th[3]};
                uint32_t bl0[2] = {tl[0], tl[1]}, bl1[2] = {tl[2], tl[3]};
                mma16816(O[2*p],   ph, bh0); mma16816(O[2*p],   pl, bh0); mma16816(O[2*p],   ph, bl0);
                mma16816(O[2*p+1], ph, bh1); mma16816(O[2*p+1], pl, bh1); mma16816(O[2*p+1], ph, bl1);
            }
        }
        if (kt + 2 <= qt) issueKV(kt + 2, (kt + 2) % 3);
    }
    // epilogue: normalize + hi/lo store
    float il0 = 1.0f / l0, il1 = 1.0f / l1;
#pragma unroll
    for (int t = 0; t < 8; t++) {
        int col = h * HD_ + t * 8 + c2;
        size_t r0 = (size_t)ga * D_ + col;
        size_t r1 = (size_t)gb * D_ + col;
        f2hilo(O[t][0] * il0, d_ao_h + r0,     d_ao_l + r0);
        f2hilo(O[t][1] * il0, d_ao_h + r0 + 1, d_ao_l + r0 + 1);
        f2hilo(O[t][2] * il1, d_ao_h + r1,     d_ao_l + r1);
        f2hilo(O[t][3] * il1, d_ao_h + r1 + 1, d_ao_l + r1 + 1);
    }
}

// ---------------- router ----------------
__global__ void router_kernel(const float* __restrict__ xffn, const float* __restrict__ keys,
                              const int* __restrict__ idx, const float* __restrict__ vals,
                              const float* __restrict__ bias) {
    int t = blockIdx.x, lane = threadIdx.x;
    int e0 = idx[t * 2], e1 = idx[t * 2 + 1];
    const float* xr = xffn + (size_t)t * D_;
    float s0 = 0.f, s1 = 0.f;
    for (int d = lane; d < D_; d += 32) {
        float x = xr[d];
        s0 += x * keys[d * TE_ + e0];
        s1 += x * keys[d * TE_ + e1];
    }
#pragma unroll
    for (int o = 16; o; o >>= 1) {
        s0 += __shfl_xor_sync(0xffffffffu, s0, o);
        s1 += __shfl_xor_sync(0xffffffffu, s1, o);
    }
    if (lane == 0) {
        float v0 = vals[t * 2] + s0 + bias[e0];
        float v1 = vals[t * 2 + 1] + s1 + bias[e1];
        float mm = fmaxf(v0, v1);
        float a = expf(v0 - mm), b = expf(v1 - mm);
        float inv = 1.0f / (a + b);
        d_scores[t * 2] = a * inv;
        d_scores[t * 2 + 1] = b * inv;
    }
}

__global__ void zero_counts_kernel() {
    if (threadIdx.x < TE_) d_counts[threadIdx.x] = 0;
}
__global__ void scatter_kernel(const int* __restrict__ idx) {
    int slot = blockIdx.x * blockDim.x + threadIdx.x;
    if (slot < NSLOT) {
        int e = idx[slot];
        int p = atomicAdd(&d_counts[e], 1);
        d_list[e * NSLOT + p] = slot;
    }
}

// ---------------- swiglu (experts): h12 -> g hi/lo ----------------
__global__ void swiglu_expert_kernel() {
    int i = blockIdx.x * 256 + threadIdx.x;
    if (i < NSLOT * ED_) {
        int sl = i >> 9, j = i & 511;
        float a = d_h12[(size_t)sl * 1024 + j];
        float b = d_h12[(size_t)sl * 1024 + 512 + j];
        float g = (a / (1.f + __expf(-a))) * b;
        f2hilo(g, d_g_h + (size_t)sl * ED_ + j, d_g_l + (size_t)sl * ED_ + j);
    }
}

// ---------------- shared swiglu: up -> gs hi/lo ----------------
__global__ void swiglu_shared_kernel() {
    size_t i = (size_t)blockIdx.x * 256 + threadIdx.x;
    if (i < (size_t)T_ * DS_) {
        size_t t = i / DS_, j = i % DS_;
        float a = d_up[t * 2 * DS_ + j];
        float b = d_up[t * 2 * DS_ + DS_ + j];
        float g = (a / (1.f + __expf(-a))) * b;
        f2hilo(g, d_gs_h + i, d_gs_l + i);
    }
}

// ---------------- combine routed outputs ----------------
__global__ void combine_kernel(const float* __restrict__ coeff) {
    int t = blockIdx.x, tid = threadIdx.x;
    float s0 = d_scores[t * 2], s1 = d_scores[t * 2 + 1];
    const float* y0 = d_ys + (size_t)(t * 2) * D_;
    const float* y1 = d_ys + (size_t)(t * 2 + 1) * D_;
    float* yo = d_y + (size_t)t * D_;
    for (int dd = tid; dd < D_; dd += 256)
        yo[dd] = (s0 * y0[dd] + s1 * y1[dd]) * coeff[dd];
}

// ---------------- final combine ----------------
__global__ void final_kernel(const float* __restrict__ sharedw, float* __restrict__ out) {
    int t = blockIdx.x;
    const float* ysh = d_ysh + (size_t)t * D_;
    float ss = 0.f;
    for (int i = threadIdx.x; i < D_; i += blockDim.x) { float v = ysh[i]; ss += v * v; }
    __shared__ float sh[32];
    float tot = block_reduce_sum(ss, sh);
    float rinv = rsqrtf(tot / (float)D_ + EPS_);
    const float* yr = d_y + (size_t)t * D_;
    const float* xr = d_xffn_in + (size_t)t * D_;
    float* o = out + (size_t)t * D_;
    for (int i = threadIdx.x; i < D_; i += blockDim.x)
        o[i] = yr[i] + ysh[i] * rinv * sharedw[i] + xr[i];
}

// ---------------- host launch ----------------
static void* sym(const void* s) { void* p = nullptr; cudaGetSymbolAddress(&p, s); return p; }

// streams/events created ONCE on the first call (the uncaptured correctness run),
// reused on every call — no resource creation during graph capture, so the
// post-teardown memory baseline is unchanged. Work per call is identical.
static cudaStream_t g_sA = nullptr, g_sB = nullptr;
static cudaEvent_t  g_evF, g_evAW, g_evOW, g_evWTS, g_evX, g_evB;
static bool g_init = false;

extern "C" void kernel_launch(void* const* d_in, const int* in_sizes, int n_in,
                              void* d_out, int out_size) {
    const float* x_input      = (const float*)d_in[0];
    const int*   indices      = (const int*)  d_in[1];
    const float* values       = (const float*)d_in[2];
    const float* attn_w       = (const float*)d_in[3];
    const float* attn_o_w     = (const float*)d_in[4];
    const float* attn_norm_w  = (const float*)d_in[5];
    const float* ffn_norm_w   = (const float*)d_in[6];
    const float* ffn_experts  = (const float*)d_in[7];
    const float* main_keys    = (const float*)d_in[8];
    const float* main_bias    = (const float*)d_in[9];
    const float* output_coeff = (const float*)d_in[10];
    const float* ffn_up_w     = (const float*)d_in[11];
    const float* ffn_down_w   = (const float*)d_in[12];
    const float* shared_norm_w= (const float*)d_in[13];
    float* out = (float*)d_out;

    if (!g_init) {
        g_init = true;
        cudaStreamCreateWithFlags(&g_sA, cudaStreamNonBlocking);
        cudaStreamCreateWithFlags(&g_sB, cudaStreamNonBlocking);
        cudaEventCreateWithFlags(&g_evF,   cudaEventDisableTiming);
        cudaEventCreateWithFlags(&g_evAW,  cudaEventDisableTiming);
        cudaEventCreateWithFlags(&g_evOW,  cudaEventDisableTiming);
        cudaEventCreateWithFlags(&g_evWTS, cudaEventDisableTiming);
        cudaEventCreateWithFlags(&g_evX,   cudaEventDisableTiming);
        cudaEventCreateWithFlags(&g_evB,   cudaEventDisableTiming);
        cudaFuncSetAttribute((const void*)gemm_mma<0,0>, cudaFuncAttributeMaxDynamicSharedMemorySize, GEMM_SMEM);
        cudaFuncSetAttribute((const void*)gemm_mma<0,1>, cudaFuncAttributeMaxDynamicSharedMemorySize, GEMM_SMEM);
        cudaFuncSetAttribute((const void*)gemm_mma<1,0>, cudaFuncAttributeMaxDynamicSharedMemorySize, GEMM_SMEM);
        cudaFuncSetAttribute((const void*)gemm_mma<2,0>, cudaFuncAttributeMaxDynamicSharedMemorySize, GEMM_SMEM);
        cudaFuncSetAttribute((const void*)flash_attn_tc, cudaFuncAttributeMaxDynamicSharedMemorySize, AT2_SMEM);
    }
    cudaStream_t sA = g_sA, sB = g_sB;
    cudaEvent_t evF = g_evF, evAW = g_evAW, evOW = g_evOW, evWTS = g_evWTS, evX = g_evX, evB = g_evB;

    __nv_bfloat16 *p_xn_h=(__nv_bfloat16*)sym(d_xn_h), *p_xn_l=(__nv_bfloat16*)sym(d_xn_l);
    __nv_bfloat16 *p_aw_h=(__nv_bfloat16*)sym(d_aw_h), *p_aw_l=(__nv_bfloat16*)sym(d_aw_l);
    __nv_bfloat16 *p_ow_h=(__nv_bfloat16*)sym(d_ow_h), *p_ow_l=(__nv_bfloat16*)sym(d_ow_l);
    __nv_bfloat16 *p_ao_h=(__nv_bfloat16*)sym(d_ao_h), *p_ao_l=(__nv_bfloat16*)sym(d_ao_l);
    __nv_bfloat16 *p_xf_h=(__nv_bfloat16*)sym(d_xffn_h), *p_xf_l=(__nv_bfloat16*)sym(d_xffn_l);
    __nv_bfloat16 *p_uw_h=(__nv_bfloat16*)sym(d_upw_h), *p_uw_l=(__nv_bfloat16*)sym(d_upw_l);
    __nv_bfloat16 *p_dw_h=(__nv_bfloat16*)sym(d_dnw_h), *p_dw_l=(__nv_bfloat16*)sym(d_dnw_l);
    __nv_bfloat16 *p_w12_h=(__nv_bfloat16*)sym(d_w12t_h), *p_w12_l=(__nv_bfloat16*)sym(d_w12t_l);
    __nv_bfloat16 *p_w3_h=(__nv_bfloat16*)sym(d_w3_h), *p_w3_l=(__nv_bfloat16*)sym(d_w3_l);
    __nv_bfloat16 *p_g_h=(__nv_bfloat16*)sym(d_g_h), *p_g_l=(__nv_bfloat16*)sym(d_g_l);
    __nv_bfloat16 *p_gs_h=(__nv_bfloat16*)sym(d_gs_h), *p_gs_l=(__nv_bfloat16*)sym(d_gs_l);
    float *p_qkv=(float*)sym(d_qkv), *p_xffn_in=(float*)sym(d_xffn_in), *p_xffn=(float*)sym(d_xffn);
    float *p_h12=(float*)sym(d_h12), *p_ys=(float*)sym(d_ys), *p_up=(float*)sym(d_up);
    float *p_ysh=(float*)sym(d_ysh);

    // fork conversions onto sA
    cudaEventRecord(evF, 0);
    cudaStreamWaitEvent(sA, evF, 0);
    conv_hilo_kernel<<<2048, 256, 0, sA>>>((const float4*)attn_w, (uint2*)p_aw_h, (uint2*)p_aw_l,
                                           (size_t)3 * D_ * D_ / 4);
    cudaEventRecord(evAW, sA);
    conv_hilo_kernel<<<1024, 256, 0, sA>>>((const float4*)attn_o_w, (uint2*)p_ow_h, (uint2*)p_ow_l,
                                           (size_t)D_ * D_ / 4);
    cudaEventRecord(evOW, sA);
    conv_hilo_kernel<<<2048, 256, 0, sA>>>((const float4*)ffn_up_w, (uint2*)p_uw_h, (uint2*)p_uw_l,
                                           (size_t)2 * DS_ * D_ / 4);
    conv_hilo_kernel<<<2048, 256, 0, sA>>>((const float4*)ffn_down_w, (uint2*)p_dw_h, (uint2*)p_dw_l,
                                           (size_t)D_ * DS_ / 4);
    conv_hilo_kernel<<<4096, 256, 0, sA>>>((const float4*)(ffn_experts + (size_t)2 * TE_ * D_ * ED_),
                                           (uint2*)p_w3_h, (uint2*)p_w3_l, (size_t)TE_ * D_ * ED_ / 4);
    transpose_w12_kernel<<<dim3(32, 16, 16), dim3(32, 8), 0, sA>>>(ffn_experts);
    cudaEventRecord(evWTS, sA);

    // attention block on stream 0 (overlaps conversions)
    rmsnorm_kernel<<<T_, 256>>>(x_input, attn_norm_w, nullptr, p_xn_h, p_xn_l);
    cudaStreamWaitEvent(0, evAW, 0);
    gemm_mma<0,0><<<dim3(24, 16), 256, GEMM_SMEM>>>(p_xn_h, p_xn_l, p_aw_h, p_aw_l,
                                                    p_qkv, nullptr, 3 * D_, D_, 0);
    rope_conv_kernel<<<dim3(S_, H_), 32>>>(p_qkv);
    flash_attn_tc<<<dim3(S_ / 64, H_), 128, AT2_SMEM>>>(0);
    cudaStreamWaitEvent(0, evOW, 0);
    gemm_mma<0,1><<<dim3(8, 16), 256, GEMM_SMEM>>>(p_ao_h, p_ao_l, p_ow_h, p_ow_l,
                                                   p_xffn_in, x_input, D_, D_, 0);

    // ffn norm, then fork expert branch to sB
    rmsnorm_kernel<<<T_, 256>>>(p_xffn_in, ffn_norm_w, p_xffn, p_xf_h, p_xf_l);
    cudaStreamWaitEvent(0, evWTS, 0);
    cudaEventRecord(evX, 0);
    cudaStreamWaitEvent(sB, evX, 0);

    // sB: routed-expert chain
    router_kernel<<<T_, 32, 0, sB>>>(p_xffn, main_keys, indices, values, main_bias);
    zero_counts_kernel<<<1, 32, 0, sB>>>();
    scatter_kernel<<<(NSLOT + 255) / 256, 256, 0, sB>>>(indices);
    gemm_mma<1,0><<<dim3(8, NSLOT / 128, TE_), 256, GEMM_SMEM, sB>>>(
        p_xf_h, p_xf_l, p_w12_h, p_w12_l, p_h12, nullptr, 1024, 1024, (long long)1024 * 1024);
    swiglu_expert_kernel<<<(NSLOT * ED_ + 255) / 256, 256, 0, sB>>>();
    gemm_mma<2,0><<<dim3(8, NSLOT / 128, TE_), 256, GEMM_SMEM, sB>>>(
        p_g_h, p_g_l, p_w3_h, p_w3_l, p_ys, nullptr, 1024, 512, (long long)D_ * ED_);
    combine_kernel<<<T_, 256, 0, sB>>>(output_coeff);
    cudaEventRecord(evB, sB);

    // stream 0: shared-expert chain (concurrent with sB)
    gemm_mma<0,0><<<dim3(32, 16), 256, GEMM_SMEM>>>(p_xf_h, p_xf_l, p_uw_h, p_uw_l,
                                                    p_up, nullptr, 2 * DS_, D_, 0);
    swiglu_shared_kernel<<<((size_t)T_ * DS_ + 255) / 256, 256>>>();
    gemm_mma<0,0><<<dim3(8, 16), 256, GEMM_SMEM>>>(p_gs_h, p_gs_l, p_dw_h, p_dw_l,
                                                   p_ysh, nullptr, D_, DS_, 0);

    // join and final combine
    cudaStreamWaitEvent(0, evB, 0);
    final_kernel<<<T_, 256>>>(shared_norm_w, out);
}

// round 12
// speedup vs baseline: 11.6823x; 1.0511x over previous
#include <cuda_runtime.h>
#include <cuda_bf16.h>
#include <math.h>
#include <stdint.h>

// ---------------- problem constants ----------------
#define S_   2048
#define D_   1024
#define H_   16
#define HD_  64
#define TE_  16
#define TOPK 2
#define ED_  512
#define DS_  2048
#define T_   2048
#define NSLOT (T_*TOPK)
#define EPS_ 1e-5f

// ---------------- scratch (device bss, no allocation) ----------------
__device__ __align__(256) __nv_bfloat16 d_xn_h[(size_t)T_*D_],     d_xn_l[(size_t)T_*D_];
__device__ __align__(256) __nv_bfloat16 d_aw_h[(size_t)3*D_*D_],   d_aw_l[(size_t)3*D_*D_];
__device__ __align__(256) __nv_bfloat16 d_ow_h[(size_t)D_*D_],     d_ow_l[(size_t)D_*D_];
__device__ __align__(256) __nv_bfloat16 d_ao_h[(size_t)T_*D_],     d_ao_l[(size_t)T_*D_];
__device__ __align__(256) __nv_bfloat16 d_xffn_h[(size_t)T_*D_],   d_xffn_l[(size_t)T_*D_];
__device__ __align__(256) __nv_bfloat16 d_upw_h[(size_t)2*DS_*D_], d_upw_l[(size_t)2*DS_*D_];  // interleaved
__device__ __align__(256) __nv_bfloat16 d_dnw_h[(size_t)D_*DS_],   d_dnw_l[(size_t)D_*DS_];
__device__ __align__(256) __nv_bfloat16 d_w12t_h[(size_t)TE_*2*ED_*D_], d_w12t_l[(size_t)TE_*2*ED_*D_]; // interleaved
__device__ __align__(256) __nv_bfloat16 d_w3_h[(size_t)TE_*D_*ED_],     d_w3_l[(size_t)TE_*D_*ED_];
__device__ __align__(256) __nv_bfloat16 d_g_h[(size_t)NSLOT*ED_],  d_g_l[(size_t)NSLOT*ED_];
__device__ __align__(256) __nv_bfloat16 d_gs_h[(size_t)T_*DS_],    d_gs_l[(size_t)T_*DS_];
__device__ __align__(256) __nv_bfloat16 d_q_h[(size_t)T_*D_], d_q_l[(size_t)T_*D_];
__device__ __align__(256) __nv_bfloat16 d_k_h[(size_t)T_*D_], d_k_l[(size_t)T_*D_];
__device__ __align__(256) __nv_bfloat16 d_v_h[(size_t)T_*D_], d_v_l[(size_t)T_*D_];
__device__ __align__(256) float d_qkv[(size_t)T_*3*D_];
__device__ __align__(256) float d_xffn_in[(size_t)T_*D_];
__device__ __align__(256) float d_xffn[(size_t)T_*D_];
__device__ __align__(256) float d_ys[(size_t)NSLOT*D_];
__device__ __align__(256) float d_y[(size_t)T_*D_];
__device__ __align__(256) float d_ysh[(size_t)T_*D_];
__device__ float d_scores[NSLOT];
__device__ int   d_counts[TE_];
__device__ int   d_list[TE_*NSLOT];

// ---------------- helpers ----------------
__device__ __forceinline__ void f2hilo(float x, __nv_bfloat16* h, __nv_bfloat16* l) {
    __nv_bfloat16 hh = __float2bfloat16(x);
    *h = hh;
    *l = __float2bfloat16(x - __bfloat162float(hh));
}
__device__ __forceinline__ uint32_t bpack(__nv_bfloat16 a, __nv_bfloat16 b) {
    uint16_t ua = *(uint16_t*)&a, ub = *(uint16_t*)&b;
    return ((uint32_t)ub << 16) | ua;
}
__device__ __forceinline__ uint32_t packh(float x, float y, uint32_t* lo) {
    __nv_bfloat16 hx = __float2bfloat16(x), hy = __float2bfloat16(y);
    __nv_bfloat16 lx = __float2bfloat16(x - __bfloat162float(hx));
    __nv_bfloat16 ly = __float2bfloat16(y - __bfloat162float(hy));
    *lo = bpack(lx, ly);
    return bpack(hx, hy);
}
__device__ __forceinline__ float block_reduce_sum(float v, float* sh) {
    __syncthreads();
    int lane = threadIdx.x & 31, wid = threadIdx.x >> 5;
#pragma unroll
    for (int o = 16; o; o >>= 1) v += __shfl_xor_sync(0xffffffffu, v, o);
    if (lane == 0) sh[wid] = v;
    __syncthreads();
    int nw = blockDim.x >> 5;
    v = (threadIdx.x < nw) ? sh[threadIdx.x] : 0.f;
    if (wid == 0) {
#pragma unroll
        for (int o = 16; o; o >>= 1) v += __shfl_xor_sync(0xffffffffu, v, o);
        if (lane == 0) sh[0] = v;
    }
    __syncthreads();
    return sh[0];
}
__device__ __forceinline__ void mma16816(float* d, const uint32_t* a, const uint32_t* b) {
    asm volatile(
        "mma.sync.aligned.m16n8k16.row.col.f32.bf16.bf16.f32 "
        "{%0,%1,%2,%3}, {%4,%5,%6,%7}, {%8,%9}, {%0,%1,%2,%3};"
        : "+f"(d[0]), "+f"(d[1]), "+f"(d[2]), "+f"(d[3])
        : "r"(a[0]), "r"(a[1]), "r"(a[2]), "r"(a[3]), "r"(b[0]), "r"(b[1]));
}
__device__ __forceinline__ void ldsm_x4(uint32_t* r, uint32_t addr) {
    asm volatile("ldmatrix.sync.aligned.m8n8.x4.shared.b16 {%0,%1,%2,%3}, [%4];"
        : "=r"(r[0]), "=r"(r[1]), "=r"(r[2]), "=r"(r[3]) : "r"(addr));
}
__device__ __forceinline__ void ldsm_x4t(uint32_t* r, uint32_t addr) {
    asm volatile("ldmatrix.sync.aligned.m8n8.x4.trans.shared.b16 {%0,%1,%2,%3}, [%4];"
        : "=r"(r[0]), "=r"(r[1]), "=r"(r[2]), "=r"(r[3]) : "r"(addr));
}
__device__ __forceinline__ void cpa16(uint32_t dst, const void* src, int sb) {
    asm volatile("cp.async.cg.shared.global [%0], [%1], 16, %2;"
                 :: "r"(dst), "l"(src), "r"(sb));
}
__device__ __forceinline__ void cpa_commit() { asm volatile("cp.async.commit_group;"); }
template<int N> __device__ __forceinline__ void cpa_wait() {
    asm volatile("cp.async.wait_group %0;" :: "n"(N));
}

// ---------------- conversion kernels (vectorized) ----------------
__global__ void conv_hilo_kernel(const float4* __restrict__ src, uint2* __restrict__ hi,
                                 uint2* __restrict__ lo, size_t n4) {
    for (size_t i = (size_t)blockIdx.x * blockDim.x + threadIdx.x; i < n4;
         i += (size_t)gridDim.x * blockDim.x) {
        float4 v = src[i];
        __nv_bfloat16 h0, l0, h1, l1, h2, l2, h3, l3;
        f2hilo(v.x, &h0, &l0); f2hilo(v.y, &h1, &l1);
        f2hilo(v.z, &h2, &l2); f2hilo(v.w, &h3, &l3);
        uint2 ho, lw;
        ho.x = bpack(h0, h1); ho.y = bpack(h2, h3);
        lw.x = bpack(l0, l1); lw.y = bpack(l2, l3);
        hi[i] = ho; lo[i] = lw;
    }
}

// interleave ffn_up rows: dest row 2j = src row j (W1), dest row 2j+1 = src row DS+j (W2)
__global__ void conv_hilo_ilv_kernel(const float4* __restrict__ src, uint2* __restrict__ hi,
                                     uint2* __restrict__ lo) {
    size_t n4 = (size_t)2 * DS_ * D_ / 4;
    size_t rowq = D_ / 4;
    for (size_t i = (size_t)blockIdx.x * blockDim.x + threadIdx.x; i < n4;
         i += (size_t)gridDim.x * blockDim.x) {
        size_t r = i / rowq, c = i % rowq;
        size_t sr = (r & 1) ? ((size_t)DS_ + (r >> 1)) : (r >> 1);
        float4 v = src[sr * rowq + c];
        __nv_bfloat16 h0, l0, h1, l1, h2, l2, h3, l3;
        f2hilo(v.x, &h0, &l0); f2hilo(v.y, &h1, &l1);
        f2hilo(v.z, &h2, &l2); f2hilo(v.w, &h3, &l3);
        uint2 ho, lw;
        ho.x = bpack(h0, h1); ho.y = bpack(h2, h3);
        lw.x = bpack(l0, l1); lw.y = bpack(l2, l3);
        hi[i] = ho; lo[i] = lw;
    }
}

// experts W1/W2 [m][e][k=D][n=ED] -> w12t [e][2n+m][k] hi/lo (interleaved for swiglu epi)
__global__ void transpose_w12_kernel(const float* __restrict__ experts) {
    __shared__ float tile[64][33];
    int e = blockIdx.z;
    int n0 = blockIdx.x * 32, k0 = blockIdx.y * 64;
    int m = n0 >> 9, c0 = n0 & 511;
    for (int kk = threadIdx.y; kk < 64; kk += 8)
        tile[kk][threadIdx.x] =
            experts[((size_t)(m * TE_ + e) * D_ + k0 + kk) * ED_ + c0 + threadIdx.x];
    __syncthreads();
    for (int ny = threadIdx.y; ny < 32; ny += 8) {
        int ng = n0 + ny;
        int mm = ng >> 9, cc = ng & 511;
        int rr = 2 * cc + mm;
        float va = tile[threadIdx.x * 2][ny];
        float vb = tile[threadIdx.x * 2 + 1][ny];
        __nv_bfloat16 ha, la, hb, lb;
        f2hilo(va, &ha, &la); f2hilo(vb, &hb, &lb);
        size_t o = ((size_t)e << 20) + (size_t)rr * 1024 + k0 + threadIdx.x * 2;
        *(uint32_t*)(d_w12t_h + o) = bpack(ha, hb);
        *(uint32_t*)(d_w12t_l + o) = bpack(la, lb);
    }
}

// ---------------- rmsnorm (fp32 optional + hi/lo) ----------------
__global__ void rmsnorm_kernel(const float* __restrict__ x, const float* __restrict__ w,
                               float* __restrict__ outf, __nv_bfloat16* __restrict__ oh,
                               __nv_bfloat16* __restrict__ ol) {
    int row = blockIdx.x;
    const float* xr = x + (size_t)row * D_;
    float ss = 0.f;
    for (int i = threadIdx.x; i < D_; i += blockDim.x) { float v = xr[i]; ss += v * v; }
    __shared__ float sh[32];
    float tot = block_reduce_sum(ss, sh);
    float rinv = rsqrtf(tot / (float)D_ + EPS_);
    for (int i = threadIdx.x; i < D_; i += blockDim.x) {
        float v = xr[i] * rinv * w[i];
        size_t o = (size_t)row * D_ + i;
        if (outf) outf[o] = v;
        f2hilo(v, oh + o, ol + o);
    }
}

// ---------------- warp-MMA split-bf16 GEMM: C[M,N] = A @ B^T ----------------
// EPI: 0 = plain fp32 C, 1 = fp32 C + residual, 2 = swiglu pair -> bf16 hi/lo (C=Gh, Res=Gl)
#define SD    40
#define STG_E (4*128*SD)
#define GEMM_SMEM (4*STG_E*2)

template<int GATHER, int EPI>
__global__ void __launch_bounds__(256, 1) gemm_mma(
    const __nv_bfloat16* __restrict__ Ah, const __nv_bfloat16* __restrict__ Al,
    const __nv_bfloat16* __restrict__ Bh, const __nv_bfloat16* __restrict__ Bl,
    float* __restrict__ C, const float* __restrict__ Res,
    int N, int K, long long bstride)
{
    __shared__ int s_row[128];
    __shared__ int s_out[128];
    int tid = threadIdx.x, wid = tid >> 5, lid = tid & 31;
    if (GATHER) {
        int e = blockIdx.z, cnt = d_counts[e];
        if ((int)blockIdx.y * 128 >= cnt) return;
        if (tid < 128) {
            int r = blockIdx.y * 128 + tid;
            int sl = (r < cnt) ? d_list[e * NSLOT + r] : -1;
            s_out[tid] = sl;
            s_row[tid] = (sl < 0) ? -1 : (GATHER == 1 ? (sl >> 1) : sl);
        }
        Bh += (size_t)blockIdx.z * bstride;
        Bl += (size_t)blockIdx.z * bstride;
    } else if (tid < 128) {
        int r = blockIdx.y * 128 + tid;
        s_row[tid] = r; s_out[tid] = r;
    }
    extern __shared__ __nv_bfloat16 sm[];
    uint32_t smb = (uint32_t)__cvta_generic_to_shared(sm);
    int n0 = blockIdx.x * 128;
    int NC = K >> 5;
    __syncthreads();

    int lrow = tid >> 2, lq = tid & 3;
    int arow0 = s_row[lrow];
    const __nv_bfloat16* asrc_h = Ah + (size_t)(arow0 < 0 ? 0 : arow0) * K + lq * 8;
    const __nv_bfloat16* asrc_l = Al + (size_t)(arow0 < 0 ? 0 : arow0) * K + lq * 8;
    const __nv_bfloat16* bsrc_h = Bh + (size_t)(n0 + lrow) * K + lq * 8;
    const __nv_bfloat16* bsrc_l = Bl + (size_t)(n0 + lrow) * K + lq * 8;
    int asb = (arow0 < 0) ? 0 : 16;
    int arow1 = s_row[lrow + 64];
    const __nv_bfloat16* asrc2_h = Ah + (size_t)(arow1 < 0 ? 0 : arow1) * K + lq * 8;
    const __nv_bfloat16* asrc2_l = Al + (size_t)(arow1 < 0 ? 0 : arow1) * K + lq * 8;
    const __nv_bfloat16* bsrc2_h = Bh + (size_t)(n0 + lrow + 64) * K + lq * 8;
    const __nv_bfloat16* bsrc2_l = Bl + (size_t)(n0 + lrow + 64) * K + lq * 8;
    int asb2 = (arow1 < 0) ? 0 : 16;
    uint32_t o1 = (uint32_t)((lrow * SD + lq * 8) << 1);
    uint32_t o2 = (uint32_t)(((lrow + 64) * SD + lq * 8) << 1);
    const uint32_t OFF_AL = (uint32_t)((128 * SD) << 1);
    const uint32_t OFF_BH = (uint32_t)((2 * 128 * SD) << 1);
    const uint32_t OFF_BL = (uint32_t)((3 * 128 * SD) << 1);

    auto issue = [&](int c, int buf) {
        uint32_t st = smb + (uint32_t)(buf * STG_E * 2);
        int kc = c << 5;
        cpa16(st + o1, asrc_h + kc, asb);
        cpa16(st + OFF_AL + o1, asrc_l + kc, asb);
        cpa16(st + OFF_BH + o1, bsrc_h + kc, 16);
        cpa16(st + OFF_BL + o1, bsrc_l + kc, 16);
        cpa16(st + o2, asrc2_h + kc, asb2);
        cpa16(st + OFF_AL + o2, asrc2_l + kc, asb2);
        cpa16(st + OFF_BH + o2, bsrc2_h + kc, 16);
        cpa16(st + OFF_BL + o2, bsrc2_l + kc, 16);
        cpa_commit();
    };

    int wm = wid & 1, wn = wid >> 1;
    int r = lid >> 2, c2 = (lid & 3) << 1;
    uint32_t a_lane = (uint32_t)(((lid & 15) * SD + ((lid >> 4) << 3)) << 1);
    uint32_t b_lane = (uint32_t)((((((lid >> 4) << 3) + (lid & 7)) * SD) + (((lid >> 3) & 1) << 3)) << 1);
    float acc[4][4][4] = {};

    issue(0, 0);
    if (NC > 1) issue(1, 1);
    if (NC > 2) issue(2, 2);
    for (int c = 0; c < NC; c++) {
        int buf = c & 3;
        if (c + 2 < NC) cpa_wait<2>();
        else if (c + 1 < NC) cpa_wait<1>();
        else cpa_wait<0>();
        __syncthreads();
        uint32_t base = smb + (uint32_t)(buf * STG_E * 2);
#pragma unroll
        for (int ks = 0; ks < 2; ks++) {
            uint32_t kb = (uint32_t)(ks << 5);
            uint32_t ah[4][4], al[4][4];
#pragma unroll
            for (int mt = 0; mt < 4; mt++) {
                uint32_t ab = base + (uint32_t)(((wm * 64 + mt * 16) * SD) << 1) + kb + a_lane;
                ldsm_x4(ah[mt], ab);
                ldsm_x4(al[mt], ab + OFF_AL);
            }
            uint32_t bh[4][2], bl[4][2];
#pragma unroll
            for (int p = 0; p < 2; p++) {
                uint32_t bb = base + OFF_BH
                            + (uint32_t)(((wn * 32 + p * 16) * SD) << 1) + kb + b_lane;
                uint32_t t[4];
                ldsm_x4(t, bb);
                bh[2*p][0] = t[0]; bh[2*p][1] = t[1];
                bh[2*p+1][0] = t[2]; bh[2*p+1][1] = t[3];
                ldsm_x4(t, bb + OFF_AL);
                bl[2*p][0] = t[0]; bl[2*p][1] = t[1];
                bl[2*p+1][0] = t[2]; bl[2*p+1][1] = t[3];
            }
#pragma unroll
            for (int nt = 0; nt < 4; nt++)
#pragma unroll
                for (int mt = 0; mt < 4; mt++) {
                    mma16816(acc[mt][nt], ah[mt], bh[nt]);
                    mma16816(acc[mt][nt], al[mt], bh[nt]);
                    mma16816(acc[mt][nt], ah[mt], bl[nt]);
                }
        }
        if (c + 3 < NC) issue(c + 3, (c + 3) & 3);
    }

    // epilogue
#pragma unroll
    for (int mt = 0; mt < 4; mt++) {
        int rloc0 = wm * 64 + mt * 16 + r;
#pragma unroll
        for (int half = 0; half < 2; half++) {
            int rloc = rloc0 + half * 8;
            int outr = s_out[rloc];
            if (GATHER && outr < 0) continue;
            if (EPI == 2) {
                __nv_bfloat16* Gh = (__nv_bfloat16*)C;
                __nv_bfloat16* Gl = (__nv_bfloat16*)(void*)Res;
                int hn = N >> 1;
#pragma unroll
                for (int nt = 0; nt < 4; nt++) {
                    int col = wn * 32 + nt * 8 + c2;
                    float v0 = acc[mt][nt][half * 2 + 0];
                    float v1 = acc[mt][nt][half * 2 + 1];
                    float g = (v0 / (1.f + __expf(-v0))) * v1;
                    size_t oo = (size_t)outr * hn + ((n0 + col) >> 1);
                    f2hilo(g, Gh + oo, Gl + oo);
                }
            } else {
                float* crow = C + (size_t)outr * N + n0;
#pragma unroll
                for (int nt = 0; nt < 4; nt++) {
                    int col = wn * 32 + nt * 8 + c2;
                    float v0 = acc[mt][nt][half * 2 + 0];
                    float v1 = acc[mt][nt][half * 2 + 1];
                    if (EPI == 1) {
                        const float* rrow = Res + (size_t)outr * N + n0;
                        v0 += rrow[col]; v1 += rrow[col + 1];
                    }
                    float2 fv = make_float2(v0, v1);
                    *(float2*)(crow + col) = fv;
                }
            }
        }
    }
}

// ---------------- RoPE + convert: qkv fp32 -> q/k/v bf16 hi/lo ----------------
__global__ void rope_conv_kernel(const float* __restrict__ qkv) {
    int s = blockIdx.x;
    int i = threadIdx.x & 31;
    float inv = powf(10000.0f, -(float)i / 32.0f);
    float fr = (float)s * inv;
    float c = cosf(fr), sn = sinf(fr);
    for (int h = threadIdx.x >> 5; h < H_; h += 8) {
        const float* q = qkv + (size_t)s * 3 * D_ + h * HD_;
        const float* k = q + D_;
        const float* v = q + 2 * D_;
        size_t o = (size_t)s * D_ + h * HD_ + i;
        float q1 = q[i], q2 = q[i + 32];
        f2hilo(q1 * c + q2 * sn,  d_q_h + o,      d_q_l + o);
        f2hilo(-q1 * sn + q2 * c, d_q_h + o + 32, d_q_l + o + 32);
        float k1 = k[i], k2 = k[i + 32];
        f2hilo(k1 * c + k2 * sn,  d_k_h + o,      d_k_l + o);
        f2hilo(-k1 * sn + k2 * c, d_k_h + o + 32, d_k_l + o + 32);
        f2hilo(v[i],      d_v_h + o,      d_v_l + o);
        f2hilo(v[i + 32], d_v_h + o + 32, d_v_l + o + 32);
    }
}

// ---------------- tensor-core flash attention: 128 q-rows/CTA, 8 warps ----------------
#define ASD 72
#define AMAT (64*ASD)                  /* bf16 elems per 64-row matrix */
#define AT2_SMEM ((4 + 12)*AMAT*2)     /* Qh,Ql (128 rows = 4 units) + 3 stages x 4 matrices */
__global__ void __launch_bounds__(256) flash_attn_tc(int dummy) {
    extern __shared__ __nv_bfloat16 asm_[];
    uint32_t bQ = (uint32_t)__cvta_generic_to_shared(asm_);
    const uint32_t OFF1 = (uint32_t)(AMAT << 1);      // bytes per 64-row matrix
    const uint32_t QL_OFF = 2 * OFF1;                 // Ql region (128 rows)
    int bx = blockIdx.x, h = blockIdx.y;
    int tid = threadIdx.x, wid = tid >> 5, lid = tid & 31;
    int q0 = bx * 128;
    int ktmax = 2 * bx + 1;

    // Q tile load: 128 rows, 256 threads
    {
        int lrow = tid >> 1, lc0 = (tid & 1) * 32;
        const __nv_bfloat16* qh = d_q_h + (size_t)(q0 + lrow) * D_ + h * HD_ + lc0;
        const __nv_bfloat16* ql = d_q_l + (size_t)(q0 + lrow) * D_ + h * HD_ + lc0;
#pragma unroll
        for (int j = 0; j < 4; j++) {
            uint32_t off = (uint32_t)((lrow * ASD + lc0 + j * 8) << 1);
            cpa16(bQ + off, qh + j * 8, 16);
            cpa16(bQ + QL_OFF + off, ql + j * 8, 16);
        }
    }
    int lrowK = tid >> 2, lqK = tid & 3;
    auto issueKV = [&](int kt, int s) {
        uint32_t st = bQ + (uint32_t)((4 + 4 * s) * AMAT * 2);
        size_t src = (size_t)(kt * 64 + lrowK) * D_ + h * HD_ + lqK * 16;
#pragma unroll
        for (int j = 0; j < 2; j++) {
            uint32_t off = (uint32_t)((lrowK * ASD + lqK * 16 + j * 8) << 1);
            cpa16(st + off,            d_k_h + src + j * 8, 16);
            cpa16(st + OFF1 + off,     d_k_l + src + j * 8, 16);
            cpa16(st + 2 * OFF1 + off, d_v_h + src + j * 8, 16);
            cpa16(st + 3 * OFF1 + off, d_v_l + src + j * 8, 16);
        }
        cpa_commit();
    };
    issueKV(0, 0);      // group 0: Q + stage0
    issueKV(1, 1);      // ktmax >= 1 always

    uint32_t a_lane = (uint32_t)(((lid & 15) * ASD + ((lid >> 4) << 3)) << 1);
    uint32_t b_lane = (uint32_t)((((((lid >> 4) << 3) + (lid & 7)) * ASD) + (((lid >> 3) & 1) << 3)) << 1);
    uint32_t v_lane = (uint32_t)((((lid & 7) + (((lid >> 3) & 1) << 3)) * ASD + ((lid >> 4) << 3)) << 1);
    int ra = lid >> 2, c2 = (lid & 3) << 1;
    int ga = q0 + wid * 16 + ra, gb = ga + 8;

    float m0 = -1e30f, m1 = -1e30f, l0 = 0.f, l1 = 0.f;
    float O[8][4] = {};

    for (int kt = 0; kt <= ktmax; kt++) {
        if (kt + 1 <= ktmax) cpa_wait<1>(); else cpa_wait<0>();
        __syncthreads();
        uint32_t bK = bQ + (uint32_t)((4 + 4 * (kt % 3)) * AMAT * 2);
        uint32_t bV = bK + 2 * OFF1;

        // S = Q K^T (split-bf16, 3 MMAs)
        float S[8][4] = {};
#pragma unroll
        for (int ks = 0; ks < 4; ks++) {
            uint32_t kb = (uint32_t)(ks << 5);
            uint32_t ah[4], al[4];
            uint32_t ab = (uint32_t)(((wid * 16) * ASD) << 1) + kb + a_lane;
            ldsm_x4(ah, bQ + ab);
            ldsm_x4(al, bQ + QL_OFF + ab);
#pragma unroll
            for (int p = 0; p < 4; p++) {
                uint32_t bb = (uint32_t)(((p * 16) * ASD) << 1) + kb + b_lane;
                uint32_t th[4], tl[4];
                ldsm_x4(th, bK + bb);
                ldsm_x4(tl, bK + OFF1 + bb);
                uint32_t bh0[2] = {th[0], th[1]}, bh1[2] = {th[2], th[3]};
                uint32_t bl0[2] = {tl[0], tl[1]}, bl1[2] = {tl[2], tl[3]};
                mma16816(S[2*p],   ah, bh0); mma16816(S[2*p],   al, bh0); mma16816(S[2*p],   ah, bl0);
                mma16816(S[2*p+1], ah, bh1); mma16816(S[2*p+1], al, bh1); mma16816(S[2*p+1], ah, bl1);
            }
        }
        // scale + causal mask (only last two tiles can overlap the diagonal)
        bool diag = (kt >= 2 * bx);
#pragma unroll
        for (int t = 0; t < 8; t++) {
            int col = kt * 64 + t * 8 + c2;
            S[t][0] *= 0.125f; S[t][1] *= 0.125f; S[t][2] *= 0.125f; S[t][3] *= 0.125f;
            if (diag) {
                if (col     > ga) S[t][0] = -1e30f;
                if (col + 1 > ga) S[t][1] = -1e30f;
                if (col     > gb) S[t][2] = -1e30f;
                if (col + 1 > gb) S[t][3] = -1e30f;
            }
        }
        // online softmax
        float mxa = -1e30f, mxb = -1e30f;
#pragma unroll
        for (int t = 0; t < 8; t++) {
            mxa = fmaxf(mxa, fmaxf(S[t][0], S[t][1]));
            mxb = fmaxf(mxb, fmaxf(S[t][2], S[t][3]));
        }
        mxa = fmaxf(mxa, __shfl_xor_sync(0xffffffffu, mxa, 1));
        mxa = fmaxf(mxa, __shfl_xor_sync(0xffffffffu, mxa, 2));
        mxb = fmaxf(mxb, __shfl_xor_sync(0xffffffffu, mxb, 1));
        mxb = fmaxf(mxb, __shfl_xor_sync(0xffffffffu, mxb, 2));
        float nma = fmaxf(m0, mxa), nmb = fmaxf(m1, mxb);
        float faca = __expf(m0 - nma), facb = __expf(m1 - nmb);
        m0 = nma; m1 = nmb;
        float suma = 0.f, sumb = 0.f;
#pragma unroll
        for (int t = 0; t < 8; t++) {
            S[t][0] = __expf(S[t][0] - nma); suma += S[t][0];
            S[t][1] = __expf(S[t][1] - nma); suma += S[t][1];
            S[t][2] = __expf(S[t][2] - nmb); sumb += S[t][2];
            S[t][3] = __expf(S[t][3] - nmb); sumb += S[t][3];
        }
        suma += __shfl_xor_sync(0xffffffffu, suma, 1);
        suma += __shfl_xor_sync(0xffffffffu, suma, 2);
        sumb += __shfl_xor_sync(0xffffffffu, sumb, 1);
        sumb += __shfl_xor_sync(0xffffffffu, sumb, 2);
        l0 = l0 * faca + suma; l1 = l1 * facb + sumb;
#pragma unroll
        for (int t = 0; t < 8; t++) {
            O[t][0] *= faca; O[t][1] *= faca; O[t][2] *= facb; O[t][3] *= facb;
        }
        // O += P V
#pragma unroll
        for (int ks = 0; ks < 4; ks++) {
            uint32_t ph[4], pl[4];
            ph[0] = packh(S[2*ks][0],   S[2*ks][1],   &pl[0]);
            ph[1] = packh(S[2*ks][2],   S[2*ks][3],   &pl[1]);
            ph[2] = packh(S[2*ks+1][0], S[2*ks+1][1], &pl[2]);
            ph[3] = packh(S[2*ks+1][2], S[2*ks+1][3], &pl[3]);
#pragma unroll
            for (int p = 0; p < 4; p++) {
                uint32_t vb = (uint32_t)(((16 * ks) * ASD + 16 * p) << 1) + v_lane;
                uint32_t th[4], tl[4];
                ldsm_x4t(th, bV + vb);
                ldsm_x4t(tl, bV + OFF1 + vb);
                uint32_t bh0[2] = {th[0], th[1]}, bh1[2] = {th[2], th[3]};
                uint32_t bl0[2] = {tl[0], tl[1]}, bl1[2] = {tl[2], tl[3]};
                mma16816(O[2*p],   ph, bh0); mma16816(O[2*p],   pl, bh0); mma16816(O[2*p],   ph, bl0);
                mma16816(O[2*p+1], ph, bh1); mma16816(O[2*p+1], pl, bh1); mma16816(O[2*p+1], ph, bl1);
            }
        }
        if (kt + 2 <= ktmax) issueKV(kt + 2, (kt + 2) % 3);
    }
    // epilogue: normalize + hi/lo store
    float il0 = 1.0f / l0, il1 = 1.0f / l1;
#pragma unroll
    for (int t = 0; t < 8; t++) {
        int col = h * HD_ + t * 8 + c2;
        size_t r0 = (size_t)ga * D_ + col;
        size_t r1 = (size_t)gb * D_ + col;
        f2hilo(O[t][0] * il0, d_ao_h + r0,     d_ao_l + r0);
        f2hilo(O[t][1] * il0, d_ao_h + r0 + 1, d_ao_l + r0 + 1);
        f2hilo(O[t][2] * il1, d_ao_h + r1,     d_ao_l + r1);
        f2hilo(O[t][3] * il1, d_ao_h + r1 + 1, d_ao_l + r1 + 1);
    }
}

// ---------------- router ----------------
__global__ void router_kernel(const float* __restrict__ xffn, const float* __restrict__ keys,
                              const int* __restrict__ idx, const float* __restrict__ vals,
                              const float* __restrict__ bias) {
    int t = blockIdx.x, lane = threadIdx.x;
    int e0 = idx[t * 2], e1 = idx[t * 2 + 1];
    const float* xr = xffn + (size_t)t * D_;
    float s0 = 0.f, s1 = 0.f;
    for (int d = lane; d < D_; d += 32) {
        float x = xr[d];
        s0 += x * keys[d * TE_ + e0];
        s1 += x * keys[d * TE_ + e1];
    }
#pragma unroll
    for (int o = 16; o; o >>= 1) {
        s0 += __shfl_xor_sync(0xffffffffu, s0, o);
        s1 += __shfl_xor_sync(0xffffffffu, s1, o);
    }
    if (lane == 0) {
        float v0 = vals[t * 2] + s0 + bias[e0];
        float v1 = vals[t * 2 + 1] + s1 + bias[e1];
        float mm = fmaxf(v0, v1);
        float a = expf(v0 - mm), b = expf(v1 - mm);
        float inv = 1.0f / (a + b);
        d_scores[t * 2] = a * inv;
        d_scores[t * 2 + 1] = b * inv;
    }
}

__global__ void zero_counts_kernel() {
    if (threadIdx.x < TE_) d_counts[threadIdx.x] = 0;
}
__global__ void scatter_kernel(const int* __restrict__ idx) {
    int slot = blockIdx.x * blockDim.x + threadIdx.x;
    if (slot < NSLOT) {
        int e = idx[slot];
        int p = atomicAdd(&d_counts[e], 1);
        d_list[e * NSLOT + p] = slot;
    }
}

// ---------------- combine routed outputs ----------------
__global__ void combine_kernel(const float* __restrict__ coeff) {
    int t = blockIdx.x, tid = threadIdx.x;
    float s0 = d_scores[t * 2], s1 = d_scores[t * 2 + 1];
    const float* y0 = d_ys + (size_t)(t * 2) * D_;
    const float* y1 = d_ys + (size_t)(t * 2 + 1) * D_;
    float* yo = d_y + (size_t)t * D_;
    for (int dd = tid; dd < D_; dd += 256)
        yo[dd] = (s0 * y0[dd] + s1 * y1[dd]) * coeff[dd];
}

// ---------------- final combine ----------------
__global__ void final_kernel(const float* __restrict__ sharedw, float* __restrict__ out) {
    int t = blockIdx.x;
    const float* ysh = d_ysh + (size_t)t * D_;
    float ss = 0.f;
    for (int i = threadIdx.x; i < D_; i += blockDim.x) { float v = ysh[i]; ss += v * v; }
    __shared__ float sh[32];
    float tot = block_reduce_sum(ss, sh);
    float rinv = rsqrtf(tot / (float)D_ + EPS_);
    const float* yr = d_y + (size_t)t * D_;
    const float* xr = d_xffn_in + (size_t)t * D_;
    float* o = out + (size_t)t * D_;
    for (int i = threadIdx.x; i < D_; i += blockDim.x)
        o[i] = yr[i] + ysh[i] * rinv * sharedw[i] + xr[i];
}

// ---------------- host launch ----------------
static void* sym(const void* s) { void* p = nullptr; cudaGetSymbolAddress(&p, s); return p; }

static cudaStream_t g_sA = nullptr, g_sB = nullptr;
static cudaEvent_t  g_evF, g_evAW, g_evOW, g_evWTS, g_evX, g_evB;
static bool g_init = false;

extern "C" void kernel_launch(void* const* d_in, const int* in_sizes, int n_in,
                              void* d_out, int out_size) {
    const float* x_input      = (const float*)d_in[0];
    const int*   indices      = (const int*)  d_in[1];
    const float* values       = (const float*)d_in[2];
    const float* attn_w       = (const float*)d_in[3];
    const float* attn_o_w     = (const float*)d_in[4];
    const float* attn_norm_w  = (const float*)d_in[5];
    const float* ffn_norm_w   = (const float*)d_in[6];
    const float* ffn_experts  = (const float*)d_in[7];
    const float* main_keys    = (const float*)d_in[8];
    const float* main_bias    = (const float*)d_in[9];
    const float* output_coeff = (const float*)d_in[10];
    const float* ffn_up_w     = (const float*)d_in[11];
    const float* ffn_down_w   = (const float*)d_in[12];
    const float* shared_norm_w= (const float*)d_in[13];
    float* out = (float*)d_out;

    if (!g_init) {
        g_init = true;
        cudaStreamCreateWithFlags(&g_sA, cudaStreamNonBlocking);
        cudaStreamCreateWithFlags(&g_sB, cudaStreamNonBlocking);
        cudaEventCreateWithFlags(&g_evF,   cudaEventDisableTiming);
        cudaEventCreateWithFlags(&g_evAW,  cudaEventDisableTiming);
        cudaEventCreateWithFlags(&g_evOW,  cudaEventDisableTiming);
        cudaEventCreateWithFlags(&g_evWTS, cudaEventDisableTiming);
        cudaEventCreateWithFlags(&g_evX,   cudaEventDisableTiming);
        cudaEventCreateWithFlags(&g_evB,   cudaEventDisableTiming);
        cudaFuncSetAttribute((const void*)gemm_mma<0,0>, cudaFuncAttributeMaxDynamicSharedMemorySize, GEMM_SMEM);
        cudaFuncSetAttribute((const void*)gemm_mma<0,1>, cudaFuncAttributeMaxDynamicSharedMemorySize, GEMM_SMEM);
        cudaFuncSetAttribute((const void*)gemm_mma<0,2>, cudaFuncAttributeMaxDynamicSharedMemorySize, GEMM_SMEM);
        cudaFuncSetAttribute((const void*)gemm_mma<1,2>, cudaFuncAttributeMaxDynamicSharedMemorySize, GEMM_SMEM);
        cudaFuncSetAttribute((const void*)gemm_mma<2,0>, cudaFuncAttributeMaxDynamicSharedMemorySize, GEMM_SMEM);
        cudaFuncSetAttribute((const void*)flash_attn_tc, cudaFuncAttributeMaxDynamicSharedMemorySize, AT2_SMEM);
    }
    cudaStream_t sA = g_sA, sB = g_sB;
    cudaEvent_t evF = g_evF, evAW = g_evAW, evOW = g_evOW, evWTS = g_evWTS, evX = g_evX, evB = g_evB;

    __nv_bfloat16 *p_xn_h=(__nv_bfloat16*)sym(d_xn_h), *p_xn_l=(__nv_bfloat16*)sym(d_xn_l);
    __nv_bfloat16 *p_aw_h=(__nv_bfloat16*)sym(d_aw_h), *p_aw_l=(__nv_bfloat16*)sym(d_aw_l);
    __nv_bfloat16 *p_ow_h=(__nv_bfloat16*)sym(d_ow_h), *p_ow_l=(__nv_bfloat16*)sym(d_ow_l);
    __nv_bfloat16 *p_ao_h=(__nv_bfloat16*)sym(d_ao_h), *p_ao_l=(__nv_bfloat16*)sym(d_ao_l);
    __nv_bfloat16 *p_xf_h=(__nv_bfloat16*)sym(d_xffn_h), *p_xf_l=(__nv_bfloat16*)sym(d_xffn_l);
    __nv_bfloat16 *p_uw_h=(__nv_bfloat16*)sym(d_upw_h), *p_uw_l=(__nv_bfloat16*)sym(d_upw_l);
    __nv_bfloat16 *p_dw_h=(__nv_bfloat16*)sym(d_dnw_h), *p_dw_l=(__nv_bfloat16*)sym(d_dnw_l);
    __nv_bfloat16 *p_w12_h=(__nv_bfloat16*)sym(d_w12t_h), *p_w12_l=(__nv_bfloat16*)sym(d_w12t_l);
    __nv_bfloat16 *p_w3_h=(__nv_bfloat16*)sym(d_w3_h), *p_w3_l=(__nv_bfloat16*)sym(d_w3_l);
    __nv_bfloat16 *p_g_h=(__nv_bfloat16*)sym(d_g_h), *p_g_l=(__nv_bfloat16*)sym(d_g_l);
    __nv_bfloat16 *p_gs_h=(__nv_bfloat16*)sym(d_gs_h), *p_gs_l=(__nv_bfloat16*)sym(d_gs_l);
    float *p_qkv=(float*)sym(d_qkv), *p_xffn_in=(float*)sym(d_xffn_in), *p_xffn=(float*)sym(d_xffn);
    float *p_ys=(float*)sym(d_ys), *p_ysh=(float*)sym(d_ysh);

    // fork conversions onto sA
    cudaEventRecord(evF, 0);
    cudaStreamWaitEvent(sA, evF, 0);
    conv_hilo_kernel<<<2048, 256, 0, sA>>>((const float4*)attn_w, (uint2*)p_aw_h, (uint2*)p_aw_l,
                                           (size_t)3 * D_ * D_ / 4);
    cudaEventRecord(evAW, sA);
    conv_hilo_kernel<<<1024, 256, 0, sA>>>((const float4*)attn_o_w, (uint2*)p_ow_h, (uint2*)p_ow_l,
                                           (size_t)D_ * D_ / 4);
    cudaEventRecord(evOW, sA);
    conv_hilo_ilv_kernel<<<2048, 256, 0, sA>>>((const float4*)ffn_up_w, (uint2*)p_uw_h, (uint2*)p_uw_l);
    conv_hilo_kernel<<<2048, 256, 0, sA>>>((const float4*)ffn_down_w, (uint2*)p_dw_h, (uint2*)p_dw_l,
                                           (size_t)D_ * DS_ / 4);
    conv_hilo_kernel<<<4096, 256, 0, sA>>>((const float4*)(ffn_experts + (size_t)2 * TE_ * D_ * ED_),
                                           (uint2*)p_w3_h, (uint2*)p_w3_l, (size_t)TE_ * D_ * ED_ / 4);
    transpose_w12_kernel<<<dim3(32, 16, 16), dim3(32, 8), 0, sA>>>(ffn_experts);
    cudaEventRecord(evWTS, sA);

    // attention block on stream 0 (overlaps conversions)
    rmsnorm_kernel<<<T_, 256>>>(x_input, attn_norm_w, nullptr, p_xn_h, p_xn_l);
    cudaStreamWaitEvent(0, evAW, 0);
    gemm_mma<0,0><<<dim3(24, 16), 256, GEMM_SMEM>>>(p_xn_h, p_xn_l, p_aw_h, p_aw_l,
                                                    p_qkv, nullptr, 3 * D_, D_, 0);
    rope_conv_kernel<<<S_, 256>>>(p_qkv);
    flash_attn_tc<<<dim3(S_ / 128, H_), 256, AT2_SMEM>>>(0);
    cudaStreamWaitEvent(0, evOW, 0);
    gemm_mma<0,1><<<dim3(8, 16), 256, GEMM_SMEM>>>(p_ao_h, p_ao_l, p_ow_h, p_ow_l,
                                                   p_xffn_in, x_input, D_, D_, 0);

    // ffn norm, then fork expert branch to sB
    rmsnorm_kernel<<<T_, 256>>>(p_xffn_in, ffn_norm_w, p_xffn, p_xf_h, p_xf_l);
    cudaStreamWaitEvent(0, evWTS, 0);
    cudaEventRecord(evX, 0);
    cudaStreamWaitEvent(sB, evX, 0);

    // sB: routed-expert chain (gemm1 fused with swiglu -> g hi/lo)
    router_kernel<<<T_, 32, 0, sB>>>(p_xffn, main_keys, indices, values, main_bias);
    zero_counts_kernel<<<1, 32, 0, sB>>>();
    scatter_kernel<<<(NSLOT + 255) / 256, 256, 0, sB>>>(indices);
    gemm_mma<1,2><<<dim3(8, NSLOT / 128, TE_), 256, GEMM_SMEM, sB>>>(
        p_xf_h, p_xf_l, p_w12_h, p_w12_l, (float*)p_g_h, (const float*)p_g_l,
        1024, 1024, (long long)1024 * 1024);
    gemm_mma<2,0><<<dim3(8, NSLOT / 128, TE_), 256, GEMM_SMEM, sB>>>(
        p_g_h, p_g_l, p_w3_h, p_w3_l, p_ys, nullptr, 1024, 512, (long long)D_ * ED_);
    combine_kernel<<<T_, 256, 0, sB>>>(output_coeff);
    cudaEventRecord(evB, sB);

    // stream 0: shared-expert chain (up fused with swiglu -> gs hi/lo)
    gemm_mma<0,2><<<dim3(32, 16), 256, GEMM_SMEM>>>(p_xf_h, p_xf_l, p_uw_h, p_uw_l,
                                                    (float*)p_gs_h, (const float*)p_gs_l,
                                                    2 * DS_, D_, 0);
    gemm_mma<0,0><<<dim3(8, 16), 256, GEMM_SMEM>>>(p_gs_h, p_gs_l, p_dw_h, p_dw_l,
                                                   p_ysh, nullptr, D_, DS_, 0);

    // join and final combine
    cudaStreamWaitEvent(0, evB, 0);
    final_kernel<<<T_, 256>>>(shared_norm_w, out);
}

// round 13
// speedup vs baseline: 11.7414x; 1.0051x over previous
#include <cuda_runtime.h>
#include <cuda_bf16.h>
#include <math.h>
#include <stdint.h>

// ---------------- problem constants ----------------
#define S_   2048
#define D_   1024
#define H_   16
#define HD_  64
#define TE_  16
#define TOPK 2
#define ED_  512
#define DS_  2048
#define T_   2048
#define NSLOT (T_*TOPK)
#define EPS_ 1e-5f

// ---------------- scratch (device bss, no allocation) ----------------
__device__ __align__(256) __nv_bfloat16 d_xn_h[(size_t)T_*D_],     d_xn_l[(size_t)T_*D_];
__device__ __align__(256) __nv_bfloat16 d_aw_h[(size_t)3*D_*D_],   d_aw_l[(size_t)3*D_*D_];
__device__ __align__(256) __nv_bfloat16 d_ow_h[(size_t)D_*D_],     d_ow_l[(size_t)D_*D_];
__device__ __align__(256) __nv_bfloat16 d_ao_h[(size_t)T_*D_],     d_ao_l[(size_t)T_*D_];
__device__ __align__(256) __nv_bfloat16 d_xffn_h[(size_t)T_*D_],   d_xffn_l[(size_t)T_*D_];
__device__ __align__(256) __nv_bfloat16 d_upw_h[(size_t)2*DS_*D_], d_upw_l[(size_t)2*DS_*D_];  // interleaved
__device__ __align__(256) __nv_bfloat16 d_dnw_h[(size_t)D_*DS_],   d_dnw_l[(size_t)D_*DS_];
__device__ __align__(256) __nv_bfloat16 d_w12t_h[(size_t)TE_*2*ED_*D_], d_w12t_l[(size_t)TE_*2*ED_*D_]; // interleaved
__device__ __align__(256) __nv_bfloat16 d_w3_h[(size_t)TE_*D_*ED_],     d_w3_l[(size_t)TE_*D_*ED_];
__device__ __align__(256) __nv_bfloat16 d_g_h[(size_t)NSLOT*ED_],  d_g_l[(size_t)NSLOT*ED_];
__device__ __align__(256) __nv_bfloat16 d_gs_h[(size_t)T_*DS_],    d_gs_l[(size_t)T_*DS_];
__device__ __align__(256) __nv_bfloat16 d_q_h[(size_t)T_*D_], d_q_l[(size_t)T_*D_];
__device__ __align__(256) __nv_bfloat16 d_k_h[(size_t)T_*D_], d_k_l[(size_t)T_*D_];
__device__ __align__(256) __nv_bfloat16 d_v_h[(size_t)T_*D_], d_v_l[(size_t)T_*D_];
__device__ __align__(256) float d_qkv[(size_t)T_*3*D_];
__device__ __align__(256) float d_xffn_in[(size_t)T_*D_];
__device__ __align__(256) float d_xffn[(size_t)T_*D_];
__device__ __align__(256) float d_y[(size_t)T_*D_];
__device__ __align__(256) float d_ysh[(size_t)T_*D_];
__device__ float d_scores[NSLOT];
__device__ int   d_counts[TE_];
__device__ int   d_list[TE_*NSLOT];

// ---------------- helpers ----------------
__device__ __forceinline__ void f2hilo(float x, __nv_bfloat16* h, __nv_bfloat16* l) {
    __nv_bfloat16 hh = __float2bfloat16(x);
    *h = hh;
    *l = __float2bfloat16(x - __bfloat162float(hh));
}
__device__ __forceinline__ uint32_t bpack(__nv_bfloat16 a, __nv_bfloat16 b) {
    uint16_t ua = *(uint16_t*)&a, ub = *(uint16_t*)&b;
    return ((uint32_t)ub << 16) | ua;
}
__device__ __forceinline__ uint32_t packh(float x, float y, uint32_t* lo) {
    __nv_bfloat16 hx = __float2bfloat16(x), hy = __float2bfloat16(y);
    __nv_bfloat16 lx = __float2bfloat16(x - __bfloat162float(hx));
    __nv_bfloat16 ly = __float2bfloat16(y - __bfloat162float(hy));
    *lo = bpack(lx, ly);
    return bpack(hx, hy);
}
__device__ __forceinline__ float block_reduce_sum(float v, float* sh) {
    __syncthreads();
    int lane = threadIdx.x & 31, wid = threadIdx.x >> 5;
#pragma unroll
    for (int o = 16; o; o >>= 1) v += __shfl_xor_sync(0xffffffffu, v, o);
    if (lane == 0) sh[wid] = v;
    __syncthreads();
    int nw = blockDim.x >> 5;
    v = (threadIdx.x < nw) ? sh[threadIdx.x] : 0.f;
    if (wid == 0) {
#pragma unroll
        for (int o = 16; o; o >>= 1) v += __shfl_xor_sync(0xffffffffu, v, o);
        if (lane == 0) sh[0] = v;
    }
    __syncthreads();
    return sh[0];
}
__device__ __forceinline__ void mma16816(float* d, const uint32_t* a, const uint32_t* b) {
    asm volatile(
        "mma.sync.aligned.m16n8k16.row.col.f32.bf16.bf16.f32 "
        "{%0,%1,%2,%3}, {%4,%5,%6,%7}, {%8,%9}, {%0,%1,%2,%3};"
        : "+f"(d[0]), "+f"(d[1]), "+f"(d[2]), "+f"(d[3])
        : "r"(a[0]), "r"(a[1]), "r"(a[2]), "r"(a[3]), "r"(b[0]), "r"(b[1]));
}
__device__ __forceinline__ void ldsm_x4(uint32_t* r, uint32_t addr) {
    asm volatile("ldmatrix.sync.aligned.m8n8.x4.shared.b16 {%0,%1,%2,%3}, [%4];"
        : "=r"(r[0]), "=r"(r[1]), "=r"(r[2]), "=r"(r[3]) : "r"(addr));
}
__device__ __forceinline__ void ldsm_x4t(uint32_t* r, uint32_t addr) {
    asm volatile("ldmatrix.sync.aligned.m8n8.x4.trans.shared.b16 {%0,%1,%2,%3}, [%4];"
        : "=r"(r[0]), "=r"(r[1]), "=r"(r[2]), "=r"(r[3]) : "r"(addr));
}
__device__ __forceinline__ void cpa16(uint32_t dst, const void* src, int sb) {
    asm volatile("cp.async.cg.shared.global [%0], [%1], 16, %2;"
                 :: "r"(dst), "l"(src), "r"(sb));
}
__device__ __forceinline__ void cpa_commit() { asm volatile("cp.async.commit_group;"); }
template<int N> __device__ __forceinline__ void cpa_wait() {
    asm volatile("cp.async.wait_group %0;" :: "n"(N));
}

// ---------------- conversion kernels (vectorized) ----------------
__global__ void conv_hilo_kernel(const float4* __restrict__ src, uint2* __restrict__ hi,
                                 uint2* __restrict__ lo, size_t n4) {
    for (size_t i = (size_t)blockIdx.x * blockDim.x + threadIdx.x; i < n4;
         i += (size_t)gridDim.x * blockDim.x) {
        float4 v = src[i];
        __nv_bfloat16 h0, l0, h1, l1, h2, l2, h3, l3;
        f2hilo(v.x, &h0, &l0); f2hilo(v.y, &h1, &l1);
        f2hilo(v.z, &h2, &l2); f2hilo(v.w, &h3, &l3);
        uint2 ho, lw;
        ho.x = bpack(h0, h1); ho.y = bpack(h2, h3);
        lw.x = bpack(l0, l1); lw.y = bpack(l2, l3);
        hi[i] = ho; lo[i] = lw;
    }
}

// interleave ffn_up rows: dest row 2j = src row j (W1), dest row 2j+1 = src row DS+j (W2)
__global__ void conv_hilo_ilv_kernel(const float4* __restrict__ src, uint2* __restrict__ hi,
                                     uint2* __restrict__ lo) {
    size_t n4 = (size_t)2 * DS_ * D_ / 4;
    size_t rowq = D_ / 4;
    for (size_t i = (size_t)blockIdx.x * blockDim.x + threadIdx.x; i < n4;
         i += (size_t)gridDim.x * blockDim.x) {
        size_t r = i / rowq, c = i % rowq;
        size_t sr = (r & 1) ? ((size_t)DS_ + (r >> 1)) : (r >> 1);
        float4 v = src[sr * rowq + c];
        __nv_bfloat16 h0, l0, h1, l1, h2, l2, h3, l3;
        f2hilo(v.x, &h0, &l0); f2hilo(v.y, &h1, &l1);
        f2hilo(v.z, &h2, &l2); f2hilo(v.w, &h3, &l3);
        uint2 ho, lw;
        ho.x = bpack(h0, h1); ho.y = bpack(h2, h3);
        lw.x = bpack(l0, l1); lw.y = bpack(l2, l3);
        hi[i] = ho; lo[i] = lw;
    }
}

// experts W1/W2 [m][e][k=D][n=ED] -> w12t [e][2n+m][k] hi/lo (interleaved for swiglu epi)
__global__ void transpose_w12_kernel(const float* __restrict__ experts) {
    __shared__ float tile[64][33];
    int e = blockIdx.z;
    int n0 = blockIdx.x * 32, k0 = blockIdx.y * 64;
    int m = n0 >> 9, c0 = n0 & 511;
    for (int kk = threadIdx.y; kk < 64; kk += 8)
        tile[kk][threadIdx.x] =
            experts[((size_t)(m * TE_ + e) * D_ + k0 + kk) * ED_ + c0 + threadIdx.x];
    __syncthreads();
    for (int ny = threadIdx.y; ny < 32; ny += 8) {
        int ng = n0 + ny;
        int mm = ng >> 9, cc = ng & 511;
        int rr = 2 * cc + mm;
        float va = tile[threadIdx.x * 2][ny];
        float vb = tile[threadIdx.x * 2 + 1][ny];
        __nv_bfloat16 ha, la, hb, lb;
        f2hilo(va, &ha, &la); f2hilo(vb, &hb, &lb);
        size_t o = ((size_t)e << 20) + (size_t)rr * 1024 + k0 + threadIdx.x * 2;
        *(uint32_t*)(d_w12t_h + o) = bpack(ha, hb);
        *(uint32_t*)(d_w12t_l + o) = bpack(la, lb);
    }
}

// ---------------- rmsnorm (fp32 optional + hi/lo) ----------------
__global__ void rmsnorm_kernel(const float* __restrict__ x, const float* __restrict__ w,
                               float* __restrict__ outf, __nv_bfloat16* __restrict__ oh,
                               __nv_bfloat16* __restrict__ ol) {
    int row = blockIdx.x;
    const float* xr = x + (size_t)row * D_;
    float ss = 0.f;
    for (int i = threadIdx.x; i < D_; i += blockDim.x) { float v = xr[i]; ss += v * v; }
    __shared__ float sh[32];
    float tot = block_reduce_sum(ss, sh);
    float rinv = rsqrtf(tot / (float)D_ + EPS_);
    for (int i = threadIdx.x; i < D_; i += blockDim.x) {
        float v = xr[i] * rinv * w[i];
        size_t o = (size_t)row * D_ + i;
        if (outf) outf[o] = v;
        f2hilo(v, oh + o, ol + o);
    }
}

// ---------------- warp-MMA split-bf16 GEMM: C[M,N] = A @ B^T ----------------
// EPI: 0 = fp32 C, 1 = fp32 C + residual, 2 = swiglu pair -> bf16 hi/lo (C=Gh, Res=Gl),
//      3 = routed combine: atomicAdd(d_y[tok], score[slot] * v)
#define SD    40
#define STG_E (4*128*SD)
#define GEMM_SMEM (4*STG_E*2)

template<int GATHER, int EPI>
__global__ void __launch_bounds__(256, 1) gemm_mma(
    const __nv_bfloat16* __restrict__ Ah, const __nv_bfloat16* __restrict__ Al,
    const __nv_bfloat16* __restrict__ Bh, const __nv_bfloat16* __restrict__ Bl,
    float* __restrict__ C, const float* __restrict__ Res,
    int N, int K, long long bstride)
{
    __shared__ int s_row[128];
    __shared__ int s_out[128];
    int tid = threadIdx.x, wid = tid >> 5, lid = tid & 31;
    if (GATHER) {
        int e = blockIdx.z, cnt = d_counts[e];
        if ((int)blockIdx.y * 128 >= cnt) return;
        if (tid < 128) {
            int r = blockIdx.y * 128 + tid;
            int sl = (r < cnt) ? d_list[e * NSLOT + r] : -1;
            s_out[tid] = sl;
            s_row[tid] = (sl < 0) ? -1 : (GATHER == 1 ? (sl >> 1) : sl);
        }
        Bh += (size_t)blockIdx.z * bstride;
        Bl += (size_t)blockIdx.z * bstride;
    } else if (tid < 128) {
        int r = blockIdx.y * 128 + tid;
        s_row[tid] = r; s_out[tid] = r;
    }
    extern __shared__ __nv_bfloat16 sm[];
    uint32_t smb = (uint32_t)__cvta_generic_to_shared(sm);
    int n0 = blockIdx.x * 128;
    int NC = K >> 5;
    __syncthreads();

    int lrow = tid >> 2, lq = tid & 3;
    int arow0 = s_row[lrow];
    const __nv_bfloat16* asrc_h = Ah + (size_t)(arow0 < 0 ? 0 : arow0) * K + lq * 8;
    const __nv_bfloat16* asrc_l = Al + (size_t)(arow0 < 0 ? 0 : arow0) * K + lq * 8;
    const __nv_bfloat16* bsrc_h = Bh + (size_t)(n0 + lrow) * K + lq * 8;
    const __nv_bfloat16* bsrc_l = Bl + (size_t)(n0 + lrow) * K + lq * 8;
    int asb = (arow0 < 0) ? 0 : 16;
    int arow1 = s_row[lrow + 64];
    const __nv_bfloat16* asrc2_h = Ah + (size_t)(arow1 < 0 ? 0 : arow1) * K + lq * 8;
    const __nv_bfloat16* asrc2_l = Al + (size_t)(arow1 < 0 ? 0 : arow1) * K + lq * 8;
    const __nv_bfloat16* bsrc2_h = Bh + (size_t)(n0 + lrow + 64) * K + lq * 8;
    const __nv_bfloat16* bsrc2_l = Bl + (size_t)(n0 + lrow + 64) * K + lq * 8;
    int asb2 = (arow1 < 0) ? 0 : 16;
    uint32_t o1 = (uint32_t)((lrow * SD + lq * 8) << 1);
    uint32_t o2 = (uint32_t)(((lrow + 64) * SD + lq * 8) << 1);
    const uint32_t OFF_AL = (uint32_t)((128 * SD) << 1);
    const uint32_t OFF_BH = (uint32_t)((2 * 128 * SD) << 1);
    const uint32_t OFF_BL = (uint32_t)((3 * 128 * SD) << 1);

    auto issue = [&](int c, int buf) {
        uint32_t st = smb + (uint32_t)(buf * STG_E * 2);
        int kc = c << 5;
        cpa16(st + o1, asrc_h + kc, asb);
        cpa16(st + OFF_AL + o1, asrc_l + kc, asb);
        cpa16(st + OFF_BH + o1, bsrc_h + kc, 16);
        cpa16(st + OFF_BL + o1, bsrc_l + kc, 16);
        cpa16(st + o2, asrc2_h + kc, asb2);
        cpa16(st + OFF_AL + o2, asrc2_l + kc, asb2);
        cpa16(st + OFF_BH + o2, bsrc2_h + kc, 16);
        cpa16(st + OFF_BL + o2, bsrc2_l + kc, 16);
        cpa_commit();
    };

    int wm = wid & 1, wn = wid >> 1;
    int r = lid >> 2, c2 = (lid & 3) << 1;
    uint32_t a_lane = (uint32_t)(((lid & 15) * SD + ((lid >> 4) << 3)) << 1);
    uint32_t b_lane = (uint32_t)((((((lid >> 4) << 3) + (lid & 7)) * SD) + (((lid >> 3) & 1) << 3)) << 1);
    float acc[4][4][4] = {};

    issue(0, 0);
    if (NC > 1) issue(1, 1);
    if (NC > 2) issue(2, 2);
    for (int c = 0; c < NC; c++) {
        int buf = c & 3;
        if (c + 2 < NC) cpa_wait<2>();
        else if (c + 1 < NC) cpa_wait<1>();
        else cpa_wait<0>();
        __syncthreads();
        uint32_t base = smb + (uint32_t)(buf * STG_E * 2);
#pragma unroll
        for (int ks = 0; ks < 2; ks++) {
            uint32_t kb = (uint32_t)(ks << 5);
            uint32_t ah[4][4], al[4][4];
#pragma unroll
            for (int mt = 0; mt < 4; mt++) {
                uint32_t ab = base + (uint32_t)(((wm * 64 + mt * 16) * SD) << 1) + kb + a_lane;
                ldsm_x4(ah[mt], ab);
                ldsm_x4(al[mt], ab + OFF_AL);
            }
            uint32_t bh[4][2], bl[4][2];
#pragma unroll
            for (int p = 0; p < 2; p++) {
                uint32_t bb = base + OFF_BH
                            + (uint32_t)(((wn * 32 + p * 16) * SD) << 1) + kb + b_lane;
                uint32_t t[4];
                ldsm_x4(t, bb);
                bh[2*p][0] = t[0]; bh[2*p][1] = t[1];
                bh[2*p+1][0] = t[2]; bh[2*p+1][1] = t[3];
                ldsm_x4(t, bb + OFF_AL);
                bl[2*p][0] = t[0]; bl[2*p][1] = t[1];
                bl[2*p+1][0] = t[2]; bl[2*p+1][1] = t[3];
            }
#pragma unroll
            for (int nt = 0; nt < 4; nt++)
#pragma unroll
                for (int mt = 0; mt < 4; mt++) {
                    mma16816(acc[mt][nt], ah[mt], bh[nt]);
                    mma16816(acc[mt][nt], al[mt], bh[nt]);
                    mma16816(acc[mt][nt], ah[mt], bl[nt]);
                }
        }
        if (c + 3 < NC) issue(c + 3, (c + 3) & 3);
    }

    // epilogue
#pragma unroll
    for (int mt = 0; mt < 4; mt++) {
        int rloc0 = wm * 64 + mt * 16 + r;
#pragma unroll
        for (int half = 0; half < 2; half++) {
            int rloc = rloc0 + half * 8;
            int outr = s_out[rloc];
            if (GATHER && outr < 0) continue;
            if (EPI == 2) {
                __nv_bfloat16* Gh = (__nv_bfloat16*)C;
                __nv_bfloat16* Gl = (__nv_bfloat16*)(void*)Res;
                int hn = N >> 1;
#pragma unroll
                for (int nt = 0; nt < 4; nt++) {
                    int col = wn * 32 + nt * 8 + c2;
                    float v0 = acc[mt][nt][half * 2 + 0];
                    float v1 = acc[mt][nt][half * 2 + 1];
                    float g = (v0 / (1.f + __expf(-v0))) * v1;
                    size_t oo = (size_t)outr * hn + ((n0 + col) >> 1);
                    f2hilo(g, Gh + oo, Gl + oo);
                }
            } else if (EPI == 3) {
                int tok = outr >> 1;
                float sc = d_scores[outr];
                float* crow = C + (size_t)tok * N + n0;
#pragma unroll
                for (int nt = 0; nt < 4; nt++) {
                    int col = wn * 32 + nt * 8 + c2;
                    atomicAdd(crow + col,     sc * acc[mt][nt][half * 2 + 0]);
                    atomicAdd(crow + col + 1, sc * acc[mt][nt][half * 2 + 1]);
                }
            } else {
                float* crow = C + (size_t)outr * N + n0;
#pragma unroll
                for (int nt = 0; nt < 4; nt++) {
                    int col = wn * 32 + nt * 8 + c2;
                    float v0 = acc[mt][nt][half * 2 + 0];
                    float v1 = acc[mt][nt][half * 2 + 1];
                    if (EPI == 1) {
                        const float* rrow = Res + (size_t)outr * N + n0;
                        v0 += rrow[col]; v1 += rrow[col + 1];
                    }
                    float2 fv = make_float2(v0, v1);
                    *(float2*)(crow + col) = fv;
                }
            }
        }
    }
}

// ---------------- RoPE + convert: qkv fp32 -> q/k/v bf16 hi/lo ----------------
__global__ void rope_conv_kernel(const float* __restrict__ qkv) {
    int s = blockIdx.x;
    int i = threadIdx.x & 31;
    float inv = powf(10000.0f, -(float)i / 32.0f);
    float fr = (float)s * inv;
    float c = cosf(fr), sn = sinf(fr);
    for (int h = threadIdx.x >> 5; h < H_; h += 8) {
        const float* q = qkv + (size_t)s * 3 * D_ + h * HD_;
        const float* k = q + D_;
        const float* v = q + 2 * D_;
        size_t o = (size_t)s * D_ + h * HD_ + i;
        float q1 = q[i], q2 = q[i + 32];
        f2hilo(q1 * c + q2 * sn,  d_q_h + o,      d_q_l + o);
        f2hilo(-q1 * sn + q2 * c, d_q_h + o + 32, d_q_l + o + 32);
        float k1 = k[i], k2 = k[i + 32];
        f2hilo(k1 * c + k2 * sn,  d_k_h + o,      d_k_l + o);
        f2hilo(-k1 * sn + k2 * c, d_k_h + o + 32, d_k_l + o + 32);
        f2hilo(v[i],      d_v_h + o,      d_v_l + o);
        f2hilo(v[i + 32], d_v_h + o + 32, d_v_l + o + 32);
    }
}

// ---------------- tensor-core flash attention: 128 q-rows/CTA, 8 warps ----------------
// heavy CTAs first (reversed bx) so the load-imbalanced tail backfills.
#define ASD 72
#define AMAT (64*ASD)
#define AT2_SMEM ((4 + 12)*AMAT*2)
__global__ void __launch_bounds__(256) flash_attn_tc(int dummy) {
    extern __shared__ __nv_bfloat16 asm_[];
    uint32_t bQ = (uint32_t)__cvta_generic_to_shared(asm_);
    const uint32_t OFF1 = (uint32_t)(AMAT << 1);
    const uint32_t QL_OFF = 2 * OFF1;
    int bx = gridDim.x - 1 - blockIdx.x, h = blockIdx.y;
    int tid = threadIdx.x, wid = tid >> 5, lid = tid & 31;
    int q0 = bx * 128;
    int ktmax = 2 * bx + 1;

    // Q tile load: 128 rows, 256 threads
    {
        int lrow = tid >> 1, lc0 = (tid & 1) * 32;
        const __nv_bfloat16* qh = d_q_h + (size_t)(q0 + lrow) * D_ + h * HD_ + lc0;
        const __nv_bfloat16* ql = d_q_l + (size_t)(q0 + lrow) * D_ + h * HD_ + lc0;
#pragma unroll
        for (int j = 0; j < 4; j++) {
            uint32_t off = (uint32_t)((lrow * ASD + lc0 + j * 8) << 1);
            cpa16(bQ + off, qh + j * 8, 16);
            cpa16(bQ + QL_OFF + off, ql + j * 8, 16);
        }
    }
    int lrowK = tid >> 2, lqK = tid & 3;
    auto issueKV = [&](int kt, int s) {
        uint32_t st = bQ + (uint32_t)((4 + 4 * s) * AMAT * 2);
        size_t src = (size_t)(kt * 64 + lrowK) * D_ + h * HD_ + lqK * 16;
#pragma unroll
        for (int j = 0; j < 2; j++) {
            uint32_t off = (uint32_t)((lrowK * ASD + lqK * 16 + j * 8) << 1);
            cpa16(st + off,            d_k_h + src + j * 8, 16);
            cpa16(st + OFF1 + off,     d_k_l + src + j * 8, 16);
            cpa16(st + 2 * OFF1 + off, d_v_h + src + j * 8, 16);
            cpa16(st + 3 * OFF1 + off, d_v_l + src + j * 8, 16);
        }
        cpa_commit();
    };
    issueKV(0, 0);
    issueKV(1, 1);

    uint32_t a_lane = (uint32_t)(((lid & 15) * ASD + ((lid >> 4) << 3)) << 1);
    uint32_t b_lane = (uint32_t)((((((lid >> 4) << 3) + (lid & 7)) * ASD) + (((lid >> 3) & 1) << 3)) << 1);
    uint32_t v_lane = (uint32_t)((((lid & 7) + (((lid >> 3) & 1) << 3)) * ASD + ((lid >> 4) << 3)) << 1);
    int ra = lid >> 2, c2 = (lid & 3) << 1;
    int ga = q0 + wid * 16 + ra, gb = ga + 8;

    float m0 = -1e30f, m1 = -1e30f, l0 = 0.f, l1 = 0.f;
    float O[8][4] = {};

    for (int kt = 0; kt <= ktmax; kt++) {
        if (kt + 1 <= ktmax) cpa_wait<1>(); else cpa_wait<0>();
        __syncthreads();
        uint32_t bK = bQ + (uint32_t)((4 + 4 * (kt % 3)) * AMAT * 2);
        uint32_t bV = bK + 2 * OFF1;

        float S[8][4] = {};
#pragma unroll
        for (int ks = 0; ks < 4; ks++) {
            uint32_t kb = (uint32_t)(ks << 5);
            uint32_t ah[4], al[4];
            uint32_t ab = (uint32_t)(((wid * 16) * ASD) << 1) + kb + a_lane;
            ldsm_x4(ah, bQ + ab);
            ldsm_x4(al, bQ + QL_OFF + ab);
#pragma unroll
            for (int p = 0; p < 4; p++) {
                uint32_t bb = (uint32_t)(((p * 16) * ASD) << 1) + kb + b_lane;
                uint32_t th[4], tl[4];
                ldsm_x4(th, bK + bb);
                ldsm_x4(tl, bK + OFF1 + bb);
                uint32_t bh0[2] = {th[0], th[1]}, bh1[2] = {th[2], th[3]};
                uint32_t bl0[2] = {tl[0], tl[1]}, bl1[2] = {tl[2], tl[3]};
                mma16816(S[2*p],   ah, bh0); mma16816(S[2*p],   al, bh0); mma16816(S[2*p],   ah, bl0);
                mma16816(S[2*p+1], ah, bh1); mma16816(S[2*p+1], al, bh1); mma16816(S[2*p+1], ah, bl1);
            }
        }
        bool diag = (kt >= 2 * bx);
#pragma unroll
        for (int t = 0; t < 8; t++) {
            int col = kt * 64 + t * 8 + c2;
            S[t][0] *= 0.125f; S[t][1] *= 0.125f; S[t][2] *= 0.125f; S[t][3] *= 0.125f;
            if (diag) {
                if (col     > ga) S[t][0] = -1e30f;
                if (col + 1 > ga) S[t][1] = -1e30f;
                if (col     > gb) S[t][2] = -1e30f;
                if (col + 1 > gb) S[t][3] = -1e30f;
            }
        }
        float mxa = -1e30f, mxb = -1e30f;
#pragma unroll
        for (int t = 0; t < 8; t++) {
            mxa = fmaxf(mxa, fmaxf(S[t][0], S[t][1]));
            mxb = fmaxf(mxb, fmaxf(S[t][2], S[t][3]));
        }
        mxa = fmaxf(mxa, __shfl_xor_sync(0xffffffffu, mxa, 1));
        mxa = fmaxf(mxa, __shfl_xor_sync(0xffffffffu, mxa, 2));
        mxb = fmaxf(mxb, __shfl_xor_sync(0xffffffffu, mxb, 1));
        mxb = fmaxf(mxb, __shfl_xor_sync(0xffffffffu, mxb, 2));
        float nma = fmaxf(m0, mxa), nmb = fmaxf(m1, mxb);
        float faca = __expf(m0 - nma), facb = __expf(m1 - nmb);
        m0 = nma; m1 = nmb;
        float suma = 0.f, sumb = 0.f;
#pragma unroll
        for (int t = 0; t < 8; t++) {
            S[t][0] = __expf(S[t][0] - nma); suma += S[t][0];
            S[t][1] = __expf(S[t][1] - nma); suma += S[t][1];
            S[t][2] = __expf(S[t][2] - nmb); sumb += S[t][2];
            S[t][3] = __expf(S[t][3] - nmb); sumb += S[t][3];
        }
        suma += __shfl_xor_sync(0xffffffffu, suma, 1);
        suma += __shfl_xor_sync(0xffffffffu, suma, 2);
        sumb += __shfl_xor_sync(0xffffffffu, sumb, 1);
        sumb += __shfl_xor_sync(0xffffffffu, sumb, 2);
        l0 = l0 * faca + suma; l1 = l1 * facb + sumb;
#pragma unroll
        for (int t = 0; t < 8; t++) {
            O[t][0] *= faca; O[t][1] *= faca; O[t][2] *= facb; O[t][3] *= facb;
        }
#pragma unroll
        for (int ks = 0; ks < 4; ks++) {
            uint32_t ph[4], pl[4];
            ph[0] = packh(S[2*ks][0],   S[2*ks][1],   &pl[0]);
            ph[1] = packh(S[2*ks][2],   S[2*ks][3],   &pl[1]);
            ph[2] = packh(S[2*ks+1][0], S[2*ks+1][1], &pl[2]);
            ph[3] = packh(S[2*ks+1][2], S[2*ks+1][3], &pl[3]);
#pragma unroll
            for (int p = 0; p < 4; p++) {
                uint32_t vb = (uint32_t)(((16 * ks) * ASD + 16 * p) << 1) + v_lane;
                uint32_t th[4], tl[4];
                ldsm_x4t(th, bV + vb);
                ldsm_x4t(tl, bV + OFF1 + vb);
                uint32_t bh0[2] = {th[0], th[1]}, bh1[2] = {th[2], th[3]};
                uint32_t bl0[2] = {tl[0], tl[1]}, bl1[2] = {tl[2], tl[3]};
                mma16816(O[2*p],   ph, bh0); mma16816(O[2*p],   pl, bh0); mma16816(O[2*p],   ph, bl0);
                mma16816(O[2*p+1], ph, bh1); mma16816(O[2*p+1], pl, bh1); mma16816(O[2*p+1], ph, bl1);
            }
        }
        if (kt + 2 <= ktmax) issueKV(kt + 2, (kt + 2) % 3);
    }
    float il0 = 1.0f / l0, il1 = 1.0f / l1;
#pragma unroll
    for (int t = 0; t < 8; t++) {
        int col = h * HD_ + t * 8 + c2;
        size_t r0 = (size_t)ga * D_ + col;
        size_t r1 = (size_t)gb * D_ + col;
        f2hilo(O[t][0] * il0, d_ao_h + r0,     d_ao_l + r0);
        f2hilo(O[t][1] * il0, d_ao_h + r0 + 1, d_ao_l + r0 + 1);
        f2hilo(O[t][2] * il1, d_ao_h + r1,     d_ao_l + r1);
        f2hilo(O[t][3] * il1, d_ao_h + r1 + 1, d_ao_l + r1 + 1);
    }
}

// ---------------- router ----------------
__global__ void router_kernel(const float* __restrict__ xffn, const float* __restrict__ keys,
                              const int* __restrict__ idx, const float* __restrict__ vals,
                              const float* __restrict__ bias) {
    int t = blockIdx.x, lane = threadIdx.x;
    int e0 = idx[t * 2], e1 = idx[t * 2 + 1];
    const float* xr = xffn + (size_t)t * D_;
    float s0 = 0.f, s1 = 0.f;
    for (int d = lane; d < D_; d += 32) {
        float x = xr[d];
        s0 += x * keys[d * TE_ + e0];
        s1 += x * keys[d * TE_ + e1];
    }
#pragma unroll
    for (int o = 16; o; o >>= 1) {
        s0 += __shfl_xor_sync(0xffffffffu, s0, o);
        s1 += __shfl_xor_sync(0xffffffffu, s1, o);
    }
    if (lane == 0) {
        float v0 = vals[t * 2] + s0 + bias[e0];
        float v1 = vals[t * 2 + 1] + s1 + bias[e1];
        float mm = fmaxf(v0, v1);
        float a = expf(v0 - mm), b = expf(v1 - mm);
        float inv = 1.0f / (a + b);
        d_scores[t * 2] = a * inv;
        d_scores[t * 2 + 1] = b * inv;
    }
}

__global__ void zero_counts_kernel() {
    if (threadIdx.x < TE_) d_counts[threadIdx.x] = 0;
}
__global__ void scatter_kernel(const int* __restrict__ idx) {
    int slot = blockIdx.x * blockDim.x + threadIdx.x;
    if (slot < NSLOT) {
        int e = idx[slot];
        int p = atomicAdd(&d_counts[e], 1);
        d_list[e * NSLOT + p] = slot;
    }
}

// ---------------- final combine (coeff folded in) ----------------
__global__ void final_kernel(const float* __restrict__ sharedw, const float* __restrict__ coeff,
                             float* __restrict__ out) {
    int t = blockIdx.x;
    const float* ysh = d_ysh + (size_t)t * D_;
    float ss = 0.f;
    for (int i = threadIdx.x; i < D_; i += blockDim.x) { float v = ysh[i]; ss += v * v; }
    __shared__ float sh[32];
    float tot = block_reduce_sum(ss, sh);
    float rinv = rsqrtf(tot / (float)D_ + EPS_);
    const float* yr = d_y + (size_t)t * D_;
    const float* xr = d_xffn_in + (size_t)t * D_;
    float* o = out + (size_t)t * D_;
    for (int i = threadIdx.x; i < D_; i += blockDim.x)
        o[i] = yr[i] * coeff[i] + ysh[i] * rinv * sharedw[i] + xr[i];
}

// ---------------- host launch ----------------
static void* sym(const void* s) { void* p = nullptr; cudaGetSymbolAddress(&p, s); return p; }

static cudaStream_t g_sA = nullptr, g_sB = nullptr;
static cudaEvent_t  g_evF, g_evAW, g_evOW, g_evWTS, g_evX, g_evB;
static bool g_init = false;

extern "C" void kernel_launch(void* const* d_in, const int* in_sizes, int n_in,
                              void* d_out, int out_size) {
    const float* x_input      = (const float*)d_in[0];
    const int*   indices      = (const int*)  d_in[1];
    const float* values       = (const float*)d_in[2];
    const float* attn_w       = (const float*)d_in[3];
    const float* attn_o_w     = (const float*)d_in[4];
    const float* attn_norm_w  = (const float*)d_in[5];
    const float* ffn_norm_w   = (const float*)d_in[6];
    const float* ffn_experts  = (const float*)d_in[7];
    const float* main_keys    = (const float*)d_in[8];
    const float* main_bias    = (const float*)d_in[9];
    const float* output_coeff = (const float*)d_in[10];
    const float* ffn_up_w     = (const float*)d_in[11];
    const float* ffn_down_w   = (const float*)d_in[12];
    const float* shared_norm_w= (const float*)d_in[13];
    float* out = (float*)d_out;

    if (!g_init) {
        g_init = true;
        cudaStreamCreateWithFlags(&g_sA, cudaStreamNonBlocking);
        cudaStreamCreateWithFlags(&g_sB, cudaStreamNonBlocking);
        cudaEventCreateWithFlags(&g_evF,   cudaEventDisableTiming);
        cudaEventCreateWithFlags(&g_evAW,  cudaEventDisableTiming);
        cudaEventCreateWithFlags(&g_evOW,  cudaEventDisableTiming);
        cudaEventCreateWithFlags(&g_evWTS, cudaEventDisableTiming);
        cudaEventCreateWithFlags(&g_evX,   cudaEventDisableTiming);
        cudaEventCreateWithFlags(&g_evB,   cudaEventDisableTiming);
        cudaFuncSetAttribute((const void*)gemm_mma<0,0>, cudaFuncAttributeMaxDynamicSharedMemorySize, GEMM_SMEM);
        cudaFuncSetAttribute((const void*)gemm_mma<0,1>, cudaFuncAttributeMaxDynamicSharedMemorySize, GEMM_SMEM);
        cudaFuncSetAttribute((const void*)gemm_mma<0,2>, cudaFuncAttributeMaxDynamicSharedMemorySize, GEMM_SMEM);
        cudaFuncSetAttribute((const void*)gemm_mma<1,2>, cudaFuncAttributeMaxDynamicSharedMemorySize, GEMM_SMEM);
        cudaFuncSetAttribute((const void*)gemm_mma<2,3>, cudaFuncAttributeMaxDynamicSharedMemorySize, GEMM_SMEM);
        cudaFuncSetAttribute((const void*)flash_attn_tc, cudaFuncAttributeMaxDynamicSharedMemorySize, AT2_SMEM);
    }
    cudaStream_t sA = g_sA, sB = g_sB;
    cudaEvent_t evF = g_evF, evAW = g_evAW, evOW = g_evOW, evWTS = g_evWTS, evX = g_evX, evB = g_evB;

    __nv_bfloat16 *p_xn_h=(__nv_bfloat16*)sym(d_xn_h), *p_xn_l=(__nv_bfloat16*)sym(d_xn_l);
    __nv_bfloat16 *p_aw_h=(__nv_bfloat16*)sym(d_aw_h), *p_aw_l=(__nv_bfloat16*)sym(d_aw_l);
    __nv_bfloat16 *p_ow_h=(__nv_bfloat16*)sym(d_ow_h), *p_ow_l=(__nv_bfloat16*)sym(d_ow_l);
    __nv_bfloat16 *p_ao_h=(__nv_bfloat16*)sym(d_ao_h), *p_ao_l=(__nv_bfloat16*)sym(d_ao_l);
    __nv_bfloat16 *p_xf_h=(__nv_bfloat16*)sym(d_xffn_h), *p_xf_l=(__nv_bfloat16*)sym(d_xffn_l);
    __nv_bfloat16 *p_uw_h=(__nv_bfloat16*)sym(d_upw_h), *p_uw_l=(__nv_bfloat16*)sym(d_upw_l);
    __nv_bfloat16 *p_dw_h=(__nv_bfloat16*)sym(d_dnw_h), *p_dw_l=(__nv_bfloat16*)sym(d_dnw_l);
    __nv_bfloat16 *p_w12_h=(__nv_bfloat16*)sym(d_w12t_h), *p_w12_l=(__nv_bfloat16*)sym(d_w12t_l);
    __nv_bfloat16 *p_w3_h=(__nv_bfloat16*)sym(d_w3_h), *p_w3_l=(__nv_bfloat16*)sym(d_w3_l);
    __nv_bfloat16 *p_g_h=(__nv_bfloat16*)sym(d_g_h), *p_g_l=(__nv_bfloat16*)sym(d_g_l);
    __nv_bfloat16 *p_gs_h=(__nv_bfloat16*)sym(d_gs_h), *p_gs_l=(__nv_bfloat16*)sym(d_gs_l);
    float *p_qkv=(float*)sym(d_qkv), *p_xffn_in=(float*)sym(d_xffn_in), *p_xffn=(float*)sym(d_xffn);
    float *p_y=(float*)sym(d_y), *p_ysh=(float*)sym(d_ysh);

    // fork conversions onto sA
    cudaEventRecord(evF, 0);
    cudaStreamWaitEvent(sA, evF, 0);
    conv_hilo_kernel<<<2048, 256, 0, sA>>>((const float4*)attn_w, (uint2*)p_aw_h, (uint2*)p_aw_l,
                                           (size_t)3 * D_ * D_ / 4);
    cudaEventRecord(evAW, sA);
    conv_hilo_kernel<<<1024, 256, 0, sA>>>((const float4*)attn_o_w, (uint2*)p_ow_h, (uint2*)p_ow_l,
                                           (size_t)D_ * D_ / 4);
    cudaEventRecord(evOW, sA);
    conv_hilo_ilv_kernel<<<2048, 256, 0, sA>>>((const float4*)ffn_up_w, (uint2*)p_uw_h, (uint2*)p_uw_l);
    conv_hilo_kernel<<<2048, 256, 0, sA>>>((const float4*)ffn_down_w, (uint2*)p_dw_h, (uint2*)p_dw_l,
                                           (size_t)D_ * DS_ / 4);
    conv_hilo_kernel<<<4096, 256, 0, sA>>>((const float4*)(ffn_experts + (size_t)2 * TE_ * D_ * ED_),
                                           (uint2*)p_w3_h, (uint2*)p_w3_l, (size_t)TE_ * D_ * ED_ / 4);
    transpose_w12_kernel<<<dim3(32, 16, 16), dim3(32, 8), 0, sA>>>(ffn_experts);
    cudaEventRecord(evWTS, sA);

    // attention block on stream 0 (overlaps conversions)
    rmsnorm_kernel<<<T_, 256>>>(x_input, attn_norm_w, nullptr, p_xn_h, p_xn_l);
    cudaStreamWaitEvent(0, evAW, 0);
    gemm_mma<0,0><<<dim3(24, 16), 256, GEMM_SMEM>>>(p_xn_h, p_xn_l, p_aw_h, p_aw_l,
                                                    p_qkv, nullptr, 3 * D_, D_, 0);
    rope_conv_kernel<<<S_, 256>>>(p_qkv);
    flash_attn_tc<<<dim3(S_ / 128, H_), 256, AT2_SMEM>>>(0);
    cudaStreamWaitEvent(0, evOW, 0);
    gemm_mma<0,1><<<dim3(8, 16), 256, GEMM_SMEM>>>(p_ao_h, p_ao_l, p_ow_h, p_ow_l,
                                                   p_xffn_in, x_input, D_, D_, 0);

    // ffn norm, then fork expert branch to sB
    rmsnorm_kernel<<<T_, 256>>>(p_xffn_in, ffn_norm_w, p_xffn, p_xf_h, p_xf_l);
    cudaStreamWaitEvent(0, evWTS, 0);
    cudaEventRecord(evX, 0);
    cudaStreamWaitEvent(sB, evX, 0);

    // sB: routed-expert chain (gemm1 fused swiglu, gemm2 fused combine via atomics)
    router_kernel<<<T_, 32, 0, sB>>>(p_xffn, main_keys, indices, values, main_bias);
    zero_counts_kernel<<<1, 32, 0, sB>>>();
    scatter_kernel<<<(NSLOT + 255) / 256, 256, 0, sB>>>(indices);
    cudaMemsetAsync(p_y, 0, (size_t)T_ * D_ * sizeof(float), sB);
    gemm_mma<1,2><<<dim3(8, NSLOT / 128, TE_), 256, GEMM_SMEM, sB>>>(
        p_xf_h, p_xf_l, p_w12_h, p_w12_l, (float*)p_g_h, (const float*)p_g_l,
        1024, 1024, (long long)1024 * 1024);
    gemm_mma<2,3><<<dim3(8, NSLOT / 128, TE_), 256, GEMM_SMEM, sB>>>(
        p_g_h, p_g_l, p_w3_h, p_w3_l, p_y, nullptr, 1024, 512, (long long)D_ * ED_);
    cudaEventRecord(evB, sB);

    // stream 0: shared-expert chain (up fused with swiglu -> gs hi/lo)
    gemm_mma<0,2><<<dim3(32, 16), 256, GEMM_SMEM>>>(p_xf_h, p_xf_l, p_uw_h, p_uw_l,
                                                    (float*)p_gs_h, (const float*)p_gs_l,
                                                    2 * DS_, D_, 0);
    gemm_mma<0,0><<<dim3(8, 16), 256, GEMM_SMEM>>>(p_gs_h, p_gs_l, p_dw_h, p_dw_l,
                                                   p_ysh, nullptr, D_, DS_, 0);

    // join and final combine
    cudaStreamWaitEvent(0, evB, 0);
    final_kernel<<<T_, 256>>>(shared_norm_w, output_coeff, out);
}